// round 9
// baseline (speedup 1.0000x reference)
#include <cuda_runtime.h>
#include <cuda_bf16.h>
#include <math.h>
#include <stdint.h>

#define BB 2
#define SS 1024
#define DD 768
#define HH 12
#define HDD 64
#define LL 12
#define VV 50257
#define FF 3072
#define MM (BB*SS)   // 2048

// ---------------- scratch (allocation-free) ----------------
// split format: uint4 group = {hi01, hi23, lo01, lo23} for 4 consecutive elems.
__device__ float g_x[MM*DD];
__device__ int   g_pos[BB*SS];
__device__ uint4 g_h_s[MM*DD/4];
__device__ uint4 g_qkv_s[MM*3*DD/4];
__device__ uint4 g_attn_s[MM*DD/4];
__device__ uint4 g_ff_s[MM*FF/4];
__device__ uint4 g_wq_s[LL*DD*DD/4];
__device__ uint4 g_wk_s[LL*DD*DD/4];
__device__ uint4 g_wv_s[LL*DD*DD/4];
__device__ uint4 g_wp_s[LL*DD*DD/4];
__device__ uint4 g_w1_s[LL*DD*FF/4];
__device__ uint4 g_w2_s[LL*DD*FF/4];
__device__ uint4 g_tok_s[(size_t)VV*DD/4];

// ================= helpers =================
__device__ __forceinline__ uint32_t smem_u32(const void* p) {
    uint32_t a;
    asm("{ .reg .u64 t; cvta.to.shared.u64 t, %1; cvt.u32.u64 %0, t; }" : "=r"(a) : "l"(p));
    return a;
}
__device__ __forceinline__ void ldsm_x4(uint32_t& r0, uint32_t& r1, uint32_t& r2, uint32_t& r3,
                                        uint32_t addr) {
    asm volatile("ldmatrix.sync.aligned.m8n8.x4.shared.b16 {%0,%1,%2,%3}, [%4];"
                 : "=r"(r0), "=r"(r1), "=r"(r2), "=r"(r3) : "r"(addr));
}
__device__ __forceinline__ void ldsm_x4_t(uint32_t& r0, uint32_t& r1, uint32_t& r2, uint32_t& r3,
                                          uint32_t addr) {
    asm volatile("ldmatrix.sync.aligned.m8n8.x4.trans.shared.b16 {%0,%1,%2,%3}, [%4];"
                 : "=r"(r0), "=r"(r1), "=r"(r2), "=r"(r3) : "r"(addr));
}
__device__ __forceinline__ void mma16816(float* c, const uint32_t* a, const uint32_t* b) {
    asm volatile("mma.sync.aligned.m16n8k16.row.col.f32.bf16.bf16.f32 "
                 "{%0,%1,%2,%3}, {%4,%5,%6,%7}, {%8,%9}, {%0,%1,%2,%3};"
                 : "+f"(c[0]), "+f"(c[1]), "+f"(c[2]), "+f"(c[3])
                 : "r"(a[0]), "r"(a[1]), "r"(a[2]), "r"(a[3]), "r"(b[0]), "r"(b[1]));
}
__device__ __forceinline__ void split4(float4 v, uint2& hi, uint2& lo) {
    __nv_bfloat16 h0 = __float2bfloat16(v.x), h1 = __float2bfloat16(v.y);
    __nv_bfloat16 h2 = __float2bfloat16(v.z), h3 = __float2bfloat16(v.w);
    __nv_bfloat16 l0 = __float2bfloat16(v.x - __bfloat162float(h0));
    __nv_bfloat16 l1 = __float2bfloat16(v.y - __bfloat162float(h1));
    __nv_bfloat16 l2 = __float2bfloat16(v.z - __bfloat162float(h2));
    __nv_bfloat16 l3 = __float2bfloat16(v.w - __bfloat162float(h3));
    __nv_bfloat162 a = __nv_bfloat162(h0, h1), b = __nv_bfloat162(h2, h3);
    __nv_bfloat162 c = __nv_bfloat162(l0, l1), d = __nv_bfloat162(l2, l3);
    hi.x = *(uint32_t*)&a; hi.y = *(uint32_t*)&b;
    lo.x = *(uint32_t*)&c; lo.y = *(uint32_t*)&d;
}
__device__ __forceinline__ void split2(float a, float b, uint32_t& hi, uint32_t& lo) {
    __nv_bfloat16 h0 = __float2bfloat16(a), h1 = __float2bfloat16(b);
    __nv_bfloat16 l0 = __float2bfloat16(a - __bfloat162float(h0));
    __nv_bfloat16 l1 = __float2bfloat16(b - __bfloat162float(h1));
    __nv_bfloat162 H(h0, h1), L(l0, l1);
    hi = *(uint32_t*)&H; lo = *(uint32_t*)&L;
}
__device__ __forceinline__ float gelu_exact(float v) {
    return 0.5f * v * (1.0f + erff(v * 0.70710678118654752f));
}

// ---------------- fp32 -> split converter (grid-stride) ----------------
__global__ void split_kernel(const float4* __restrict__ src, uint4* __restrict__ dst, int n) {
    for (int i = blockIdx.x*blockDim.x + threadIdx.x; i < n; i += gridDim.x*blockDim.x) {
        uint2 hi, lo;
        split4(src[i], hi, lo);
        dst[i] = make_uint4(hi.x, hi.y, lo.x, lo.y);
    }
}

// ============ split-bf16 GEMM: 128 thr, 64x128 tile, 2 CTAs/SM ============
// smem per buffer: Ahi[5120] Alo[5120] Bhi[BHI] Blo[BHI]; two buffers.
#define A_LO 5120
#define BOFF 10240

template<int TRANSB, int OUTSPLIT>
__global__ void __launch_bounds__(128, 2)
mma_gemm(const uint4* __restrict__ As, const uint4* __restrict__ Bs,
         const float* __restrict__ bias, const float* __restrict__ res,
         float* __restrict__ C, uint4* __restrict__ Cs,
         int M, int N, int K, int act)
{
    extern __shared__ __align__(16) unsigned char sm[];
    constexpr int BHI   = TRANSB ? 10240 : 8704;
    constexpr int BUFSZ = BOFF + 2*BHI;
    const uint32_t sbase = smem_u32(sm);
    const int tid = threadIdx.x, lane = tid & 31, wid = tid >> 5;
    const int wm = wid & 1, wn = wid >> 1;
    const int m0 = blockIdx.y << 6, n0 = blockIdx.x << 7;
    const int grp = lane >> 2, tig = lane & 3;
    const int K4 = K >> 2, N4 = N >> 2;

    float acc[2][8][4];
    #pragma unroll
    for (int i = 0; i < 2; i++)
        #pragma unroll
        for (int j = 0; j < 8; j++)
            #pragma unroll
            for (int q = 0; q < 4; q++) acc[i][j][q] = 0.f;

    const int arow = tid >> 3, ak4 = tid & 7;     // A: rows arow+16p, k-group ak4
    const uint4* pa = As + (size_t)(m0 + arow) * K4 + ak4;

    const uint4* pb;
    bool bpred[8];
    if (TRANSB) {
        #pragma unroll
        for (int p = 0; p < 8; p++) bpred[p] = (n0 + arow + 16*p) < N;
        pb = Bs + (size_t)(n0 + arow) * K4 + ak4;
    } else {
        #pragma unroll
        for (int p = 0; p < 8; p++) bpred[p] = true;
        pb = Bs + (size_t)(tid >> 5) * N4 + (n0 >> 2) + (tid & 31);
    }

    const int NC = K >> 5;
    uint4 ra[4], rb[8];
    const uint4 z4 = make_uint4(0u, 0u, 0u, 0u);

    const uint32_t aoff_t = (uint32_t)arow * 80u + (uint32_t)ak4 * 8u;
    uint32_t boff_t;
    if (TRANSB) boff_t = aoff_t;
    else        boff_t = (uint32_t)(tid >> 5) * 272u + (uint32_t)(tid & 31) * 8u;

    // ---- load chunk 0 + store buffer 0 ----
    #pragma unroll
    for (int p = 0; p < 4; p++) ra[p] = pa[(size_t)(16*p) * K4];
    #pragma unroll
    for (int p = 0; p < 8; p++) {
        if (TRANSB) rb[p] = bpred[p] ? pb[(size_t)(16*p) * K4] : z4;
        else        rb[p] = pb[(size_t)(4*p) * N4];
    }
    #pragma unroll
    for (int p = 0; p < 4; p++) {
        uint32_t ao = aoff_t + (uint32_t)(16*p) * 80u;
        *(uint2*)(sm + ao)        = make_uint2(ra[p].x, ra[p].y);
        *(uint2*)(sm + A_LO + ao) = make_uint2(ra[p].z, ra[p].w);
    }
    #pragma unroll
    for (int p = 0; p < 8; p++) {
        uint32_t bo = TRANSB ? (boff_t + (uint32_t)(16*p) * 80u)
                             : (boff_t + (uint32_t)(4*p) * 272u);
        *(uint2*)(sm + BOFF + bo)       = make_uint2(rb[p].x, rb[p].y);
        *(uint2*)(sm + BOFF + BHI + bo) = make_uint2(rb[p].z, rb[p].w);
    }
    __syncthreads();

    for (int kc = 0; kc < NC; kc++) {
        // ---- prefetch next chunk into regs ----
        if (kc + 1 < NC) {
            const int kg = (kc + 1) * 8;
            #pragma unroll
            for (int p = 0; p < 4; p++) ra[p] = pa[(size_t)(16*p) * K4 + kg];
            #pragma unroll
            for (int p = 0; p < 8; p++) {
                if (TRANSB) rb[p] = bpred[p] ? pb[(size_t)(16*p) * K4 + kg] : z4;
                else        rb[p] = pb[((size_t)(4*p) + (size_t)(kc+1)*32) * N4];
            }
        }

        // ---- compute from buffer kc&1 ----
        const uint32_t cb = sbase + (uint32_t)(kc & 1) * BUFSZ;
        #pragma unroll
        for (int ks = 0; ks < 2; ks++) {
            uint32_t ah[2][4], al[2][4], bh[8][2], bl[8][2];
            #pragma unroll
            for (int mt = 0; mt < 2; mt++) {
                uint32_t addr = cb + (uint32_t)(wm*32 + mt*16 + (lane & 15)) * 80u
                              + (uint32_t)(ks*32) + ((lane >> 4) << 4);
                ldsm_x4(ah[mt][0], ah[mt][1], ah[mt][2], ah[mt][3], addr);
                ldsm_x4(al[mt][0], al[mt][1], al[mt][2], al[mt][3], addr + A_LO);
            }
            #pragma unroll
            for (int ntp = 0; ntp < 4; ntp++) {
                uint32_t r0, r1, r2, r3;
                if (TRANSB) {
                    uint32_t addr = cb + BOFF
                                  + (uint32_t)(wn*64 + ntp*16 + (lane & 15)) * 80u
                                  + (uint32_t)(ks*32) + ((lane >> 4) << 4);
                    ldsm_x4(r0, r1, r2, r3, addr);
                    bh[2*ntp][0] = r0; bh[2*ntp+1][0] = r1;
                    bh[2*ntp][1] = r2; bh[2*ntp+1][1] = r3;
                    ldsm_x4(r0, r1, r2, r3, addr + BHI);
                    bl[2*ntp][0] = r0; bl[2*ntp+1][0] = r1;
                    bl[2*ntp][1] = r2; bl[2*ntp+1][1] = r3;
                } else {
                    uint32_t addr = cb + BOFF
                                  + (uint32_t)(ks*16 + (lane & 15)) * 272u
                                  + (uint32_t)(wn*64 + ntp*16) * 2u + ((lane >> 4) << 4);
                    ldsm_x4_t(r0, r1, r2, r3, addr);
                    bh[2*ntp][0] = r0; bh[2*ntp][1] = r1;
                    bh[2*ntp+1][0] = r2; bh[2*ntp+1][1] = r3;
                    ldsm_x4_t(r0, r1, r2, r3, addr + BHI);
                    bl[2*ntp][0] = r0; bl[2*ntp][1] = r1;
                    bl[2*ntp+1][0] = r2; bl[2*ntp+1][1] = r3;
                }
            }
            #pragma unroll
            for (int mt = 0; mt < 2; mt++)
                #pragma unroll
                for (int nt = 0; nt < 8; nt++) {
                    mma16816(acc[mt][nt], ah[mt], bh[nt]);
                    mma16816(acc[mt][nt], ah[mt], bl[nt]);
                    mma16816(acc[mt][nt], al[mt], bh[nt]);
                }
        }

        // ---- store next chunk into buffer (kc+1)&1, one sync ----
        if (kc + 1 < NC) {
            unsigned char* nb = sm + (uint32_t)((kc + 1) & 1) * BUFSZ;
            #pragma unroll
            for (int p = 0; p < 4; p++) {
                uint32_t ao = aoff_t + (uint32_t)(16*p) * 80u;
                *(uint2*)(nb + ao)        = make_uint2(ra[p].x, ra[p].y);
                *(uint2*)(nb + A_LO + ao) = make_uint2(ra[p].z, ra[p].w);
            }
            #pragma unroll
            for (int p = 0; p < 8; p++) {
                uint32_t bo = TRANSB ? (boff_t + (uint32_t)(16*p) * 80u)
                                     : (boff_t + (uint32_t)(4*p) * 272u);
                *(uint2*)(nb + BOFF + bo)       = make_uint2(rb[p].x, rb[p].y);
                *(uint2*)(nb + BOFF + BHI + bo) = make_uint2(rb[p].z, rb[p].w);
            }
            __syncthreads();
        }
    }

    const int mrow = m0 + wm*32;
    #pragma unroll
    for (int mt = 0; mt < 2; mt++) {
        #pragma unroll
        for (int nt = 0; nt < 8; nt++) {
            int col = n0 + wn*64 + nt*8 + tig*2;
            bool ok0 = (!TRANSB) || (col < N);
            bool ok1 = (!TRANSB) || (col + 1 < N);
            float b0v = 0.f, b1v = 0.f;
            if (bias) { if (ok0) b0v = bias[col]; if (ok1) b1v = bias[col+1]; }
            #pragma unroll
            for (int hh = 0; hh < 2; hh++) {
                int row = mrow + mt*16 + grp + hh*8;
                float v0 = acc[mt][nt][2*hh+0] + b0v;
                float v1 = acc[mt][nt][2*hh+1] + b1v;
                if (act) { v0 = gelu_exact(v0); v1 = gelu_exact(v1); }
                if (OUTSPLIT) {
                    float x2 = __shfl_down_sync(0xffffffffu, v0, 1);
                    float x3 = __shfl_down_sync(0xffffffffu, v1, 1);
                    if ((tig & 1) == 0) {
                        uint2 hi, lo;
                        split4(make_float4(v0, v1, x2, x3), hi, lo);
                        Cs[(size_t)row * (N >> 2) + (col >> 2)] = make_uint4(hi.x, hi.y, lo.x, lo.y);
                    }
                } else {
                    size_t base = (size_t)row * N + col;
                    if (res) { if (ok0) v0 += res[base]; if (ok1) v1 += res[base+1]; }
                    if (!TRANSB) {
                        float2 o; o.x = v0; o.y = v1;
                        *(float2*)(C + base) = o;
                    } else {
                        if (ok0) C[base] = v0;
                        if (ok1) C[base+1] = v1;
                    }
                }
            }
        }
    }
}

// ============ fused QKV GEMM: 128 thr, 64x128 tile, split in/out ============
__global__ void __launch_bounds__(128, 2)
qkv_gemm(const uint4* __restrict__ As,
         const uint4* __restrict__ Wqs, const uint4* __restrict__ Wks, const uint4* __restrict__ Wvs,
         const float* __restrict__ bq_, const float* __restrict__ bk_, const float* __restrict__ bv_,
         uint4* __restrict__ Cs)
{
    extern __shared__ __align__(16) unsigned char sm[];
    constexpr int BHI   = 8704;
    constexpr int BUFSZ = BOFF + 2*BHI;   // 27648
    const int K4 = DD >> 2, N4 = DD >> 2;
    const uint32_t sbase = smem_u32(sm);
    const int tid = threadIdx.x, lane = tid & 31, wid = tid >> 5;
    const int wm = wid & 1, wn = wid >> 1;
    const int m0 = blockIdx.y << 6;
    const int sel = blockIdx.x / 6;
    const int n0 = (blockIdx.x % 6) << 7;
    const uint4* Bs   = (sel == 0) ? Wqs : (sel == 1) ? Wks : Wvs;
    const float* bias = (sel == 0) ? bq_ : (sel == 1) ? bk_ : bv_;
    const int grp = lane >> 2, tig = lane & 3;

    float acc[2][8][4];
    #pragma unroll
    for (int i = 0; i < 2; i++)
        #pragma unroll
        for (int j = 0; j < 8; j++)
            #pragma unroll
            for (int q = 0; q < 4; q++) acc[i][j][q] = 0.f;

    const int arow = tid >> 3, ak4 = tid & 7;
    const uint4* pa = As + (size_t)(m0 + arow) * K4 + ak4;
    const uint4* pb = Bs + (size_t)(tid >> 5) * N4 + (n0 >> 2) + (tid & 31);

    const int NC = DD >> 5;
    uint4 ra[4], rb[8];
    const uint32_t aoff_t = (uint32_t)arow * 80u + (uint32_t)ak4 * 8u;
    const uint32_t boff_t = (uint32_t)(tid >> 5) * 272u + (uint32_t)(tid & 31) * 8u;

    #pragma unroll
    for (int p = 0; p < 4; p++) ra[p] = pa[(size_t)(16*p) * K4];
    #pragma unroll
    for (int p = 0; p < 8; p++) rb[p] = pb[(size_t)(4*p) * N4];
    #pragma unroll
    for (int p = 0; p < 4; p++) {
        uint32_t ao = aoff_t + (uint32_t)(16*p) * 80u;
        *(uint2*)(sm + ao)        = make_uint2(ra[p].x, ra[p].y);
        *(uint2*)(sm + A_LO + ao) = make_uint2(ra[p].z, ra[p].w);
    }
    #pragma unroll
    for (int p = 0; p < 8; p++) {
        uint32_t bo = boff_t + (uint32_t)(4*p) * 272u;
        *(uint2*)(sm + BOFF + bo)       = make_uint2(rb[p].x, rb[p].y);
        *(uint2*)(sm + BOFF + BHI + bo) = make_uint2(rb[p].z, rb[p].w);
    }
    __syncthreads();

    for (int kc = 0; kc < NC; kc++) {
        if (kc + 1 < NC) {
            const int kg = (kc + 1) * 8;
            #pragma unroll
            for (int p = 0; p < 4; p++) ra[p] = pa[(size_t)(16*p) * K4 + kg];
            #pragma unroll
            for (int p = 0; p < 8; p++) rb[p] = pb[((size_t)(4*p) + (size_t)(kc+1)*32) * N4];
        }

        const uint32_t cb = sbase + (uint32_t)(kc & 1) * BUFSZ;
        #pragma unroll
        for (int ks = 0; ks < 2; ks++) {
            uint32_t ah[2][4], al[2][4], bh[8][2], bl[8][2];
            #pragma unroll
            for (int mt = 0; mt < 2; mt++) {
                uint32_t addr = cb + (uint32_t)(wm*32 + mt*16 + (lane & 15)) * 80u
                              + (uint32_t)(ks*32) + ((lane >> 4) << 4);
                ldsm_x4(ah[mt][0], ah[mt][1], ah[mt][2], ah[mt][3], addr);
                ldsm_x4(al[mt][0], al[mt][1], al[mt][2], al[mt][3], addr + A_LO);
            }
            #pragma unroll
            for (int ntp = 0; ntp < 4; ntp++) {
                uint32_t r0, r1, r2, r3;
                uint32_t addr = cb + BOFF
                              + (uint32_t)(ks*16 + (lane & 15)) * 272u
                              + (uint32_t)(wn*64 + ntp*16) * 2u + ((lane >> 4) << 4);
                ldsm_x4_t(r0, r1, r2, r3, addr);
                bh[2*ntp][0] = r0; bh[2*ntp][1] = r1;
                bh[2*ntp+1][0] = r2; bh[2*ntp+1][1] = r3;
                ldsm_x4_t(r0, r1, r2, r3, addr + BHI);
                bl[2*ntp][0] = r0; bl[2*ntp][1] = r1;
                bl[2*ntp+1][0] = r2; bl[2*ntp+1][1] = r3;
            }
            #pragma unroll
            for (int mt = 0; mt < 2; mt++)
                #pragma unroll
                for (int nt = 0; nt < 8; nt++) {
                    mma16816(acc[mt][nt], ah[mt], bh[nt]);
                    mma16816(acc[mt][nt], ah[mt], bl[nt]);
                    mma16816(acc[mt][nt], al[mt], bh[nt]);
                }
        }

        if (kc + 1 < NC) {
            unsigned char* nb = sm + (uint32_t)((kc + 1) & 1) * BUFSZ;
            #pragma unroll
            for (int p = 0; p < 4; p++) {
                uint32_t ao = aoff_t + (uint32_t)(16*p) * 80u;
                *(uint2*)(nb + ao)        = make_uint2(ra[p].x, ra[p].y);
                *(uint2*)(nb + A_LO + ao) = make_uint2(ra[p].z, ra[p].w);
            }
            #pragma unroll
            for (int p = 0; p < 8; p++) {
                uint32_t bo = boff_t + (uint32_t)(4*p) * 272u;
                *(uint2*)(nb + BOFF + bo)       = make_uint2(rb[p].x, rb[p].y);
                *(uint2*)(nb + BOFF + BHI + bo) = make_uint2(rb[p].z, rb[p].w);
            }
            __syncthreads();
        }
    }

    const int mrow = m0 + wm*32;
    #pragma unroll
    for (int mt = 0; mt < 2; mt++) {
        #pragma unroll
        for (int nt = 0; nt < 8; nt++) {
            int col = n0 + wn*64 + nt*8 + tig*2;
            float b0v = bias[col], b1v = bias[col+1];
            #pragma unroll
            for (int hh = 0; hh < 2; hh++) {
                int row = mrow + mt*16 + grp + hh*8;
                float v0 = acc[mt][nt][2*hh+0] + b0v;
                float v1 = acc[mt][nt][2*hh+1] + b1v;
                float x2 = __shfl_down_sync(0xffffffffu, v0, 1);
                float x3 = __shfl_down_sync(0xffffffffu, v1, 1);
                if ((tig & 1) == 0) {
                    uint2 hi, lo;
                    split4(make_float4(v0, v1, x2, x3), hi, lo);
                    Cs[(size_t)row * 576 + (size_t)(sel*192) + (col >> 2)]
                        = make_uint4(hi.x, hi.y, lo.x, lo.y);
                }
            }
        }
    }
}

// ============ flash attention (split qkv input, split attn output) ============
__global__ void __launch_bounds__(128, 1)
flash_kernel(const uint4* __restrict__ qkvs, const float* __restrict__ amask,
             uint4* __restrict__ outs)
{
    __shared__ __align__(16) unsigned char sm[4*9216 + 256];
    const int KHo = 0, KLo = 9216, VHo = 18432, VLo = 27648, AMo = 36864;
    const uint32_t sbase = smem_u32(sm);
    const int tid = threadIdx.x, lane = tid & 31, w = tid >> 5;
    const int grp = lane >> 2, tig = lane & 3;
    const int qt = (int)gridDim.x - 1 - (int)blockIdx.x;
    const int bh = blockIdx.y, b = bh / HH, h = bh % HH;
    const int q0 = qt * 64;

    uint32_t qh[4][4], ql[4][4];
    #pragma unroll
    for (int ks = 0; ks < 4; ks++)
        #pragma unroll
        for (int j = 0; j < 4; j++) {
            int row = q0 + w*16 + grp + (j & 1) * 8;
            int col = h*64 + ks*16 + (j >> 1) * 8 + tig*2;
            uint4 g = qkvs[(size_t)(b*SS + row) * 576 + (col >> 2)];
            if ((col & 3) == 0) { qh[ks][j] = g.x; ql[ks][j] = g.z; }
            else                { qh[ks][j] = g.y; ql[ks][j] = g.w; }
        }

    float o[8][4];
    #pragma unroll
    for (int i = 0; i < 8; i++)
        #pragma unroll
        for (int j = 0; j < 4; j++) o[i][j] = 0.f;
    float mrow0 = -1e30f, mrow1 = -1e30f, lrow0 = 0.f, lrow1 = 0.f;
    const int qr0 = q0 + w*16 + grp, qr1 = qr0 + 8;

    for (int kt = 0; kt <= qt; kt++) {
        __syncthreads();
        const size_t kgbase = (size_t)(b*SS + kt*64) * 576 + 192 + h*16;
        for (int idx = tid; idx < 64*16; idx += 128) {
            int r = idx >> 4, c4 = idx & 15;
            uint4 kg = qkvs[kgbase + (size_t)r*576 + c4];
            *(uint2*)(sm + KHo + r*144 + c4*8) = make_uint2(kg.x, kg.y);
            *(uint2*)(sm + KLo + r*144 + c4*8) = make_uint2(kg.z, kg.w);
            uint4 vg = qkvs[kgbase + 192 + (size_t)r*576 + c4];
            *(uint2*)(sm + VHo + r*144 + c4*8) = make_uint2(vg.x, vg.y);
            *(uint2*)(sm + VLo + r*144 + c4*8) = make_uint2(vg.z, vg.w);
        }
        if (tid < 64) ((float*)(sm + AMo))[tid] = amask[b*SS + kt*64 + tid];
        __syncthreads();

        float s[8][4];
        #pragma unroll
        for (int i = 0; i < 8; i++)
            #pragma unroll
            for (int j = 0; j < 4; j++) s[i][j] = 0.f;
        #pragma unroll
        for (int ks = 0; ks < 4; ks++) {
            uint32_t kh_[8][2], kl_[8][2];
            #pragma unroll
            for (int ntp = 0; ntp < 4; ntp++) {
                uint32_t r0, r1, r2, r3;
                uint32_t addr = sbase + KHo + (uint32_t)(ntp*16 + (lane & 15)) * 144u
                              + (uint32_t)(ks*32) + ((lane >> 4) << 4);
                ldsm_x4(r0, r1, r2, r3, addr);
                kh_[2*ntp][0] = r0; kh_[2*ntp][1] = r2;
                kh_[2*ntp+1][0] = r1; kh_[2*ntp+1][1] = r3;
                ldsm_x4(r0, r1, r2, r3, addr + (KLo - KHo));
                kl_[2*ntp][0] = r0; kl_[2*ntp][1] = r2;
                kl_[2*ntp+1][0] = r1; kl_[2*ntp+1][1] = r3;
            }
            #pragma unroll
            for (int nt = 0; nt < 8; nt++) {
                mma16816(s[nt], qh[ks], kh_[nt]);
                mma16816(s[nt], qh[ks], kl_[nt]);
                mma16816(s[nt], ql[ks], kh_[nt]);
            }
        }
        const float* am = (const float*)(sm + AMo);
        #pragma unroll
        for (int nt = 0; nt < 8; nt++) {
            int c0 = nt*8 + tig*2;
            int kc0 = kt*64 + c0, kc1 = kc0 + 1;
            float a0 = am[c0], a1 = am[c0+1];
            s[nt][0] = (kc0 <= qr0 && a0 != 0.f) ? s[nt][0]*0.125f : -1e30f;
            s[nt][1] = (kc1 <= qr0 && a1 != 0.f) ? s[nt][1]*0.125f : -1e30f;
            s[nt][2] = (kc0 <= qr1 && a0 != 0.f) ? s[nt][2]*0.125f : -1e30f;
            s[nt][3] = (kc1 <= qr1 && a1 != 0.f) ? s[nt][3]*0.125f : -1e30f;
        }
        float mx0 = -1e30f, mx1 = -1e30f;
        #pragma unroll
        for (int nt = 0; nt < 8; nt++) {
            mx0 = fmaxf(mx0, fmaxf(s[nt][0], s[nt][1]));
            mx1 = fmaxf(mx1, fmaxf(s[nt][2], s[nt][3]));
        }
        mx0 = fmaxf(mx0, __shfl_xor_sync(0xffffffffu, mx0, 1));
        mx0 = fmaxf(mx0, __shfl_xor_sync(0xffffffffu, mx0, 2));
        mx1 = fmaxf(mx1, __shfl_xor_sync(0xffffffffu, mx1, 1));
        mx1 = fmaxf(mx1, __shfl_xor_sync(0xffffffffu, mx1, 2));
        float mn0 = fmaxf(mrow0, mx0), mn1 = fmaxf(mrow1, mx1);
        float sc0 = __expf(mrow0 - mn0), sc1 = __expf(mrow1 - mn1);
        mrow0 = mn0; mrow1 = mn1;
        float rs0 = 0.f, rs1 = 0.f;
        #pragma unroll
        for (int nt = 0; nt < 8; nt++) {
            s[nt][0] = __expf(s[nt][0] - mn0); rs0 += s[nt][0];
            s[nt][1] = __expf(s[nt][1] - mn0); rs0 += s[nt][1];
            s[nt][2] = __expf(s[nt][2] - mn1); rs1 += s[nt][2];
            s[nt][3] = __expf(s[nt][3] - mn1); rs1 += s[nt][3];
        }
        rs0 += __shfl_xor_sync(0xffffffffu, rs0, 1);
        rs0 += __shfl_xor_sync(0xffffffffu, rs0, 2);
        rs1 += __shfl_xor_sync(0xffffffffu, rs1, 1);
        rs1 += __shfl_xor_sync(0xffffffffu, rs1, 2);
        lrow0 = lrow0*sc0 + rs0; lrow1 = lrow1*sc1 + rs1;
        #pragma unroll
        for (int nt = 0; nt < 8; nt++) {
            o[nt][0] *= sc0; o[nt][1] *= sc0;
            o[nt][2] *= sc1; o[nt][3] *= sc1;
        }
        #pragma unroll
        for (int ks = 0; ks < 4; ks++) {
            uint32_t pah[4], pal[4];
            split2(s[2*ks][0],   s[2*ks][1],   pah[0], pal[0]);
            split2(s[2*ks][2],   s[2*ks][3],   pah[1], pal[1]);
            split2(s[2*ks+1][0], s[2*ks+1][1], pah[2], pal[2]);
            split2(s[2*ks+1][2], s[2*ks+1][3], pah[3], pal[3]);
            uint32_t vh_[8][2], vl_[8][2];
            #pragma unroll
            for (int ntp = 0; ntp < 4; ntp++) {
                uint32_t r0, r1, r2, r3;
                uint32_t addr = sbase + VHo + (uint32_t)(ks*16 + (lane & 15)) * 144u
                              + (uint32_t)(ntp*32) + ((lane >> 4) << 4);
                ldsm_x4_t(r0, r1, r2, r3, addr);
                vh_[2*ntp][0] = r0; vh_[2*ntp][1] = r1;
                vh_[2*ntp+1][0] = r2; vh_[2*ntp+1][1] = r3;
                ldsm_x4_t(r0, r1, r2, r3, addr + (VLo - VHo));
                vl_[2*ntp][0] = r0; vl_[2*ntp][1] = r1;
                vl_[2*ntp+1][0] = r2; vl_[2*ntp+1][1] = r3;
            }
            #pragma unroll
            for (int nt = 0; nt < 8; nt++) {
                mma16816(o[nt], pah, vh_[nt]);
                mma16816(o[nt], pah, vl_[nt]);
                mma16816(o[nt], pal, vh_[nt]);
            }
        }
    }
    float inv0 = 1.f / lrow0, inv1 = 1.f / lrow1;
    #pragma unroll
    for (int nt = 0; nt < 8; nt++) {
        int col = h*64 + nt*8 + tig*2;
        float v0 = o[nt][0]*inv0, v1 = o[nt][1]*inv0;
        float u0 = o[nt][2]*inv1, u1 = o[nt][3]*inv1;
        float x2 = __shfl_down_sync(0xffffffffu, v0, 1);
        float x3 = __shfl_down_sync(0xffffffffu, v1, 1);
        float y2 = __shfl_down_sync(0xffffffffu, u0, 1);
        float y3 = __shfl_down_sync(0xffffffffu, u1, 1);
        if ((tig & 1) == 0) {
            uint2 hi, lo;
            split4(make_float4(v0, v1, x2, x3), hi, lo);
            outs[(size_t)(b*SS + qr0) * 192 + (col >> 2)] = make_uint4(hi.x, hi.y, lo.x, lo.y);
            split4(make_float4(u0, u1, y2, y3), hi, lo);
            outs[(size_t)(b*SS + qr1) * 192 + (col >> 2)] = make_uint4(hi.x, hi.y, lo.x, lo.y);
        }
    }
}

// ---------------- position ids ----------------
__global__ void posids_kernel(const float* __restrict__ amask, int* __restrict__ pos) {
    int b = blockIdx.x;
    if (threadIdx.x == 0) {
        float c = 0.f;
        for (int s = 0; s < SS; s++) {
            float m = amask[b*SS + s];
            c += m;
            pos[b*SS + s] = (m == 0.f) ? 0 : (int)(c - 1.f);
        }
    }
}

// ---------------- embedding ----------------
__global__ void embed_kernel(const int* __restrict__ ids, const int* __restrict__ pos,
                             const float* __restrict__ tok, const float* __restrict__ pemb,
                             float* __restrict__ x) {
    int row = blockIdx.x;
    int id = ids[row];
    int p  = pos[row];
    int tid = threadIdx.x;
    #pragma unroll
    for (int t = 0; t < 3; t++) {
        int d = tid + t*256;
        x[(size_t)row*DD + d] = tok[(size_t)id*DD + d] + pemb[(size_t)p*DD + d];
    }
}

// ---------------- layernorm -> split output (192 threads) ----------------
__global__ void ln_split_kernel(const float* __restrict__ x, const float* __restrict__ g,
                                const float* __restrict__ b, uint4* __restrict__ ys) {
    __shared__ float pr[6];
    int row = blockIdx.x, tid = threadIdx.x;   // 192 threads
    float4 v = ((const float4*)(x + (size_t)row*DD))[tid];
    float s = v.x + v.y + v.z + v.w;
    #pragma unroll
    for (int o = 16; o; o >>= 1) s += __shfl_xor_sync(0xffffffffu, s, o);
    if ((tid & 31) == 0) pr[tid >> 5] = s;
    __syncthreads();
    float mu = (pr[0]+pr[1]+pr[2]+pr[3]+pr[4]+pr[5]) * (1.f/DD);
    float dx = v.x-mu, dy = v.y-mu, dz = v.z-mu, dw = v.w-mu;
    float s2 = dx*dx + dy*dy + dz*dz + dw*dw;
    #pragma unroll
    for (int o = 16; o; o >>= 1) s2 += __shfl_xor_sync(0xffffffffu, s2, o);
    __syncthreads();
    if ((tid & 31) == 0) pr[tid >> 5] = s2;
    __syncthreads();
    float rstd = rsqrtf((pr[0]+pr[1]+pr[2]+pr[3]+pr[4]+pr[5]) * (1.f/DD) + 1e-5f);
    float4 gg = ((const float4*)g)[tid], bb = ((const float4*)b)[tid];
    float4 y = make_float4(dx*rstd*gg.x + bb.x, dy*rstd*gg.y + bb.y,
                           dz*rstd*gg.z + bb.z, dw*rstd*gg.w + bb.w);
    uint2 hi, lo; split4(y, hi, lo);
    ys[(size_t)row*192 + tid] = make_uint4(hi.x, hi.y, lo.x, lo.y);
}

// ---------------- launch ----------------
extern "C" void kernel_launch(void* const* d_in, const int* in_sizes, int n_in,
                              void* d_out, int out_size) {
    const int*   ids   = (const int*)  d_in[0];
    const float* amask = (const float*)d_in[1];
    const float* tok   = (const float*)d_in[2];
    const float* pemb  = (const float*)d_in[3];
    const float* ln1g  = (const float*)d_in[4];
    const float* ln1b  = (const float*)d_in[5];
    const float* Wq    = (const float*)d_in[6];
    const float* bq    = (const float*)d_in[7];
    const float* Wk    = (const float*)d_in[8];
    const float* bk    = (const float*)d_in[9];
    const float* Wv    = (const float*)d_in[10];
    const float* bv    = (const float*)d_in[11];
    const float* Wp    = (const float*)d_in[12];
    const float* bp    = (const float*)d_in[13];
    const float* ln2g  = (const float*)d_in[14];
    const float* ln2b  = (const float*)d_in[15];
    const float* W1    = (const float*)d_in[16];
    const float* b1    = (const float*)d_in[17];
    const float* W2    = (const float*)d_in[18];
    const float* b2    = (const float*)d_in[19];
    const float* lnfg  = (const float*)d_in[20];
    const float* lnfb  = (const float*)d_in[21];
    float* out = (float*)d_out;

    float *xp; int* pidp;
    uint4 *hs, *qkvs, *as, *fs, *wqs, *wks, *wvs, *wps, *w1s, *w2s, *toks;
    cudaGetSymbolAddress((void**)&xp,   g_x);
    cudaGetSymbolAddress((void**)&pidp, g_pos);
    cudaGetSymbolAddress((void**)&hs,   g_h_s);
    cudaGetSymbolAddress((void**)&qkvs, g_qkv_s);
    cudaGetSymbolAddress((void**)&as,   g_attn_s);
    cudaGetSymbolAddress((void**)&fs,   g_ff_s);
    cudaGetSymbolAddress((void**)&wqs,  g_wq_s);
    cudaGetSymbolAddress((void**)&wks,  g_wk_s);
    cudaGetSymbolAddress((void**)&wvs,  g_wv_s);
    cudaGetSymbolAddress((void**)&wps,  g_wp_s);
    cudaGetSymbolAddress((void**)&w1s,  g_w1_s);
    cudaGetSymbolAddress((void**)&w2s,  g_w2_s);
    cudaGetSymbolAddress((void**)&toks, g_tok_s);

    const int SM_T0 = 2*(BOFF + 2*8704);    // 55296
    const int SM_T1 = 2*(BOFF + 2*10240);   // 61440
    cudaFuncSetAttribute(mma_gemm<0,0>, cudaFuncAttributeMaxDynamicSharedMemorySize, SM_T0);
    cudaFuncSetAttribute(mma_gemm<0,1>, cudaFuncAttributeMaxDynamicSharedMemorySize, SM_T0);
    cudaFuncSetAttribute(mma_gemm<1,0>, cudaFuncAttributeMaxDynamicSharedMemorySize, SM_T1);
    cudaFuncSetAttribute(qkv_gemm, cudaFuncAttributeMaxDynamicSharedMemorySize, SM_T0);

    const int SG = 1184;
    split_kernel<<<SG, 256>>>((const float4*)Wq, wqs, LL*DD*DD/4);
    split_kernel<<<SG, 256>>>((const float4*)Wk, wks, LL*DD*DD/4);
    split_kernel<<<SG, 256>>>((const float4*)Wv, wvs, LL*DD*DD/4);
    split_kernel<<<SG, 256>>>((const float4*)Wp, wps, LL*DD*DD/4);
    split_kernel<<<SG, 256>>>((const float4*)W1, w1s, LL*DD*FF/4);
    split_kernel<<<SG, 256>>>((const float4*)W2, w2s, LL*DD*FF/4);
    split_kernel<<<SG, 256>>>((const float4*)tok, toks, VV*DD/4);

    posids_kernel<<<BB, 32>>>(amask, pidp);
    embed_kernel<<<MM, 256>>>(ids, pidp, tok, pemb, xp);

    dim3 gD(DD/128, MM/64);            // 6 x 32
    dim3 gQKV(18, MM/64);              // 18 x 32
    dim3 gF(FF/128, MM/64);            // 24 x 32
    dim3 gV((VV+127)/128, MM/64);      // 393 x 32
    dim3 gFA(SS/64, BB*HH);

    for (int l = 0; l < LL; l++) {
        const uint4* wql = wqs + (size_t)l*(DD*DD/4);
        const uint4* wkl = wks + (size_t)l*(DD*DD/4);
        const uint4* wvl = wvs + (size_t)l*(DD*DD/4);
        const uint4* wpl = wps + (size_t)l*(DD*DD/4);
        const uint4* w1l = w1s + (size_t)l*(DD*FF/4);
        const uint4* w2l = w2s + (size_t)l*(DD*FF/4);

        ln_split_kernel<<<MM, 192>>>(xp, ln1g + l*DD, ln1b + l*DD, hs);
        qkv_gemm<<<gQKV, 128, SM_T0>>>(hs, wql, wkl, wvl, bq + l*DD, bk + l*DD, bv + l*DD, qkvs);
        flash_kernel<<<gFA, 128>>>(qkvs, amask, as);
        mma_gemm<0,0><<<gD, 128, SM_T0>>>(as, wpl, bp + l*DD, xp, xp, nullptr, MM, DD, DD, 0);
        ln_split_kernel<<<MM, 192>>>(xp, ln2g + l*DD, ln2b + l*DD, hs);
        mma_gemm<0,1><<<gF, 128, SM_T0>>>(hs, w1l, b1 + l*FF, nullptr, nullptr, fs, MM, FF, DD, 1);
        mma_gemm<0,0><<<gD, 128, SM_T0>>>(fs, w2l, b2 + l*DD, xp, xp, nullptr, MM, DD, FF, 0);
    }

    ln_split_kernel<<<MM, 192>>>(xp, lnfg, lnfb, hs);
    mma_gemm<1,0><<<gV, 128, SM_T1>>>(hs, toks, nullptr, nullptr, out, nullptr, MM, VV, DD, 0);
}

// round 10
// speedup vs baseline: 1.4679x; 1.4679x over previous
#include <cuda_runtime.h>
#include <cuda_bf16.h>
#include <math.h>
#include <stdint.h>

#define BB 2
#define SS 1024
#define DD 768
#define HH 12
#define HDD 64
#define LL 12
#define VV 50257
#define FF 3072
#define MM (BB*SS)   // 2048

// ---------------- scratch (allocation-free) ----------------
// split format: uint4 group = {hi01, hi23, lo01, lo23} for 4 consecutive elems.
__device__ float g_x[MM*DD];
__device__ int   g_pos[BB*SS];
__device__ uint4 g_h_s[MM*DD/4];
__device__ uint4 g_qkv_s[MM*3*DD/4];
__device__ uint4 g_attn_s[MM*DD/4];
__device__ uint4 g_ff_s[MM*FF/4];
__device__ uint4 g_wq_s[LL*DD*DD/4];
__device__ uint4 g_wk_s[LL*DD*DD/4];
__device__ uint4 g_wv_s[LL*DD*DD/4];
__device__ uint4 g_wp_s[LL*DD*DD/4];
__device__ uint4 g_w1_s[LL*DD*FF/4];
__device__ uint4 g_w2_s[LL*DD*FF/4];
__device__ uint4 g_tok_s[(size_t)VV*DD/4];

// ================= helpers =================
__device__ __forceinline__ uint32_t smem_u32(const void* p) {
    uint32_t a;
    asm("{ .reg .u64 t; cvta.to.shared.u64 t, %1; cvt.u32.u64 %0, t; }" : "=r"(a) : "l"(p));
    return a;
}
__device__ __forceinline__ void ldsm_x4(uint32_t& r0, uint32_t& r1, uint32_t& r2, uint32_t& r3,
                                        uint32_t addr) {
    asm volatile("ldmatrix.sync.aligned.m8n8.x4.shared.b16 {%0,%1,%2,%3}, [%4];"
                 : "=r"(r0), "=r"(r1), "=r"(r2), "=r"(r3) : "r"(addr));
}
__device__ __forceinline__ void ldsm_x4_t(uint32_t& r0, uint32_t& r1, uint32_t& r2, uint32_t& r3,
                                          uint32_t addr) {
    asm volatile("ldmatrix.sync.aligned.m8n8.x4.trans.shared.b16 {%0,%1,%2,%3}, [%4];"
                 : "=r"(r0), "=r"(r1), "=r"(r2), "=r"(r3) : "r"(addr));
}
__device__ __forceinline__ void mma16816(float* c, const uint32_t* a, const uint32_t* b) {
    asm volatile("mma.sync.aligned.m16n8k16.row.col.f32.bf16.bf16.f32 "
                 "{%0,%1,%2,%3}, {%4,%5,%6,%7}, {%8,%9}, {%0,%1,%2,%3};"
                 : "+f"(c[0]), "+f"(c[1]), "+f"(c[2]), "+f"(c[3])
                 : "r"(a[0]), "r"(a[1]), "r"(a[2]), "r"(a[3]), "r"(b[0]), "r"(b[1]));
}
__device__ __forceinline__ void split4(float4 v, uint2& hi, uint2& lo) {
    __nv_bfloat16 h0 = __float2bfloat16(v.x), h1 = __float2bfloat16(v.y);
    __nv_bfloat16 h2 = __float2bfloat16(v.z), h3 = __float2bfloat16(v.w);
    __nv_bfloat16 l0 = __float2bfloat16(v.x - __bfloat162float(h0));
    __nv_bfloat16 l1 = __float2bfloat16(v.y - __bfloat162float(h1));
    __nv_bfloat16 l2 = __float2bfloat16(v.z - __bfloat162float(h2));
    __nv_bfloat16 l3 = __float2bfloat16(v.w - __bfloat162float(h3));
    __nv_bfloat162 a = __nv_bfloat162(h0, h1), b = __nv_bfloat162(h2, h3);
    __nv_bfloat162 c = __nv_bfloat162(l0, l1), d = __nv_bfloat162(l2, l3);
    hi.x = *(uint32_t*)&a; hi.y = *(uint32_t*)&b;
    lo.x = *(uint32_t*)&c; lo.y = *(uint32_t*)&d;
}
__device__ __forceinline__ void split2(float a, float b, uint32_t& hi, uint32_t& lo) {
    __nv_bfloat16 h0 = __float2bfloat16(a), h1 = __float2bfloat16(b);
    __nv_bfloat16 l0 = __float2bfloat16(a - __bfloat162float(h0));
    __nv_bfloat16 l1 = __float2bfloat16(b - __bfloat162float(h1));
    __nv_bfloat162 H(h0, h1), L(l0, l1);
    hi = *(uint32_t*)&H; lo = *(uint32_t*)&L;
}
__device__ __forceinline__ float gelu_exact(float v) {
    return 0.5f * v * (1.0f + erff(v * 0.70710678118654752f));
}

// ---------------- fp32 -> split converter (grid-stride) ----------------
__global__ void split_kernel(const float4* __restrict__ src, uint4* __restrict__ dst, int n) {
    for (int i = blockIdx.x*blockDim.x + threadIdx.x; i < n; i += gridDim.x*blockDim.x) {
        uint2 hi, lo;
        split4(src[i], hi, lo);
        dst[i] = make_uint4(hi.x, hi.y, lo.x, lo.y);
    }
}

// ============ split-bf16 GEMM, pre-split inputs, double-buffered smem ============
// smem per buffer: Ahi[10240] Alo[10240] Bhi[BHI] Blo[BHI]; two buffers.
// TRANSB=1 (LM head): grid is (m-tiles, n-tiles) so m varies fastest per wave
// (B tiles + whole A stay L2-resident; B streamed ~once instead of 16x).
template<int TRANSB, int OUTSPLIT>
__global__ void __launch_bounds__(256, 1)
mma_gemm(const uint4* __restrict__ As, const uint4* __restrict__ Bs,
         const float* __restrict__ bias, const float* __restrict__ res,
         float* __restrict__ C, uint4* __restrict__ Cs,
         int M, int N, int K, int act)
{
    extern __shared__ __align__(16) unsigned char sm[];
    constexpr int BHI   = TRANSB ? 10240 : 8704;
    constexpr int BOFF  = 20480;                 // A hi+lo
    constexpr int BUFSZ = BOFF + 2*BHI;
    const uint32_t sbase = smem_u32(sm);
    const int tid = threadIdx.x, lane = tid & 31, wid = tid >> 5;
    const int wm = wid & 3, wn = wid >> 2;
    const int m0 = (TRANSB ? blockIdx.x : blockIdx.y) << 7;
    const int n0 = (TRANSB ? blockIdx.y : blockIdx.x) << 7;
    const int grp = lane >> 2, tig = lane & 3;
    const int K4 = K >> 2, N4 = N >> 2;

    float acc[2][8][4];
    #pragma unroll
    for (int i = 0; i < 2; i++)
        #pragma unroll
        for (int j = 0; j < 8; j++)
            #pragma unroll
            for (int q = 0; q < 4; q++) acc[i][j][q] = 0.f;

    const int arow = tid >> 3, ak4 = tid & 7;
    const uint4* pa = As + (size_t)(m0 + arow) * K4 + ak4;

    const uint4* pb;
    bool bpred[4];
    if (TRANSB) {
        #pragma unroll
        for (int p = 0; p < 4; p++) bpred[p] = (n0 + arow + 32*p) < N;
        pb = Bs + (size_t)(n0 + arow) * K4 + ak4;
    } else {
        #pragma unroll
        for (int p = 0; p < 4; p++) bpred[p] = true;
        pb = Bs + (size_t)(tid >> 5) * N4 + (n0 >> 2) + (tid & 31);
    }

    const int NC = K >> 5;
    uint4 ra[4], rb[4];
    const uint4 z4 = make_uint4(0u, 0u, 0u, 0u);

    // smem store offsets (per-thread, buffer-relative)
    const uint32_t aoff_t = (uint32_t)arow * 80u + (uint32_t)ak4 * 8u;
    uint32_t boff_t;
    if (TRANSB) boff_t = aoff_t;
    else        boff_t = (uint32_t)(tid >> 5) * 272u + (uint32_t)(tid & 31) * 8u;

    // ---- load chunk 0 + store buffer 0 ----
    #pragma unroll
    for (int p = 0; p < 4; p++) {
        ra[p] = pa[(size_t)(32*p) * K4];
        if (TRANSB) rb[p] = bpred[p] ? pb[(size_t)(32*p) * K4] : z4;
        else        rb[p] = pb[(size_t)(8*p) * N4];
    }
    #pragma unroll
    for (int p = 0; p < 4; p++) {
        uint32_t ao = aoff_t + (uint32_t)(32*p) * 80u;
        *(uint2*)(sm + ao)         = make_uint2(ra[p].x, ra[p].y);
        *(uint2*)(sm + 10240 + ao) = make_uint2(ra[p].z, ra[p].w);
        uint32_t bo = TRANSB ? (boff_t + (uint32_t)(32*p) * 80u)
                             : (boff_t + (uint32_t)(8*p) * 272u);
        *(uint2*)(sm + BOFF + bo)       = make_uint2(rb[p].x, rb[p].y);
        *(uint2*)(sm + BOFF + BHI + bo) = make_uint2(rb[p].z, rb[p].w);
    }
    __syncthreads();

    for (int kc = 0; kc < NC; kc++) {
        // ---- prefetch next chunk into regs ----
        if (kc + 1 < NC) {
            const int kg = (kc + 1) * 8;
            #pragma unroll
            for (int p = 0; p < 4; p++) {
                ra[p] = pa[(size_t)(32*p) * K4 + kg];
                if (TRANSB) rb[p] = bpred[p] ? pb[(size_t)(32*p) * K4 + kg] : z4;
                else        rb[p] = pb[((size_t)(8*p) + (size_t)(kc+1)*32) * N4];
            }
        }

        // ---- compute from buffer kc&1 ----
        const uint32_t cb = sbase + (uint32_t)(kc & 1) * BUFSZ;
        #pragma unroll
        for (int ks = 0; ks < 2; ks++) {
            uint32_t ah[2][4], al[2][4], bh[8][2], bl[8][2];
            #pragma unroll
            for (int mt = 0; mt < 2; mt++) {
                uint32_t addr = cb + (uint32_t)(wm*32 + mt*16 + (lane & 15)) * 80u
                              + (uint32_t)(ks*32) + ((lane >> 4) << 4);
                ldsm_x4(ah[mt][0], ah[mt][1], ah[mt][2], ah[mt][3], addr);
                ldsm_x4(al[mt][0], al[mt][1], al[mt][2], al[mt][3], addr + 10240);
            }
            #pragma unroll
            for (int ntp = 0; ntp < 4; ntp++) {
                uint32_t r0, r1, r2, r3;
                if (TRANSB) {
                    uint32_t addr = cb + BOFF
                                  + (uint32_t)(wn*64 + ntp*16 + (lane & 15)) * 80u
                                  + (uint32_t)(ks*32) + ((lane >> 4) << 4);
                    ldsm_x4(r0, r1, r2, r3, addr);
                    bh[2*ntp][0] = r0; bh[2*ntp+1][0] = r1;
                    bh[2*ntp][1] = r2; bh[2*ntp+1][1] = r3;
                    ldsm_x4(r0, r1, r2, r3, addr + BHI);
                    bl[2*ntp][0] = r0; bl[2*ntp+1][0] = r1;
                    bl[2*ntp][1] = r2; bl[2*ntp+1][1] = r3;
                } else {
                    uint32_t addr = cb + BOFF
                                  + (uint32_t)(ks*16 + (lane & 15)) * 272u
                                  + (uint32_t)(wn*64 + ntp*16) * 2u + ((lane >> 4) << 4);
                    ldsm_x4_t(r0, r1, r2, r3, addr);
                    bh[2*ntp][0] = r0; bh[2*ntp][1] = r1;
                    bh[2*ntp+1][0] = r2; bh[2*ntp+1][1] = r3;
                    ldsm_x4_t(r0, r1, r2, r3, addr + BHI);
                    bl[2*ntp][0] = r0; bl[2*ntp][1] = r1;
                    bl[2*ntp+1][0] = r2; bl[2*ntp+1][1] = r3;
                }
            }
            #pragma unroll
            for (int mt = 0; mt < 2; mt++)
                #pragma unroll
                for (int nt = 0; nt < 8; nt++) {
                    mma16816(acc[mt][nt], ah[mt], bh[nt]);
                    mma16816(acc[mt][nt], ah[mt], bl[nt]);
                    mma16816(acc[mt][nt], al[mt], bh[nt]);
                }
        }

        // ---- store next chunk into buffer (kc+1)&1, one sync ----
        if (kc + 1 < NC) {
            unsigned char* nb = sm + (uint32_t)((kc + 1) & 1) * BUFSZ;
            #pragma unroll
            for (int p = 0; p < 4; p++) {
                uint32_t ao = aoff_t + (uint32_t)(32*p) * 80u;
                *(uint2*)(nb + ao)         = make_uint2(ra[p].x, ra[p].y);
                *(uint2*)(nb + 10240 + ao) = make_uint2(ra[p].z, ra[p].w);
                uint32_t bo = TRANSB ? (boff_t + (uint32_t)(32*p) * 80u)
                                     : (boff_t + (uint32_t)(8*p) * 272u);
                *(uint2*)(nb + BOFF + bo)       = make_uint2(rb[p].x, rb[p].y);
                *(uint2*)(nb + BOFF + BHI + bo) = make_uint2(rb[p].z, rb[p].w);
            }
            __syncthreads();
        }
    }

    const int mrow = m0 + wm*32;
    #pragma unroll
    for (int mt = 0; mt < 2; mt++) {
        #pragma unroll
        for (int nt = 0; nt < 8; nt++) {
            int col = n0 + wn*64 + nt*8 + tig*2;
            bool ok0 = (!TRANSB) || (col < N);
            bool ok1 = (!TRANSB) || (col + 1 < N);
            float b0v = 0.f, b1v = 0.f;
            if (bias) { if (ok0) b0v = bias[col]; if (ok1) b1v = bias[col+1]; }
            #pragma unroll
            for (int hh = 0; hh < 2; hh++) {
                int row = mrow + mt*16 + grp + hh*8;
                float v0 = acc[mt][nt][2*hh+0] + b0v;
                float v1 = acc[mt][nt][2*hh+1] + b1v;
                if (act) { v0 = gelu_exact(v0); v1 = gelu_exact(v1); }
                if (OUTSPLIT) {
                    float x2 = __shfl_down_sync(0xffffffffu, v0, 1);
                    float x3 = __shfl_down_sync(0xffffffffu, v1, 1);
                    if ((tig & 1) == 0) {
                        uint2 hi, lo;
                        split4(make_float4(v0, v1, x2, x3), hi, lo);
                        Cs[(size_t)row * (N >> 2) + (col >> 2)] = make_uint4(hi.x, hi.y, lo.x, lo.y);
                    }
                } else {
                    size_t base = (size_t)row * N + col;
                    if (res) { if (ok0) v0 += res[base]; if (ok1) v1 += res[base+1]; }
                    if (!TRANSB) {
                        float2 o; o.x = v0; o.y = v1;
                        *(float2*)(C + base) = o;
                    } else {
                        if (ok0) C[base] = v0;
                        if (ok1) C[base+1] = v1;
                    }
                }
            }
        }
    }
}

// ============ fused QKV GEMM: split in/out, double-buffered ============
__global__ void __launch_bounds__(256, 1)
qkv_gemm(const uint4* __restrict__ As,
         const uint4* __restrict__ Wqs, const uint4* __restrict__ Wks, const uint4* __restrict__ Wvs,
         const float* __restrict__ bq_, const float* __restrict__ bk_, const float* __restrict__ bv_,
         uint4* __restrict__ Cs)
{
    extern __shared__ __align__(16) unsigned char sm[];
    constexpr int BHI   = 8704;
    constexpr int BOFF  = 20480;
    constexpr int BUFSZ = BOFF + 2*BHI;   // 37888
    const int K4 = DD >> 2, N4 = DD >> 2;
    const uint32_t sbase = smem_u32(sm);
    const int tid = threadIdx.x, lane = tid & 31, wid = tid >> 5;
    const int wm = wid & 3, wn = wid >> 2;
    const int m0 = blockIdx.y << 7;
    const int sel = blockIdx.x / 6;
    const int n0 = (blockIdx.x % 6) << 7;
    const uint4* Bs   = (sel == 0) ? Wqs : (sel == 1) ? Wks : Wvs;
    const float* bias = (sel == 0) ? bq_ : (sel == 1) ? bk_ : bv_;
    const int grp = lane >> 2, tig = lane & 3;

    float acc[2][8][4];
    #pragma unroll
    for (int i = 0; i < 2; i++)
        #pragma unroll
        for (int j = 0; j < 8; j++)
            #pragma unroll
            for (int q = 0; q < 4; q++) acc[i][j][q] = 0.f;

    const int arow = tid >> 3, ak4 = tid & 7;
    const uint4* pa = As + (size_t)(m0 + arow) * K4 + ak4;
    const uint4* pb = Bs + (size_t)(tid >> 5) * N4 + (n0 >> 2) + (tid & 31);

    const int NC = DD >> 5;
    uint4 ra[4], rb[4];
    const uint32_t aoff_t = (uint32_t)arow * 80u + (uint32_t)ak4 * 8u;
    const uint32_t boff_t = (uint32_t)(tid >> 5) * 272u + (uint32_t)(tid & 31) * 8u;

    #pragma unroll
    for (int p = 0; p < 4; p++) {
        ra[p] = pa[(size_t)(32*p) * K4];
        rb[p] = pb[(size_t)(8*p) * N4];
    }
    #pragma unroll
    for (int p = 0; p < 4; p++) {
        uint32_t ao = aoff_t + (uint32_t)(32*p) * 80u;
        *(uint2*)(sm + ao)         = make_uint2(ra[p].x, ra[p].y);
        *(uint2*)(sm + 10240 + ao) = make_uint2(ra[p].z, ra[p].w);
        uint32_t bo = boff_t + (uint32_t)(8*p) * 272u;
        *(uint2*)(sm + BOFF + bo)       = make_uint2(rb[p].x, rb[p].y);
        *(uint2*)(sm + BOFF + BHI + bo) = make_uint2(rb[p].z, rb[p].w);
    }
    __syncthreads();

    for (int kc = 0; kc < NC; kc++) {
        if (kc + 1 < NC) {
            const int kg = (kc + 1) * 8;
            #pragma unroll
            for (int p = 0; p < 4; p++) {
                ra[p] = pa[(size_t)(32*p) * K4 + kg];
                rb[p] = pb[((size_t)(8*p) + (size_t)(kc+1)*32) * N4];
            }
        }

        const uint32_t cb = sbase + (uint32_t)(kc & 1) * BUFSZ;
        #pragma unroll
        for (int ks = 0; ks < 2; ks++) {
            uint32_t ah[2][4], al[2][4], bh[8][2], bl[8][2];
            #pragma unroll
            for (int mt = 0; mt < 2; mt++) {
                uint32_t addr = cb + (uint32_t)(wm*32 + mt*16 + (lane & 15)) * 80u
                              + (uint32_t)(ks*32) + ((lane >> 4) << 4);
                ldsm_x4(ah[mt][0], ah[mt][1], ah[mt][2], ah[mt][3], addr);
                ldsm_x4(al[mt][0], al[mt][1], al[mt][2], al[mt][3], addr + 10240);
            }
            #pragma unroll
            for (int ntp = 0; ntp < 4; ntp++) {
                uint32_t r0, r1, r2, r3;
                uint32_t addr = cb + BOFF
                              + (uint32_t)(ks*16 + (lane & 15)) * 272u
                              + (uint32_t)(wn*64 + ntp*16) * 2u + ((lane >> 4) << 4);
                ldsm_x4_t(r0, r1, r2, r3, addr);
                bh[2*ntp][0] = r0; bh[2*ntp][1] = r1;
                bh[2*ntp+1][0] = r2; bh[2*ntp+1][1] = r3;
                ldsm_x4_t(r0, r1, r2, r3, addr + BHI);
                bl[2*ntp][0] = r0; bl[2*ntp][1] = r1;
                bl[2*ntp+1][0] = r2; bl[2*ntp+1][1] = r3;
            }
            #pragma unroll
            for (int mt = 0; mt < 2; mt++)
                #pragma unroll
                for (int nt = 0; nt < 8; nt++) {
                    mma16816(acc[mt][nt], ah[mt], bh[nt]);
                    mma16816(acc[mt][nt], ah[mt], bl[nt]);
                    mma16816(acc[mt][nt], al[mt], bh[nt]);
                }
        }

        if (kc + 1 < NC) {
            unsigned char* nb = sm + (uint32_t)((kc + 1) & 1) * BUFSZ;
            #pragma unroll
            for (int p = 0; p < 4; p++) {
                uint32_t ao = aoff_t + (uint32_t)(32*p) * 80u;
                *(uint2*)(nb + ao)         = make_uint2(ra[p].x, ra[p].y);
                *(uint2*)(nb + 10240 + ao) = make_uint2(ra[p].z, ra[p].w);
                uint32_t bo = boff_t + (uint32_t)(8*p) * 272u;
                *(uint2*)(nb + BOFF + bo)       = make_uint2(rb[p].x, rb[p].y);
                *(uint2*)(nb + BOFF + BHI + bo) = make_uint2(rb[p].z, rb[p].w);
            }
            __syncthreads();
        }
    }

    const int mrow = m0 + wm*32;
    #pragma unroll
    for (int mt = 0; mt < 2; mt++) {
        #pragma unroll
        for (int nt = 0; nt < 8; nt++) {
            int col = n0 + wn*64 + nt*8 + tig*2;
            float b0v = bias[col], b1v = bias[col+1];
            #pragma unroll
            for (int hh = 0; hh < 2; hh++) {
                int row = mrow + mt*16 + grp + hh*8;
                float v0 = acc[mt][nt][2*hh+0] + b0v;
                float v1 = acc[mt][nt][2*hh+1] + b1v;
                float x2 = __shfl_down_sync(0xffffffffu, v0, 1);
                float x3 = __shfl_down_sync(0xffffffffu, v1, 1);
                if ((tig & 1) == 0) {
                    uint2 hi, lo;
                    split4(make_float4(v0, v1, x2, x3), hi, lo);
                    Cs[(size_t)row * 576 + (size_t)(sel*192) + (col >> 2)]
                        = make_uint4(hi.x, hi.y, lo.x, lo.y);
                }
            }
        }
    }
}

// ============ flash attention (split qkv input, split attn output) ============
__global__ void __launch_bounds__(128, 1)
flash_kernel(const uint4* __restrict__ qkvs, const float* __restrict__ amask,
             uint4* __restrict__ outs)
{
    __shared__ __align__(16) unsigned char sm[4*9216 + 256];
    const int KHo = 0, KLo = 9216, VHo = 18432, VLo = 27648, AMo = 36864;
    const uint32_t sbase = smem_u32(sm);
    const int tid = threadIdx.x, lane = tid & 31, w = tid >> 5;
    const int grp = lane >> 2, tig = lane & 3;
    const int qt = (int)gridDim.x - 1 - (int)blockIdx.x;
    const int bh = blockIdx.y, b = bh / HH, h = bh % HH;
    const int q0 = qt * 64;

    uint32_t qh[4][4], ql[4][4];
    #pragma unroll
    for (int ks = 0; ks < 4; ks++)
        #pragma unroll
        for (int j = 0; j < 4; j++) {
            int row = q0 + w*16 + grp + (j & 1) * 8;
            int col = h*64 + ks*16 + (j >> 1) * 8 + tig*2;
            uint4 g = qkvs[(size_t)(b*SS + row) * 576 + (col >> 2)];
            if ((col & 3) == 0) { qh[ks][j] = g.x; ql[ks][j] = g.z; }
            else                { qh[ks][j] = g.y; ql[ks][j] = g.w; }
        }

    float o[8][4];
    #pragma unroll
    for (int i = 0; i < 8; i++)
        #pragma unroll
        for (int j = 0; j < 4; j++) o[i][j] = 0.f;
    float mrow0 = -1e30f, mrow1 = -1e30f, lrow0 = 0.f, lrow1 = 0.f;
    const int qr0 = q0 + w*16 + grp, qr1 = qr0 + 8;

    for (int kt = 0; kt <= qt; kt++) {
        __syncthreads();
        const size_t kgbase = (size_t)(b*SS + kt*64) * 576 + 192 + h*16;
        for (int idx = tid; idx < 64*16; idx += 128) {
            int r = idx >> 4, c4 = idx & 15;
            uint4 kg = qkvs[kgbase + (size_t)r*576 + c4];
            *(uint2*)(sm + KHo + r*144 + c4*8) = make_uint2(kg.x, kg.y);
            *(uint2*)(sm + KLo + r*144 + c4*8) = make_uint2(kg.z, kg.w);
            uint4 vg = qkvs[kgbase + 192 + (size_t)r*576 + c4];
            *(uint2*)(sm + VHo + r*144 + c4*8) = make_uint2(vg.x, vg.y);
            *(uint2*)(sm + VLo + r*144 + c4*8) = make_uint2(vg.z, vg.w);
        }
        if (tid < 64) ((float*)(sm + AMo))[tid] = amask[b*SS + kt*64 + tid];
        __syncthreads();

        float s[8][4];
        #pragma unroll
        for (int i = 0; i < 8; i++)
            #pragma unroll
            for (int j = 0; j < 4; j++) s[i][j] = 0.f;
        #pragma unroll
        for (int ks = 0; ks < 4; ks++) {
            uint32_t kh_[8][2], kl_[8][2];
            #pragma unroll
            for (int ntp = 0; ntp < 4; ntp++) {
                uint32_t r0, r1, r2, r3;
                uint32_t addr = sbase + KHo + (uint32_t)(ntp*16 + (lane & 15)) * 144u
                              + (uint32_t)(ks*32) + ((lane >> 4) << 4);
                ldsm_x4(r0, r1, r2, r3, addr);
                kh_[2*ntp][0] = r0; kh_[2*ntp][1] = r2;
                kh_[2*ntp+1][0] = r1; kh_[2*ntp+1][1] = r3;
                ldsm_x4(r0, r1, r2, r3, addr + (KLo - KHo));
                kl_[2*ntp][0] = r0; kl_[2*ntp][1] = r2;
                kl_[2*ntp+1][0] = r1; kl_[2*ntp+1][1] = r3;
            }
            #pragma unroll
            for (int nt = 0; nt < 8; nt++) {
                mma16816(s[nt], qh[ks], kh_[nt]);
                mma16816(s[nt], qh[ks], kl_[nt]);
                mma16816(s[nt], ql[ks], kh_[nt]);
            }
        }
        const float* am = (const float*)(sm + AMo);
        #pragma unroll
        for (int nt = 0; nt < 8; nt++) {
            int c0 = nt*8 + tig*2;
            int kc0 = kt*64 + c0, kc1 = kc0 + 1;
            float a0 = am[c0], a1 = am[c0+1];
            s[nt][0] = (kc0 <= qr0 && a0 != 0.f) ? s[nt][0]*0.125f : -1e30f;
            s[nt][1] = (kc1 <= qr0 && a1 != 0.f) ? s[nt][1]*0.125f : -1e30f;
            s[nt][2] = (kc0 <= qr1 && a0 != 0.f) ? s[nt][2]*0.125f : -1e30f;
            s[nt][3] = (kc1 <= qr1 && a1 != 0.f) ? s[nt][3]*0.125f : -1e30f;
        }
        float mx0 = -1e30f, mx1 = -1e30f;
        #pragma unroll
        for (int nt = 0; nt < 8; nt++) {
            mx0 = fmaxf(mx0, fmaxf(s[nt][0], s[nt][1]));
            mx1 = fmaxf(mx1, fmaxf(s[nt][2], s[nt][3]));
        }
        mx0 = fmaxf(mx0, __shfl_xor_sync(0xffffffffu, mx0, 1));
        mx0 = fmaxf(mx0, __shfl_xor_sync(0xffffffffu, mx0, 2));
        mx1 = fmaxf(mx1, __shfl_xor_sync(0xffffffffu, mx1, 1));
        mx1 = fmaxf(mx1, __shfl_xor_sync(0xffffffffu, mx1, 2));
        float mn0 = fmaxf(mrow0, mx0), mn1 = fmaxf(mrow1, mx1);
        float sc0 = __expf(mrow0 - mn0), sc1 = __expf(mrow1 - mn1);
        mrow0 = mn0; mrow1 = mn1;
        float rs0 = 0.f, rs1 = 0.f;
        #pragma unroll
        for (int nt = 0; nt < 8; nt++) {
            s[nt][0] = __expf(s[nt][0] - mn0); rs0 += s[nt][0];
            s[nt][1] = __expf(s[nt][1] - mn0); rs0 += s[nt][1];
            s[nt][2] = __expf(s[nt][2] - mn1); rs1 += s[nt][2];
            s[nt][3] = __expf(s[nt][3] - mn1); rs1 += s[nt][3];
        }
        rs0 += __shfl_xor_sync(0xffffffffu, rs0, 1);
        rs0 += __shfl_xor_sync(0xffffffffu, rs0, 2);
        rs1 += __shfl_xor_sync(0xffffffffu, rs1, 1);
        rs1 += __shfl_xor_sync(0xffffffffu, rs1, 2);
        lrow0 = lrow0*sc0 + rs0; lrow1 = lrow1*sc1 + rs1;
        #pragma unroll
        for (int nt = 0; nt < 8; nt++) {
            o[nt][0] *= sc0; o[nt][1] *= sc0;
            o[nt][2] *= sc1; o[nt][3] *= sc1;
        }
        #pragma unroll
        for (int ks = 0; ks < 4; ks++) {
            uint32_t pah[4], pal[4];
            split2(s[2*ks][0],   s[2*ks][1],   pah[0], pal[0]);
            split2(s[2*ks][2],   s[2*ks][3],   pah[1], pal[1]);
            split2(s[2*ks+1][0], s[2*ks+1][1], pah[2], pal[2]);
            split2(s[2*ks+1][2], s[2*ks+1][3], pah[3], pal[3]);
            uint32_t vh_[8][2], vl_[8][2];
            #pragma unroll
            for (int ntp = 0; ntp < 4; ntp++) {
                uint32_t r0, r1, r2, r3;
                uint32_t addr = sbase + VHo + (uint32_t)(ks*16 + (lane & 15)) * 144u
                              + (uint32_t)(ntp*32) + ((lane >> 4) << 4);
                ldsm_x4_t(r0, r1, r2, r3, addr);
                vh_[2*ntp][0] = r0; vh_[2*ntp][1] = r1;
                vh_[2*ntp+1][0] = r2; vh_[2*ntp+1][1] = r3;
                ldsm_x4_t(r0, r1, r2, r3, addr + (VLo - VHo));
                vl_[2*ntp][0] = r0; vl_[2*ntp][1] = r1;
                vl_[2*ntp+1][0] = r2; vl_[2*ntp+1][1] = r3;
            }
            #pragma unroll
            for (int nt = 0; nt < 8; nt++) {
                mma16816(o[nt], pah, vh_[nt]);
                mma16816(o[nt], pah, vl_[nt]);
                mma16816(o[nt], pal, vh_[nt]);
            }
        }
    }
    float inv0 = 1.f / lrow0, inv1 = 1.f / lrow1;
    #pragma unroll
    for (int nt = 0; nt < 8; nt++) {
        int col = h*64 + nt*8 + tig*2;
        float v0 = o[nt][0]*inv0, v1 = o[nt][1]*inv0;
        float u0 = o[nt][2]*inv1, u1 = o[nt][3]*inv1;
        float x2 = __shfl_down_sync(0xffffffffu, v0, 1);
        float x3 = __shfl_down_sync(0xffffffffu, v1, 1);
        float y2 = __shfl_down_sync(0xffffffffu, u0, 1);
        float y3 = __shfl_down_sync(0xffffffffu, u1, 1);
        if ((tig & 1) == 0) {
            uint2 hi, lo;
            split4(make_float4(v0, v1, x2, x3), hi, lo);
            outs[(size_t)(b*SS + qr0) * 192 + (col >> 2)] = make_uint4(hi.x, hi.y, lo.x, lo.y);
            split4(make_float4(u0, u1, y2, y3), hi, lo);
            outs[(size_t)(b*SS + qr1) * 192 + (col >> 2)] = make_uint4(hi.x, hi.y, lo.x, lo.y);
        }
    }
}

// ---------------- position ids ----------------
__global__ void posids_kernel(const float* __restrict__ amask, int* __restrict__ pos) {
    int b = blockIdx.x;
    if (threadIdx.x == 0) {
        float c = 0.f;
        for (int s = 0; s < SS; s++) {
            float m = amask[b*SS + s];
            c += m;
            pos[b*SS + s] = (m == 0.f) ? 0 : (int)(c - 1.f);
        }
    }
}

// ---------------- embedding ----------------
__global__ void embed_kernel(const int* __restrict__ ids, const int* __restrict__ pos,
                             const float* __restrict__ tok, const float* __restrict__ pemb,
                             float* __restrict__ x) {
    int row = blockIdx.x;
    int id = ids[row];
    int p  = pos[row];
    int tid = threadIdx.x;
    #pragma unroll
    for (int t = 0; t < 3; t++) {
        int d = tid + t*256;
        x[(size_t)row*DD + d] = tok[(size_t)id*DD + d] + pemb[(size_t)p*DD + d];
    }
}

// ---------------- layernorm -> split output (192 threads) ----------------
__global__ void ln_split_kernel(const float* __restrict__ x, const float* __restrict__ g,
                                const float* __restrict__ b, uint4* __restrict__ ys) {
    __shared__ float pr[6];
    int row = blockIdx.x, tid = threadIdx.x;   // 192 threads
    float4 v = ((const float4*)(x + (size_t)row*DD))[tid];
    float s = v.x + v.y + v.z + v.w;
    #pragma unroll
    for (int o = 16; o; o >>= 1) s += __shfl_xor_sync(0xffffffffu, s, o);
    if ((tid & 31) == 0) pr[tid >> 5] = s;
    __syncthreads();
    float mu = (pr[0]+pr[1]+pr[2]+pr[3]+pr[4]+pr[5]) * (1.f/DD);
    float dx = v.x-mu, dy = v.y-mu, dz = v.z-mu, dw = v.w-mu;
    float s2 = dx*dx + dy*dy + dz*dz + dw*dw;
    #pragma unroll
    for (int o = 16; o; o >>= 1) s2 += __shfl_xor_sync(0xffffffffu, s2, o);
    __syncthreads();
    if ((tid & 31) == 0) pr[tid >> 5] = s2;
    __syncthreads();
    float rstd = rsqrtf((pr[0]+pr[1]+pr[2]+pr[3]+pr[4]+pr[5]) * (1.f/DD) + 1e-5f);
    float4 gg = ((const float4*)g)[tid], bb = ((const float4*)b)[tid];
    float4 y = make_float4(dx*rstd*gg.x + bb.x, dy*rstd*gg.y + bb.y,
                           dz*rstd*gg.z + bb.z, dw*rstd*gg.w + bb.w);
    uint2 hi, lo; split4(y, hi, lo);
    ys[(size_t)row*192 + tid] = make_uint4(hi.x, hi.y, lo.x, lo.y);
}

// ---------------- launch ----------------
extern "C" void kernel_launch(void* const* d_in, const int* in_sizes, int n_in,
                              void* d_out, int out_size) {
    const int*   ids   = (const int*)  d_in[0];
    const float* amask = (const float*)d_in[1];
    const float* tok   = (const float*)d_in[2];
    const float* pemb  = (const float*)d_in[3];
    const float* ln1g  = (const float*)d_in[4];
    const float* ln1b  = (const float*)d_in[5];
    const float* Wq    = (const float*)d_in[6];
    const float* bq    = (const float*)d_in[7];
    const float* Wk    = (const float*)d_in[8];
    const float* bk    = (const float*)d_in[9];
    const float* Wv    = (const float*)d_in[10];
    const float* bv    = (const float*)d_in[11];
    const float* Wp    = (const float*)d_in[12];
    const float* bp    = (const float*)d_in[13];
    const float* ln2g  = (const float*)d_in[14];
    const float* ln2b  = (const float*)d_in[15];
    const float* W1    = (const float*)d_in[16];
    const float* b1    = (const float*)d_in[17];
    const float* W2    = (const float*)d_in[18];
    const float* b2    = (const float*)d_in[19];
    const float* lnfg  = (const float*)d_in[20];
    const float* lnfb  = (const float*)d_in[21];
    float* out = (float*)d_out;

    float *xp; int* pidp;
    uint4 *hs, *qkvs, *as, *fs, *wqs, *wks, *wvs, *wps, *w1s, *w2s, *toks;
    cudaGetSymbolAddress((void**)&xp,   g_x);
    cudaGetSymbolAddress((void**)&pidp, g_pos);
    cudaGetSymbolAddress((void**)&hs,   g_h_s);
    cudaGetSymbolAddress((void**)&qkvs, g_qkv_s);
    cudaGetSymbolAddress((void**)&as,   g_attn_s);
    cudaGetSymbolAddress((void**)&fs,   g_ff_s);
    cudaGetSymbolAddress((void**)&wqs,  g_wq_s);
    cudaGetSymbolAddress((void**)&wks,  g_wk_s);
    cudaGetSymbolAddress((void**)&wvs,  g_wv_s);
    cudaGetSymbolAddress((void**)&wps,  g_wp_s);
    cudaGetSymbolAddress((void**)&w1s,  g_w1_s);
    cudaGetSymbolAddress((void**)&w2s,  g_w2_s);
    cudaGetSymbolAddress((void**)&toks, g_tok_s);

    const int SM_T0 = 2*(20480 + 2*8704);   // 75776
    const int SM_T1 = 2*(20480 + 2*10240);  // 81920
    cudaFuncSetAttribute(mma_gemm<0,0>, cudaFuncAttributeMaxDynamicSharedMemorySize, SM_T0);
    cudaFuncSetAttribute(mma_gemm<0,1>, cudaFuncAttributeMaxDynamicSharedMemorySize, SM_T0);
    cudaFuncSetAttribute(mma_gemm<1,0>, cudaFuncAttributeMaxDynamicSharedMemorySize, SM_T1);
    cudaFuncSetAttribute(qkv_gemm, cudaFuncAttributeMaxDynamicSharedMemorySize, SM_T0);

    const int SG = 1184;
    split_kernel<<<SG, 256>>>((const float4*)Wq, wqs, LL*DD*DD/4);
    split_kernel<<<SG, 256>>>((const float4*)Wk, wks, LL*DD*DD/4);
    split_kernel<<<SG, 256>>>((const float4*)Wv, wvs, LL*DD*DD/4);
    split_kernel<<<SG, 256>>>((const float4*)Wp, wps, LL*DD*DD/4);
    split_kernel<<<SG, 256>>>((const float4*)W1, w1s, LL*DD*FF/4);
    split_kernel<<<SG, 256>>>((const float4*)W2, w2s, LL*DD*FF/4);
    split_kernel<<<SG, 256>>>((const float4*)tok, toks, VV*DD/4);

    posids_kernel<<<BB, 32>>>(amask, pidp);
    embed_kernel<<<MM, 256>>>(ids, pidp, tok, pemb, xp);

    dim3 gD(DD/128, MM/128);           // 6 x 16
    dim3 gQKV(18, MM/128);             // 18 x 16
    dim3 gF(FF/128, MM/128);           // 24 x 16
    dim3 gV(MM/128, (VV+127)/128);     // 16 x 393 (m fastest -> B stays L2-resident)
    dim3 gFA(SS/64, BB*HH);

    for (int l = 0; l < LL; l++) {
        const uint4* wql = wqs + (size_t)l*(DD*DD/4);
        const uint4* wkl = wks + (size_t)l*(DD*DD/4);
        const uint4* wvl = wvs + (size_t)l*(DD*DD/4);
        const uint4* wpl = wps + (size_t)l*(DD*DD/4);
        const uint4* w1l = w1s + (size_t)l*(DD*FF/4);
        const uint4* w2l = w2s + (size_t)l*(DD*FF/4);

        ln_split_kernel<<<MM, 192>>>(xp, ln1g + l*DD, ln1b + l*DD, hs);
        qkv_gemm<<<gQKV, 256, SM_T0>>>(hs, wql, wkl, wvl, bq + l*DD, bk + l*DD, bv + l*DD, qkvs);
        flash_kernel<<<gFA, 128>>>(qkvs, amask, as);
        mma_gemm<0,0><<<gD, 256, SM_T0>>>(as, wpl, bp + l*DD, xp, xp, nullptr, MM, DD, DD, 0);
        ln_split_kernel<<<MM, 192>>>(xp, ln2g + l*DD, ln2b + l*DD, hs);
        mma_gemm<0,1><<<gF, 256, SM_T0>>>(hs, w1l, b1 + l*FF, nullptr, nullptr, fs, MM, FF, DD, 1);
        mma_gemm<0,0><<<gD, 256, SM_T0>>>(fs, w2l, b2 + l*DD, xp, xp, nullptr, MM, DD, FF, 0);
    }

    ln_split_kernel<<<MM, 192>>>(xp, lnfg, lnfb, hs);
    mma_gemm<1,0><<<gV, 256, SM_T1>>>(hs, toks, nullptr, nullptr, out, nullptr, MM, VV, DD, 0);
}

// round 11
// speedup vs baseline: 1.5570x; 1.0607x over previous
#include <cuda_runtime.h>
#include <cuda_bf16.h>
#include <math.h>
#include <stdint.h>

#define BB 2
#define SS 1024
#define DD 768
#define HH 12
#define HDD 64
#define LL 12
#define VV 50257
#define FF 3072
#define MM (BB*SS)   // 2048

// ---------------- scratch (allocation-free) ----------------
// split format: uint4 group = {hi01, hi23, lo01, lo23} for 4 consecutive elems.
__device__ float g_x[MM*DD];
__device__ int   g_pos[BB*SS];
__device__ uint4 g_h_s[MM*DD/4];
__device__ uint4 g_qkv_s[MM*3*DD/4];
__device__ uint4 g_attn_s[MM*DD/4];
__device__ uint4 g_ff_s[MM*FF/4];
__device__ float g_mlp2p[3*MM*DD];     // split-K partials for MLP2
__device__ uint4 g_wq_s[LL*DD*DD/4];
__device__ uint4 g_wk_s[LL*DD*DD/4];
__device__ uint4 g_wv_s[LL*DD*DD/4];
__device__ uint4 g_wp_s[LL*DD*DD/4];
__device__ uint4 g_w1_s[LL*DD*FF/4];
__device__ uint4 g_w2_s[LL*DD*FF/4];
__device__ uint4 g_tok_s[(size_t)VV*DD/4];

// ================= helpers =================
__device__ __forceinline__ uint32_t smem_u32(const void* p) {
    uint32_t a;
    asm("{ .reg .u64 t; cvta.to.shared.u64 t, %1; cvt.u32.u64 %0, t; }" : "=r"(a) : "l"(p));
    return a;
}
__device__ __forceinline__ void ldsm_x4(uint32_t& r0, uint32_t& r1, uint32_t& r2, uint32_t& r3,
                                        uint32_t addr) {
    asm volatile("ldmatrix.sync.aligned.m8n8.x4.shared.b16 {%0,%1,%2,%3}, [%4];"
                 : "=r"(r0), "=r"(r1), "=r"(r2), "=r"(r3) : "r"(addr));
}
__device__ __forceinline__ void ldsm_x4_t(uint32_t& r0, uint32_t& r1, uint32_t& r2, uint32_t& r3,
                                          uint32_t addr) {
    asm volatile("ldmatrix.sync.aligned.m8n8.x4.trans.shared.b16 {%0,%1,%2,%3}, [%4];"
                 : "=r"(r0), "=r"(r1), "=r"(r2), "=r"(r3) : "r"(addr));
}
__device__ __forceinline__ void mma16816(float* c, const uint32_t* a, const uint32_t* b) {
    asm volatile("mma.sync.aligned.m16n8k16.row.col.f32.bf16.bf16.f32 "
                 "{%0,%1,%2,%3}, {%4,%5,%6,%7}, {%8,%9}, {%0,%1,%2,%3};"
                 : "+f"(c[0]), "+f"(c[1]), "+f"(c[2]), "+f"(c[3])
                 : "r"(a[0]), "r"(a[1]), "r"(a[2]), "r"(a[3]), "r"(b[0]), "r"(b[1]));
}
__device__ __forceinline__ void split4(float4 v, uint2& hi, uint2& lo) {
    __nv_bfloat16 h0 = __float2bfloat16(v.x), h1 = __float2bfloat16(v.y);
    __nv_bfloat16 h2 = __float2bfloat16(v.z), h3 = __float2bfloat16(v.w);
    __nv_bfloat16 l0 = __float2bfloat16(v.x - __bfloat162float(h0));
    __nv_bfloat16 l1 = __float2bfloat16(v.y - __bfloat162float(h1));
    __nv_bfloat16 l2 = __float2bfloat16(v.z - __bfloat162float(h2));
    __nv_bfloat16 l3 = __float2bfloat16(v.w - __bfloat162float(h3));
    __nv_bfloat162 a = __nv_bfloat162(h0, h1), b = __nv_bfloat162(h2, h3);
    __nv_bfloat162 c = __nv_bfloat162(l0, l1), d = __nv_bfloat162(l2, l3);
    hi.x = *(uint32_t*)&a; hi.y = *(uint32_t*)&b;
    lo.x = *(uint32_t*)&c; lo.y = *(uint32_t*)&d;
}
__device__ __forceinline__ void split2(float a, float b, uint32_t& hi, uint32_t& lo) {
    __nv_bfloat16 h0 = __float2bfloat16(a), h1 = __float2bfloat16(b);
    __nv_bfloat16 l0 = __float2bfloat16(a - __bfloat162float(h0));
    __nv_bfloat16 l1 = __float2bfloat16(b - __bfloat162float(h1));
    __nv_bfloat162 H(h0, h1), L(l0, l1);
    hi = *(uint32_t*)&H; lo = *(uint32_t*)&L;
}
__device__ __forceinline__ float gelu_exact(float v) {
    return 0.5f * v * (1.0f + erff(v * 0.70710678118654752f));
}

// ---------------- fp32 -> split converter (grid-stride) ----------------
__global__ void split_kernel(const float4* __restrict__ src, uint4* __restrict__ dst, int n) {
    for (int i = blockIdx.x*blockDim.x + threadIdx.x; i < n; i += gridDim.x*blockDim.x) {
        uint2 hi, lo;
        split4(src[i], hi, lo);
        dst[i] = make_uint4(hi.x, hi.y, lo.x, lo.y);
    }
}

// ---------------- split-K reduce: x += p0+p1+p2 + bias ----------------
__global__ void reduce3_kernel(const float4* __restrict__ part, const float* __restrict__ bias,
                               float4* __restrict__ x) {
    const int S = MM*DD/4;
    for (int i = blockIdx.x*blockDim.x + threadIdx.x; i < S; i += gridDim.x*blockDim.x) {
        float4 a = part[i], b = part[i + S], c = part[i + 2*S];
        int c4 = (i % (DD/4)) * 4;
        float4 r = x[i];
        r.x += a.x + b.x + c.x + bias[c4+0];
        r.y += a.y + b.y + c.y + bias[c4+1];
        r.z += a.z + b.z + c.z + bias[c4+2];
        r.w += a.w + b.w + c.w + bias[c4+3];
        x[i] = r;
    }
}

// ============ split-bf16 GEMM, pre-split inputs, double-buffered smem ============
// lda4: A row stride in uint4 (K-major stride for A, and B when TRANSB=1).
// blockIdx.z = split-K slice: A/B advance by z*K along K; C advances by z*M*N.
template<int TRANSB, int OUTSPLIT>
__global__ void __launch_bounds__(256, 1)
mma_gemm(const uint4* __restrict__ As, const uint4* __restrict__ Bs,
         const float* __restrict__ bias, const float* __restrict__ res,
         float* __restrict__ C, uint4* __restrict__ Cs,
         int M, int N, int K, int act, int lda4)
{
    extern __shared__ __align__(16) unsigned char sm[];
    constexpr int BHI   = TRANSB ? 10240 : 8704;
    constexpr int BOFF  = 20480;                 // A hi+lo
    constexpr int BUFSZ = BOFF + 2*BHI;
    const uint32_t sbase = smem_u32(sm);
    const int tid = threadIdx.x, lane = tid & 31, wid = tid >> 5;
    const int wm = wid & 3, wn = wid >> 2;
    const int m0 = (TRANSB ? blockIdx.x : blockIdx.y) << 7;
    const int n0 = (TRANSB ? blockIdx.y : blockIdx.x) << 7;
    const int grp = lane >> 2, tig = lane & 3;
    const int N4 = N >> 2;

    // split-K slice offsets
    const int z = blockIdx.z;
    As += (size_t)z * (K >> 2);
    if (TRANSB) Bs += (size_t)z * (K >> 2);
    else        Bs += (size_t)z * K * N4;
    C  += (size_t)z * M * N;

    float acc[2][8][4];
    #pragma unroll
    for (int i = 0; i < 2; i++)
        #pragma unroll
        for (int j = 0; j < 8; j++)
            #pragma unroll
            for (int q = 0; q < 4; q++) acc[i][j][q] = 0.f;

    const int arow = tid >> 3, ak4 = tid & 7;
    const uint4* pa = As + (size_t)(m0 + arow) * lda4 + ak4;

    const uint4* pb;
    bool bpred[4];
    if (TRANSB) {
        #pragma unroll
        for (int p = 0; p < 4; p++) bpred[p] = (n0 + arow + 32*p) < N;
        pb = Bs + (size_t)(n0 + arow) * lda4 + ak4;
    } else {
        #pragma unroll
        for (int p = 0; p < 4; p++) bpred[p] = true;
        pb = Bs + (size_t)(tid >> 5) * N4 + (n0 >> 2) + (tid & 31);
    }

    const int NC = K >> 5;
    uint4 ra[4], rb[4];
    const uint4 z4 = make_uint4(0u, 0u, 0u, 0u);

    const uint32_t aoff_t = (uint32_t)arow * 80u + (uint32_t)ak4 * 8u;
    uint32_t boff_t;
    if (TRANSB) boff_t = aoff_t;
    else        boff_t = (uint32_t)(tid >> 5) * 272u + (uint32_t)(tid & 31) * 8u;

    // ---- load chunk 0 + store buffer 0 ----
    #pragma unroll
    for (int p = 0; p < 4; p++) {
        ra[p] = pa[(size_t)(32*p) * lda4];
        if (TRANSB) rb[p] = bpred[p] ? pb[(size_t)(32*p) * lda4] : z4;
        else        rb[p] = pb[(size_t)(8*p) * N4];
    }
    #pragma unroll
    for (int p = 0; p < 4; p++) {
        uint32_t ao = aoff_t + (uint32_t)(32*p) * 80u;
        *(uint2*)(sm + ao)         = make_uint2(ra[p].x, ra[p].y);
        *(uint2*)(sm + 10240 + ao) = make_uint2(ra[p].z, ra[p].w);
        uint32_t bo = TRANSB ? (boff_t + (uint32_t)(32*p) * 80u)
                             : (boff_t + (uint32_t)(8*p) * 272u);
        *(uint2*)(sm + BOFF + bo)       = make_uint2(rb[p].x, rb[p].y);
        *(uint2*)(sm + BOFF + BHI + bo) = make_uint2(rb[p].z, rb[p].w);
    }
    __syncthreads();

    for (int kc = 0; kc < NC; kc++) {
        if (kc + 1 < NC) {
            const int kg = (kc + 1) * 8;
            #pragma unroll
            for (int p = 0; p < 4; p++) {
                ra[p] = pa[(size_t)(32*p) * lda4 + kg];
                if (TRANSB) rb[p] = bpred[p] ? pb[(size_t)(32*p) * lda4 + kg] : z4;
                else        rb[p] = pb[((size_t)(8*p) + (size_t)(kc+1)*32) * N4];
            }
        }

        const uint32_t cb = sbase + (uint32_t)(kc & 1) * BUFSZ;
        #pragma unroll
        for (int ks = 0; ks < 2; ks++) {
            uint32_t ah[2][4], al[2][4], bh[8][2], bl[8][2];
            #pragma unroll
            for (int mt = 0; mt < 2; mt++) {
                uint32_t addr = cb + (uint32_t)(wm*32 + mt*16 + (lane & 15)) * 80u
                              + (uint32_t)(ks*32) + ((lane >> 4) << 4);
                ldsm_x4(ah[mt][0], ah[mt][1], ah[mt][2], ah[mt][3], addr);
                ldsm_x4(al[mt][0], al[mt][1], al[mt][2], al[mt][3], addr + 10240);
            }
            #pragma unroll
            for (int ntp = 0; ntp < 4; ntp++) {
                uint32_t r0, r1, r2, r3;
                if (TRANSB) {
                    uint32_t addr = cb + BOFF
                                  + (uint32_t)(wn*64 + ntp*16 + (lane & 15)) * 80u
                                  + (uint32_t)(ks*32) + ((lane >> 4) << 4);
                    ldsm_x4(r0, r1, r2, r3, addr);
                    bh[2*ntp][0] = r0; bh[2*ntp+1][0] = r1;
                    bh[2*ntp][1] = r2; bh[2*ntp+1][1] = r3;
                    ldsm_x4(r0, r1, r2, r3, addr + BHI);
                    bl[2*ntp][0] = r0; bl[2*ntp+1][0] = r1;
                    bl[2*ntp][1] = r2; bl[2*ntp+1][1] = r3;
                } else {
                    uint32_t addr = cb + BOFF
                                  + (uint32_t)(ks*16 + (lane & 15)) * 272u
                                  + (uint32_t)(wn*64 + ntp*16) * 2u + ((lane >> 4) << 4);
                    ldsm_x4_t(r0, r1, r2, r3, addr);
                    bh[2*ntp][0] = r0; bh[2*ntp][1] = r1;
                    bh[2*ntp+1][0] = r2; bh[2*ntp+1][1] = r3;
                    ldsm_x4_t(r0, r1, r2, r3, addr + BHI);
                    bl[2*ntp][0] = r0; bl[2*ntp][1] = r1;
                    bl[2*ntp+1][0] = r2; bl[2*ntp+1][1] = r3;
                }
            }
            #pragma unroll
            for (int mt = 0; mt < 2; mt++)
                #pragma unroll
                for (int nt = 0; nt < 8; nt++) {
                    mma16816(acc[mt][nt], ah[mt], bh[nt]);
                    mma16816(acc[mt][nt], ah[mt], bl[nt]);
                    mma16816(acc[mt][nt], al[mt], bh[nt]);
                }
        }

        if (kc + 1 < NC) {
            unsigned char* nb = sm + (uint32_t)((kc + 1) & 1) * BUFSZ;
            #pragma unroll
            for (int p = 0; p < 4; p++) {
                uint32_t ao = aoff_t + (uint32_t)(32*p) * 80u;
                *(uint2*)(nb + ao)         = make_uint2(ra[p].x, ra[p].y);
                *(uint2*)(nb + 10240 + ao) = make_uint2(ra[p].z, ra[p].w);
                uint32_t bo = TRANSB ? (boff_t + (uint32_t)(32*p) * 80u)
                                     : (boff_t + (uint32_t)(8*p) * 272u);
                *(uint2*)(nb + BOFF + bo)       = make_uint2(rb[p].x, rb[p].y);
                *(uint2*)(nb + BOFF + BHI + bo) = make_uint2(rb[p].z, rb[p].w);
            }
            __syncthreads();
        }
    }

    const int mrow = m0 + wm*32;
    #pragma unroll
    for (int mt = 0; mt < 2; mt++) {
        #pragma unroll
        for (int nt = 0; nt < 8; nt++) {
            int col = n0 + wn*64 + nt*8 + tig*2;
            bool ok0 = (!TRANSB) || (col < N);
            bool ok1 = (!TRANSB) || (col + 1 < N);
            float b0v = 0.f, b1v = 0.f;
            if (bias) { if (ok0) b0v = bias[col]; if (ok1) b1v = bias[col+1]; }
            #pragma unroll
            for (int hh = 0; hh < 2; hh++) {
                int row = mrow + mt*16 + grp + hh*8;
                float v0 = acc[mt][nt][2*hh+0] + b0v;
                float v1 = acc[mt][nt][2*hh+1] + b1v;
                if (act) { v0 = gelu_exact(v0); v1 = gelu_exact(v1); }
                if (OUTSPLIT) {
                    float x2 = __shfl_down_sync(0xffffffffu, v0, 1);
                    float x3 = __shfl_down_sync(0xffffffffu, v1, 1);
                    if ((tig & 1) == 0) {
                        uint2 hi, lo;
                        split4(make_float4(v0, v1, x2, x3), hi, lo);
                        Cs[(size_t)row * (N >> 2) + (col >> 2)] = make_uint4(hi.x, hi.y, lo.x, lo.y);
                    }
                } else {
                    size_t base = (size_t)row * N + col;
                    if (res) { if (ok0) v0 += res[base]; if (ok1) v1 += res[base+1]; }
                    if (!TRANSB) {
                        float2 o; o.x = v0; o.y = v1;
                        *(float2*)(C + base) = o;
                    } else {
                        if (ok0) C[base] = v0;
                        if (ok1) C[base+1] = v1;
                    }
                }
            }
        }
    }
}

// ============ fused QKV GEMM: split in/out, double-buffered ============
__global__ void __launch_bounds__(256, 1)
qkv_gemm(const uint4* __restrict__ As,
         const uint4* __restrict__ Wqs, const uint4* __restrict__ Wks, const uint4* __restrict__ Wvs,
         const float* __restrict__ bq_, const float* __restrict__ bk_, const float* __restrict__ bv_,
         uint4* __restrict__ Cs)
{
    extern __shared__ __align__(16) unsigned char sm[];
    constexpr int BHI   = 8704;
    constexpr int BOFF  = 20480;
    constexpr int BUFSZ = BOFF + 2*BHI;   // 37888
    const int K4 = DD >> 2, N4 = DD >> 2;
    const uint32_t sbase = smem_u32(sm);
    const int tid = threadIdx.x, lane = tid & 31, wid = tid >> 5;
    const int wm = wid & 3, wn = wid >> 2;
    const int m0 = blockIdx.y << 7;
    const int sel = blockIdx.x / 6;
    const int n0 = (blockIdx.x % 6) << 7;
    const uint4* Bs   = (sel == 0) ? Wqs : (sel == 1) ? Wks : Wvs;
    const float* bias = (sel == 0) ? bq_ : (sel == 1) ? bk_ : bv_;
    const int grp = lane >> 2, tig = lane & 3;

    float acc[2][8][4];
    #pragma unroll
    for (int i = 0; i < 2; i++)
        #pragma unroll
        for (int j = 0; j < 8; j++)
            #pragma unroll
            for (int q = 0; q < 4; q++) acc[i][j][q] = 0.f;

    const int arow = tid >> 3, ak4 = tid & 7;
    const uint4* pa = As + (size_t)(m0 + arow) * K4 + ak4;
    const uint4* pb = Bs + (size_t)(tid >> 5) * N4 + (n0 >> 2) + (tid & 31);

    const int NC = DD >> 5;
    uint4 ra[4], rb[4];
    const uint32_t aoff_t = (uint32_t)arow * 80u + (uint32_t)ak4 * 8u;
    const uint32_t boff_t = (uint32_t)(tid >> 5) * 272u + (uint32_t)(tid & 31) * 8u;

    #pragma unroll
    for (int p = 0; p < 4; p++) {
        ra[p] = pa[(size_t)(32*p) * K4];
        rb[p] = pb[(size_t)(8*p) * N4];
    }
    #pragma unroll
    for (int p = 0; p < 4; p++) {
        uint32_t ao = aoff_t + (uint32_t)(32*p) * 80u;
        *(uint2*)(sm + ao)         = make_uint2(ra[p].x, ra[p].y);
        *(uint2*)(sm + 10240 + ao) = make_uint2(ra[p].z, ra[p].w);
        uint32_t bo = boff_t + (uint32_t)(8*p) * 272u;
        *(uint2*)(sm + BOFF + bo)       = make_uint2(rb[p].x, rb[p].y);
        *(uint2*)(sm + BOFF + BHI + bo) = make_uint2(rb[p].z, rb[p].w);
    }
    __syncthreads();

    for (int kc = 0; kc < NC; kc++) {
        if (kc + 1 < NC) {
            const int kg = (kc + 1) * 8;
            #pragma unroll
            for (int p = 0; p < 4; p++) {
                ra[p] = pa[(size_t)(32*p) * K4 + kg];
                rb[p] = pb[((size_t)(8*p) + (size_t)(kc+1)*32) * N4];
            }
        }

        const uint32_t cb = sbase + (uint32_t)(kc & 1) * BUFSZ;
        #pragma unroll
        for (int ks = 0; ks < 2; ks++) {
            uint32_t ah[2][4], al[2][4], bh[8][2], bl[8][2];
            #pragma unroll
            for (int mt = 0; mt < 2; mt++) {
                uint32_t addr = cb + (uint32_t)(wm*32 + mt*16 + (lane & 15)) * 80u
                              + (uint32_t)(ks*32) + ((lane >> 4) << 4);
                ldsm_x4(ah[mt][0], ah[mt][1], ah[mt][2], ah[mt][3], addr);
                ldsm_x4(al[mt][0], al[mt][1], al[mt][2], al[mt][3], addr + 10240);
            }
            #pragma unroll
            for (int ntp = 0; ntp < 4; ntp++) {
                uint32_t r0, r1, r2, r3;
                uint32_t addr = cb + BOFF
                              + (uint32_t)(ks*16 + (lane & 15)) * 272u
                              + (uint32_t)(wn*64 + ntp*16) * 2u + ((lane >> 4) << 4);
                ldsm_x4_t(r0, r1, r2, r3, addr);
                bh[2*ntp][0] = r0; bh[2*ntp][1] = r1;
                bh[2*ntp+1][0] = r2; bh[2*ntp+1][1] = r3;
                ldsm_x4_t(r0, r1, r2, r3, addr + BHI);
                bl[2*ntp][0] = r0; bl[2*ntp][1] = r1;
                bl[2*ntp+1][0] = r2; bl[2*ntp+1][1] = r3;
            }
            #pragma unroll
            for (int mt = 0; mt < 2; mt++)
                #pragma unroll
                for (int nt = 0; nt < 8; nt++) {
                    mma16816(acc[mt][nt], ah[mt], bh[nt]);
                    mma16816(acc[mt][nt], ah[mt], bl[nt]);
                    mma16816(acc[mt][nt], al[mt], bh[nt]);
                }
        }

        if (kc + 1 < NC) {
            unsigned char* nb = sm + (uint32_t)((kc + 1) & 1) * BUFSZ;
            #pragma unroll
            for (int p = 0; p < 4; p++) {
                uint32_t ao = aoff_t + (uint32_t)(32*p) * 80u;
                *(uint2*)(nb + ao)         = make_uint2(ra[p].x, ra[p].y);
                *(uint2*)(nb + 10240 + ao) = make_uint2(ra[p].z, ra[p].w);
                uint32_t bo = boff_t + (uint32_t)(8*p) * 272u;
                *(uint2*)(nb + BOFF + bo)       = make_uint2(rb[p].x, rb[p].y);
                *(uint2*)(nb + BOFF + BHI + bo) = make_uint2(rb[p].z, rb[p].w);
            }
            __syncthreads();
        }
    }

    const int mrow = m0 + wm*32;
    #pragma unroll
    for (int mt = 0; mt < 2; mt++) {
        #pragma unroll
        for (int nt = 0; nt < 8; nt++) {
            int col = n0 + wn*64 + nt*8 + tig*2;
            float b0v = bias[col], b1v = bias[col+1];
            #pragma unroll
            for (int hh = 0; hh < 2; hh++) {
                int row = mrow + mt*16 + grp + hh*8;
                float v0 = acc[mt][nt][2*hh+0] + b0v;
                float v1 = acc[mt][nt][2*hh+1] + b1v;
                float x2 = __shfl_down_sync(0xffffffffu, v0, 1);
                float x3 = __shfl_down_sync(0xffffffffu, v1, 1);
                if ((tig & 1) == 0) {
                    uint2 hi, lo;
                    split4(make_float4(v0, v1, x2, x3), hi, lo);
                    Cs[(size_t)row * 576 + (size_t)(sel*192) + (col >> 2)]
                        = make_uint4(hi.x, hi.y, lo.x, lo.y);
                }
            }
        }
    }
}

// ============ flash attention (split qkv input, split attn output) ============
__global__ void __launch_bounds__(128, 1)
flash_kernel(const uint4* __restrict__ qkvs, const float* __restrict__ amask,
             uint4* __restrict__ outs)
{
    __shared__ __align__(16) unsigned char sm[4*9216 + 256];
    const int KHo = 0, KLo = 9216, VHo = 18432, VLo = 27648, AMo = 36864;
    const uint32_t sbase = smem_u32(sm);
    const int tid = threadIdx.x, lane = tid & 31, w = tid >> 5;
    const int grp = lane >> 2, tig = lane & 3;
    const int qt = (int)gridDim.x - 1 - (int)blockIdx.x;
    const int bh = blockIdx.y, b = bh / HH, h = bh % HH;
    const int q0 = qt * 64;

    uint32_t qh[4][4], ql[4][4];
    #pragma unroll
    for (int ks = 0; ks < 4; ks++)
        #pragma unroll
        for (int j = 0; j < 4; j++) {
            int row = q0 + w*16 + grp + (j & 1) * 8;
            int col = h*64 + ks*16 + (j >> 1) * 8 + tig*2;
            uint4 g = qkvs[(size_t)(b*SS + row) * 576 + (col >> 2)];
            if ((col & 3) == 0) { qh[ks][j] = g.x; ql[ks][j] = g.z; }
            else                { qh[ks][j] = g.y; ql[ks][j] = g.w; }
        }

    float o[8][4];
    #pragma unroll
    for (int i = 0; i < 8; i++)
        #pragma unroll
        for (int j = 0; j < 4; j++) o[i][j] = 0.f;
    float mrow0 = -1e30f, mrow1 = -1e30f, lrow0 = 0.f, lrow1 = 0.f;
    const int qr0 = q0 + w*16 + grp, qr1 = qr0 + 8;

    for (int kt = 0; kt <= qt; kt++) {
        __syncthreads();
        const size_t kgbase = (size_t)(b*SS + kt*64) * 576 + 192 + h*16;
        for (int idx = tid; idx < 64*16; idx += 128) {
            int r = idx >> 4, c4 = idx & 15;
            uint4 kg = qkvs[kgbase + (size_t)r*576 + c4];
            *(uint2*)(sm + KHo + r*144 + c4*8) = make_uint2(kg.x, kg.y);
            *(uint2*)(sm + KLo + r*144 + c4*8) = make_uint2(kg.z, kg.w);
            uint4 vg = qkvs[kgbase + 192 + (size_t)r*576 + c4];
            *(uint2*)(sm + VHo + r*144 + c4*8) = make_uint2(vg.x, vg.y);
            *(uint2*)(sm + VLo + r*144 + c4*8) = make_uint2(vg.z, vg.w);
        }
        if (tid < 64) ((float*)(sm + AMo))[tid] = amask[b*SS + kt*64 + tid];
        __syncthreads();

        float s[8][4];
        #pragma unroll
        for (int i = 0; i < 8; i++)
            #pragma unroll
            for (int j = 0; j < 4; j++) s[i][j] = 0.f;
        #pragma unroll
        for (int ks = 0; ks < 4; ks++) {
            uint32_t kh_[8][2], kl_[8][2];
            #pragma unroll
            for (int ntp = 0; ntp < 4; ntp++) {
                uint32_t r0, r1, r2, r3;
                uint32_t addr = sbase + KHo + (uint32_t)(ntp*16 + (lane & 15)) * 144u
                              + (uint32_t)(ks*32) + ((lane >> 4) << 4);
                ldsm_x4(r0, r1, r2, r3, addr);
                kh_[2*ntp][0] = r0; kh_[2*ntp][1] = r2;
                kh_[2*ntp+1][0] = r1; kh_[2*ntp+1][1] = r3;
                ldsm_x4(r0, r1, r2, r3, addr + (KLo - KHo));
                kl_[2*ntp][0] = r0; kl_[2*ntp][1] = r2;
                kl_[2*ntp+1][0] = r1; kl_[2*ntp+1][1] = r3;
            }
            #pragma unroll
            for (int nt = 0; nt < 8; nt++) {
                mma16816(s[nt], qh[ks], kh_[nt]);
                mma16816(s[nt], qh[ks], kl_[nt]);
                mma16816(s[nt], ql[ks], kh_[nt]);
            }
        }
        const float* am = (const float*)(sm + AMo);
        #pragma unroll
        for (int nt = 0; nt < 8; nt++) {
            int c0 = nt*8 + tig*2;
            int kc0 = kt*64 + c0, kc1 = kc0 + 1;
            float a0 = am[c0], a1 = am[c0+1];
            s[nt][0] = (kc0 <= qr0 && a0 != 0.f) ? s[nt][0]*0.125f : -1e30f;
            s[nt][1] = (kc1 <= qr0 && a1 != 0.f) ? s[nt][1]*0.125f : -1e30f;
            s[nt][2] = (kc0 <= qr1 && a0 != 0.f) ? s[nt][2]*0.125f : -1e30f;
            s[nt][3] = (kc1 <= qr1 && a1 != 0.f) ? s[nt][3]*0.125f : -1e30f;
        }
        float mx0 = -1e30f, mx1 = -1e30f;
        #pragma unroll
        for (int nt = 0; nt < 8; nt++) {
            mx0 = fmaxf(mx0, fmaxf(s[nt][0], s[nt][1]));
            mx1 = fmaxf(mx1, fmaxf(s[nt][2], s[nt][3]));
        }
        mx0 = fmaxf(mx0, __shfl_xor_sync(0xffffffffu, mx0, 1));
        mx0 = fmaxf(mx0, __shfl_xor_sync(0xffffffffu, mx0, 2));
        mx1 = fmaxf(mx1, __shfl_xor_sync(0xffffffffu, mx1, 1));
        mx1 = fmaxf(mx1, __shfl_xor_sync(0xffffffffu, mx1, 2));
        float mn0 = fmaxf(mrow0, mx0), mn1 = fmaxf(mrow1, mx1);
        float sc0 = __expf(mrow0 - mn0), sc1 = __expf(mrow1 - mn1);
        mrow0 = mn0; mrow1 = mn1;
        float rs0 = 0.f, rs1 = 0.f;
        #pragma unroll
        for (int nt = 0; nt < 8; nt++) {
            s[nt][0] = __expf(s[nt][0] - mn0); rs0 += s[nt][0];
            s[nt][1] = __expf(s[nt][1] - mn0); rs0 += s[nt][1];
            s[nt][2] = __expf(s[nt][2] - mn1); rs1 += s[nt][2];
            s[nt][3] = __expf(s[nt][3] - mn1); rs1 += s[nt][3];
        }
        rs0 += __shfl_xor_sync(0xffffffffu, rs0, 1);
        rs0 += __shfl_xor_sync(0xffffffffu, rs0, 2);
        rs1 += __shfl_xor_sync(0xffffffffu, rs1, 1);
        rs1 += __shfl_xor_sync(0xffffffffu, rs1, 2);
        lrow0 = lrow0*sc0 + rs0; lrow1 = lrow1*sc1 + rs1;
        #pragma unroll
        for (int nt = 0; nt < 8; nt++) {
            o[nt][0] *= sc0; o[nt][1] *= sc0;
            o[nt][2] *= sc1; o[nt][3] *= sc1;
        }
        #pragma unroll
        for (int ks = 0; ks < 4; ks++) {
            uint32_t pah[4], pal[4];
            split2(s[2*ks][0],   s[2*ks][1],   pah[0], pal[0]);
            split2(s[2*ks][2],   s[2*ks][3],   pah[1], pal[1]);
            split2(s[2*ks+1][0], s[2*ks+1][1], pah[2], pal[2]);
            split2(s[2*ks+1][2], s[2*ks+1][3], pah[3], pal[3]);
            uint32_t vh_[8][2], vl_[8][2];
            #pragma unroll
            for (int ntp = 0; ntp < 4; ntp++) {
                uint32_t r0, r1, r2, r3;
                uint32_t addr = sbase + VHo + (uint32_t)(ks*16 + (lane & 15)) * 144u
                              + (uint32_t)(ntp*32) + ((lane >> 4) << 4);
                ldsm_x4_t(r0, r1, r2, r3, addr);
                vh_[2*ntp][0] = r0; vh_[2*ntp][1] = r1;
                vh_[2*ntp+1][0] = r2; vh_[2*ntp+1][1] = r3;
                ldsm_x4_t(r0, r1, r2, r3, addr + (VLo - VHo));
                vl_[2*ntp][0] = r0; vl_[2*ntp][1] = r1;
                vl_[2*ntp+1][0] = r2; vl_[2*ntp+1][1] = r3;
            }
            #pragma unroll
            for (int nt = 0; nt < 8; nt++) {
                mma16816(o[nt], pah, vh_[nt]);
                mma16816(o[nt], pah, vl_[nt]);
                mma16816(o[nt], pal, vh_[nt]);
            }
        }
    }
    float inv0 = 1.f / lrow0, inv1 = 1.f / lrow1;
    #pragma unroll
    for (int nt = 0; nt < 8; nt++) {
        int col = h*64 + nt*8 + tig*2;
        float v0 = o[nt][0]*inv0, v1 = o[nt][1]*inv0;
        float u0 = o[nt][2]*inv1, u1 = o[nt][3]*inv1;
        float x2 = __shfl_down_sync(0xffffffffu, v0, 1);
        float x3 = __shfl_down_sync(0xffffffffu, v1, 1);
        float y2 = __shfl_down_sync(0xffffffffu, u0, 1);
        float y3 = __shfl_down_sync(0xffffffffu, u1, 1);
        if ((tig & 1) == 0) {
            uint2 hi, lo;
            split4(make_float4(v0, v1, x2, x3), hi, lo);
            outs[(size_t)(b*SS + qr0) * 192 + (col >> 2)] = make_uint4(hi.x, hi.y, lo.x, lo.y);
            split4(make_float4(u0, u1, y2, y3), hi, lo);
            outs[(size_t)(b*SS + qr1) * 192 + (col >> 2)] = make_uint4(hi.x, hi.y, lo.x, lo.y);
        }
    }
}

// ---------------- position ids ----------------
__global__ void posids_kernel(const float* __restrict__ amask, int* __restrict__ pos) {
    int b = blockIdx.x;
    if (threadIdx.x == 0) {
        float c = 0.f;
        for (int s = 0; s < SS; s++) {
            float m = amask[b*SS + s];
            c += m;
            pos[b*SS + s] = (m == 0.f) ? 0 : (int)(c - 1.f);
        }
    }
}

// ---------------- embedding ----------------
__global__ void embed_kernel(const int* __restrict__ ids, const int* __restrict__ pos,
                             const float* __restrict__ tok, const float* __restrict__ pemb,
                             float* __restrict__ x) {
    int row = blockIdx.x;
    int id = ids[row];
    int p  = pos[row];
    int tid = threadIdx.x;
    #pragma unroll
    for (int t = 0; t < 3; t++) {
        int d = tid + t*256;
        x[(size_t)row*DD + d] = tok[(size_t)id*DD + d] + pemb[(size_t)p*DD + d];
    }
}

// ---------------- layernorm -> split output (192 threads) ----------------
__global__ void ln_split_kernel(const float* __restrict__ x, const float* __restrict__ g,
                                const float* __restrict__ b, uint4* __restrict__ ys) {
    __shared__ float pr[6];
    int row = blockIdx.x, tid = threadIdx.x;   // 192 threads
    float4 v = ((const float4*)(x + (size_t)row*DD))[tid];
    float s = v.x + v.y + v.z + v.w;
    #pragma unroll
    for (int o = 16; o; o >>= 1) s += __shfl_xor_sync(0xffffffffu, s, o);
    if ((tid & 31) == 0) pr[tid >> 5] = s;
    __syncthreads();
    float mu = (pr[0]+pr[1]+pr[2]+pr[3]+pr[4]+pr[5]) * (1.f/DD);
    float dx = v.x-mu, dy = v.y-mu, dz = v.z-mu, dw = v.w-mu;
    float s2 = dx*dx + dy*dy + dz*dz + dw*dw;
    #pragma unroll
    for (int o = 16; o; o >>= 1) s2 += __shfl_xor_sync(0xffffffffu, s2, o);
    __syncthreads();
    if ((tid & 31) == 0) pr[tid >> 5] = s2;
    __syncthreads();
    float rstd = rsqrtf((pr[0]+pr[1]+pr[2]+pr[3]+pr[4]+pr[5]) * (1.f/DD) + 1e-5f);
    float4 gg = ((const float4*)g)[tid], bb = ((const float4*)b)[tid];
    float4 y = make_float4(dx*rstd*gg.x + bb.x, dy*rstd*gg.y + bb.y,
                           dz*rstd*gg.z + bb.z, dw*rstd*gg.w + bb.w);
    uint2 hi, lo; split4(y, hi, lo);
    ys[(size_t)row*192 + tid] = make_uint4(hi.x, hi.y, lo.x, lo.y);
}

// ---------------- launch ----------------
extern "C" void kernel_launch(void* const* d_in, const int* in_sizes, int n_in,
                              void* d_out, int out_size) {
    const int*   ids   = (const int*)  d_in[0];
    const float* amask = (const float*)d_in[1];
    const float* tok   = (const float*)d_in[2];
    const float* pemb  = (const float*)d_in[3];
    const float* ln1g  = (const float*)d_in[4];
    const float* ln1b  = (const float*)d_in[5];
    const float* Wq    = (const float*)d_in[6];
    const float* bq    = (const float*)d_in[7];
    const float* Wk    = (const float*)d_in[8];
    const float* bk    = (const float*)d_in[9];
    const float* Wv    = (const float*)d_in[10];
    const float* bv    = (const float*)d_in[11];
    const float* Wp    = (const float*)d_in[12];
    const float* bp    = (const float*)d_in[13];
    const float* ln2g  = (const float*)d_in[14];
    const float* ln2b  = (const float*)d_in[15];
    const float* W1    = (const float*)d_in[16];
    const float* b1    = (const float*)d_in[17];
    const float* W2    = (const float*)d_in[18];
    const float* b2    = (const float*)d_in[19];
    const float* lnfg  = (const float*)d_in[20];
    const float* lnfb  = (const float*)d_in[21];
    float* out = (float*)d_out;

    float *xp, *partp; int* pidp;
    uint4 *hs, *qkvs, *as, *fs, *wqs, *wks, *wvs, *wps, *w1s, *w2s, *toks;
    cudaGetSymbolAddress((void**)&xp,   g_x);
    cudaGetSymbolAddress((void**)&partp, g_mlp2p);
    cudaGetSymbolAddress((void**)&pidp, g_pos);
    cudaGetSymbolAddress((void**)&hs,   g_h_s);
    cudaGetSymbolAddress((void**)&qkvs, g_qkv_s);
    cudaGetSymbolAddress((void**)&as,   g_attn_s);
    cudaGetSymbolAddress((void**)&fs,   g_ff_s);
    cudaGetSymbolAddress((void**)&wqs,  g_wq_s);
    cudaGetSymbolAddress((void**)&wks,  g_wk_s);
    cudaGetSymbolAddress((void**)&wvs,  g_wv_s);
    cudaGetSymbolAddress((void**)&wps,  g_wp_s);
    cudaGetSymbolAddress((void**)&w1s,  g_w1_s);
    cudaGetSymbolAddress((void**)&w2s,  g_w2_s);
    cudaGetSymbolAddress((void**)&toks, g_tok_s);

    const int SM_T0 = 2*(20480 + 2*8704);   // 75776
    const int SM_T1 = 2*(20480 + 2*10240);  // 81920
    cudaFuncSetAttribute(mma_gemm<0,0>, cudaFuncAttributeMaxDynamicSharedMemorySize, SM_T0);
    cudaFuncSetAttribute(mma_gemm<0,1>, cudaFuncAttributeMaxDynamicSharedMemorySize, SM_T0);
    cudaFuncSetAttribute(mma_gemm<1,0>, cudaFuncAttributeMaxDynamicSharedMemorySize, SM_T1);
    cudaFuncSetAttribute(qkv_gemm, cudaFuncAttributeMaxDynamicSharedMemorySize, SM_T0);

    const int SG = 1184;
    split_kernel<<<SG, 256>>>((const float4*)Wq, wqs, LL*DD*DD/4);
    split_kernel<<<SG, 256>>>((const float4*)Wk, wks, LL*DD*DD/4);
    split_kernel<<<SG, 256>>>((const float4*)Wv, wvs, LL*DD*DD/4);
    split_kernel<<<SG, 256>>>((const float4*)Wp, wps, LL*DD*DD/4);
    split_kernel<<<SG, 256>>>((const float4*)W1, w1s, LL*DD*FF/4);
    split_kernel<<<SG, 256>>>((const float4*)W2, w2s, LL*DD*FF/4);
    split_kernel<<<SG, 256>>>((const float4*)tok, toks, VV*DD/4);

    posids_kernel<<<BB, 32>>>(amask, pidp);
    embed_kernel<<<MM, 256>>>(ids, pidp, tok, pemb, xp);

    dim3 gD(DD/128, MM/128);           // 6 x 16
    dim3 gQKV(18, MM/128);             // 18 x 16
    dim3 gF(FF/128, MM/128);           // 24 x 16
    dim3 gM2(DD/128, MM/128, 3);       // 6 x 16 x 3  (split-K)
    dim3 gV(MM/128, (VV+127)/128);     // 16 x 393 (m fastest)
    dim3 gFA(SS/64, BB*HH);

    for (int l = 0; l < LL; l++) {
        const uint4* wql = wqs + (size_t)l*(DD*DD/4);
        const uint4* wkl = wks + (size_t)l*(DD*DD/4);
        const uint4* wvl = wvs + (size_t)l*(DD*DD/4);
        const uint4* wpl = wps + (size_t)l*(DD*DD/4);
        const uint4* w1l = w1s + (size_t)l*(DD*FF/4);
        const uint4* w2l = w2s + (size_t)l*(DD*FF/4);

        ln_split_kernel<<<MM, 192>>>(xp, ln1g + l*DD, ln1b + l*DD, hs);
        qkv_gemm<<<gQKV, 256, SM_T0>>>(hs, wql, wkl, wvl, bq + l*DD, bk + l*DD, bv + l*DD, qkvs);
        flash_kernel<<<gFA, 128>>>(qkvs, amask, as);
        mma_gemm<0,0><<<gD, 256, SM_T0>>>(as, wpl, bp + l*DD, xp, xp, nullptr,
                                          MM, DD, DD, 0, DD/4);
        ln_split_kernel<<<MM, 192>>>(xp, ln2g + l*DD, ln2b + l*DD, hs);
        mma_gemm<0,1><<<gF, 256, SM_T0>>>(hs, w1l, b1 + l*FF, nullptr, nullptr, fs,
                                          MM, FF, DD, 1, DD/4);
        // MLP2 split-K=3: partials, then reduce (+bias +residual into x)
        mma_gemm<0,0><<<gM2, 256, SM_T0>>>(fs, w2l, nullptr, nullptr, partp, nullptr,
                                           MM, DD, FF/3, 0, FF/4);
        reduce3_kernel<<<1536, 256>>>((const float4*)partp, b2 + l*DD, (float4*)xp);
    }

    ln_split_kernel<<<MM, 192>>>(xp, lnfg, lnfb, hs);
    mma_gemm<1,0><<<gV, 256, SM_T1>>>(hs, toks, nullptr, nullptr, out, nullptr,
                                      MM, VV, DD, 0, DD/4);
}

// round 12
// speedup vs baseline: 1.5769x; 1.0128x over previous
#include <cuda_runtime.h>
#include <cuda_bf16.h>
#include <math.h>
#include <stdint.h>

#define BB 2
#define SS 1024
#define DD 768
#define HH 12
#define HDD 64
#define LL 12
#define VV 50257
#define FF 3072
#define MM (BB*SS)   // 2048

// ---------------- scratch (allocation-free) ----------------
// split format: uint4 group = {hi01, hi23, lo01, lo23} for 4 consecutive elems.
__device__ float g_x[MM*DD];
__device__ int   g_pos[BB*SS];
__device__ uint4 g_h_s[MM*DD/4];
__device__ uint4 g_qkv_s[MM*3*DD/4];
__device__ uint4 g_attn_s[MM*DD/4];
__device__ uint4 g_ff_s[MM*FF/4];
__device__ float g_mlp2p[3*MM*DD];     // split-K partials (MLP2 / proj)
__device__ uint4 g_wq_s[LL*DD*DD/4];
__device__ uint4 g_wk_s[LL*DD*DD/4];
__device__ uint4 g_wv_s[LL*DD*DD/4];
__device__ uint4 g_wp_s[LL*DD*DD/4];
__device__ uint4 g_w1_s[LL*DD*FF/4];
__device__ uint4 g_w2_s[LL*DD*FF/4];
__device__ uint4 g_tok_s[(size_t)VV*DD/4];

// ================= helpers =================
__device__ __forceinline__ uint32_t smem_u32(const void* p) {
    uint32_t a;
    asm("{ .reg .u64 t; cvta.to.shared.u64 t, %1; cvt.u32.u64 %0, t; }" : "=r"(a) : "l"(p));
    return a;
}
__device__ __forceinline__ void ldsm_x4(uint32_t& r0, uint32_t& r1, uint32_t& r2, uint32_t& r3,
                                        uint32_t addr) {
    asm volatile("ldmatrix.sync.aligned.m8n8.x4.shared.b16 {%0,%1,%2,%3}, [%4];"
                 : "=r"(r0), "=r"(r1), "=r"(r2), "=r"(r3) : "r"(addr));
}
__device__ __forceinline__ void ldsm_x4_t(uint32_t& r0, uint32_t& r1, uint32_t& r2, uint32_t& r3,
                                          uint32_t addr) {
    asm volatile("ldmatrix.sync.aligned.m8n8.x4.trans.shared.b16 {%0,%1,%2,%3}, [%4];"
                 : "=r"(r0), "=r"(r1), "=r"(r2), "=r"(r3) : "r"(addr));
}
__device__ __forceinline__ void mma16816(float* c, const uint32_t* a, const uint32_t* b) {
    asm volatile("mma.sync.aligned.m16n8k16.row.col.f32.bf16.bf16.f32 "
                 "{%0,%1,%2,%3}, {%4,%5,%6,%7}, {%8,%9}, {%0,%1,%2,%3};"
                 : "+f"(c[0]), "+f"(c[1]), "+f"(c[2]), "+f"(c[3])
                 : "r"(a[0]), "r"(a[1]), "r"(a[2]), "r"(a[3]), "r"(b[0]), "r"(b[1]));
}
__device__ __forceinline__ void split4(float4 v, uint2& hi, uint2& lo) {
    __nv_bfloat16 h0 = __float2bfloat16(v.x), h1 = __float2bfloat16(v.y);
    __nv_bfloat16 h2 = __float2bfloat16(v.z), h3 = __float2bfloat16(v.w);
    __nv_bfloat16 l0 = __float2bfloat16(v.x - __bfloat162float(h0));
    __nv_bfloat16 l1 = __float2bfloat16(v.y - __bfloat162float(h1));
    __nv_bfloat16 l2 = __float2bfloat16(v.z - __bfloat162float(h2));
    __nv_bfloat16 l3 = __float2bfloat16(v.w - __bfloat162float(h3));
    __nv_bfloat162 a = __nv_bfloat162(h0, h1), b = __nv_bfloat162(h2, h3);
    __nv_bfloat162 c = __nv_bfloat162(l0, l1), d = __nv_bfloat162(l2, l3);
    hi.x = *(uint32_t*)&a; hi.y = *(uint32_t*)&b;
    lo.x = *(uint32_t*)&c; lo.y = *(uint32_t*)&d;
}
__device__ __forceinline__ void split2(float a, float b, uint32_t& hi, uint32_t& lo) {
    __nv_bfloat16 h0 = __float2bfloat16(a), h1 = __float2bfloat16(b);
    __nv_bfloat16 l0 = __float2bfloat16(a - __bfloat162float(h0));
    __nv_bfloat16 l1 = __float2bfloat16(b - __bfloat162float(h1));
    __nv_bfloat162 H(h0, h1), L(l0, l1);
    hi = *(uint32_t*)&H; lo = *(uint32_t*)&L;
}
__device__ __forceinline__ float gelu_exact(float v) {
    return 0.5f * v * (1.0f + erff(v * 0.70710678118654752f));
}

// ---------------- fp32 -> split converter (grid-stride) ----------------
__global__ void split_kernel(const float4* __restrict__ src, uint4* __restrict__ dst, int n) {
    for (int i = blockIdx.x*blockDim.x + threadIdx.x; i < n; i += gridDim.x*blockDim.x) {
        uint2 hi, lo;
        split4(src[i], hi, lo);
        dst[i] = make_uint4(hi.x, hi.y, lo.x, lo.y);
    }
}

// ---------------- split-K reduce: x += p0+p1+p2 + bias ----------------
__global__ void reduce3_kernel(const float4* __restrict__ part, const float* __restrict__ bias,
                               float4* __restrict__ x) {
    const int S = MM*DD/4;
    for (int i = blockIdx.x*blockDim.x + threadIdx.x; i < S; i += gridDim.x*blockDim.x) {
        float4 a = part[i], b = part[i + S], c = part[i + 2*S];
        int c4 = (i % (DD/4)) * 4;
        float4 r = x[i];
        r.x += a.x + b.x + c.x + bias[c4+0];
        r.y += a.y + b.y + c.y + bias[c4+1];
        r.z += a.z + b.z + c.z + bias[c4+2];
        r.w += a.w + b.w + c.w + bias[c4+3];
        x[i] = r;
    }
}

// ============ split-bf16 GEMM, pre-split inputs, double-buffered smem ============
// lda4: A row stride in uint4 (K-major stride for A, and B when TRANSB=1).
// blockIdx.z = split-K slice: A/B advance by z*K along K; C advances by z*M*N.
template<int TRANSB, int OUTSPLIT>
__global__ void __launch_bounds__(256, 1)
mma_gemm(const uint4* __restrict__ As, const uint4* __restrict__ Bs,
         const float* __restrict__ bias, const float* __restrict__ res,
         float* __restrict__ C, uint4* __restrict__ Cs,
         int M, int N, int K, int act, int lda4)
{
    extern __shared__ __align__(16) unsigned char sm[];
    constexpr int BHI   = TRANSB ? 10240 : 8704;
    constexpr int BOFF  = 20480;                 // A hi+lo
    constexpr int BUFSZ = BOFF + 2*BHI;
    const uint32_t sbase = smem_u32(sm);
    const int tid = threadIdx.x, lane = tid & 31, wid = tid >> 5;
    const int wm = wid & 3, wn = wid >> 2;
    const int m0 = (TRANSB ? blockIdx.x : blockIdx.y) << 7;
    const int n0 = (TRANSB ? blockIdx.y : blockIdx.x) << 7;
    const int grp = lane >> 2, tig = lane & 3;
    const int N4 = N >> 2;

    // split-K slice offsets
    const int z = blockIdx.z;
    As += (size_t)z * (K >> 2);
    if (TRANSB) Bs += (size_t)z * (K >> 2);
    else        Bs += (size_t)z * K * N4;
    C  += (size_t)z * M * N;

    float acc[2][8][4];
    #pragma unroll
    for (int i = 0; i < 2; i++)
        #pragma unroll
        for (int j = 0; j < 8; j++)
            #pragma unroll
            for (int q = 0; q < 4; q++) acc[i][j][q] = 0.f;

    const int arow = tid >> 3, ak4 = tid & 7;
    const uint4* pa = As + (size_t)(m0 + arow) * lda4 + ak4;

    const uint4* pb;
    bool bpred[4];
    if (TRANSB) {
        #pragma unroll
        for (int p = 0; p < 4; p++) bpred[p] = (n0 + arow + 32*p) < N;
        pb = Bs + (size_t)(n0 + arow) * lda4 + ak4;
    } else {
        #pragma unroll
        for (int p = 0; p < 4; p++) bpred[p] = true;
        pb = Bs + (size_t)(tid >> 5) * N4 + (n0 >> 2) + (tid & 31);
    }

    const int NC = K >> 5;
    uint4 ra[4], rb[4];
    const uint4 z4 = make_uint4(0u, 0u, 0u, 0u);

    const uint32_t aoff_t = (uint32_t)arow * 80u + (uint32_t)ak4 * 8u;
    uint32_t boff_t;
    if (TRANSB) boff_t = aoff_t;
    else        boff_t = (uint32_t)(tid >> 5) * 272u + (uint32_t)(tid & 31) * 8u;

    // ---- load chunk 0 + store buffer 0 ----
    #pragma unroll
    for (int p = 0; p < 4; p++) {
        ra[p] = pa[(size_t)(32*p) * lda4];
        if (TRANSB) rb[p] = bpred[p] ? pb[(size_t)(32*p) * lda4] : z4;
        else        rb[p] = pb[(size_t)(8*p) * N4];
    }
    #pragma unroll
    for (int p = 0; p < 4; p++) {
        uint32_t ao = aoff_t + (uint32_t)(32*p) * 80u;
        *(uint2*)(sm + ao)         = make_uint2(ra[p].x, ra[p].y);
        *(uint2*)(sm + 10240 + ao) = make_uint2(ra[p].z, ra[p].w);
        uint32_t bo = TRANSB ? (boff_t + (uint32_t)(32*p) * 80u)
                             : (boff_t + (uint32_t)(8*p) * 272u);
        *(uint2*)(sm + BOFF + bo)       = make_uint2(rb[p].x, rb[p].y);
        *(uint2*)(sm + BOFF + BHI + bo) = make_uint2(rb[p].z, rb[p].w);
    }
    __syncthreads();

    for (int kc = 0; kc < NC; kc++) {
        if (kc + 1 < NC) {
            const int kg = (kc + 1) * 8;
            #pragma unroll
            for (int p = 0; p < 4; p++) {
                ra[p] = pa[(size_t)(32*p) * lda4 + kg];
                if (TRANSB) rb[p] = bpred[p] ? pb[(size_t)(32*p) * lda4 + kg] : z4;
                else        rb[p] = pb[((size_t)(8*p) + (size_t)(kc+1)*32) * N4];
            }
        }

        const uint32_t cb = sbase + (uint32_t)(kc & 1) * BUFSZ;
        #pragma unroll
        for (int ks = 0; ks < 2; ks++) {
            uint32_t ah[2][4], al[2][4], bh[8][2], bl[8][2];
            #pragma unroll
            for (int mt = 0; mt < 2; mt++) {
                uint32_t addr = cb + (uint32_t)(wm*32 + mt*16 + (lane & 15)) * 80u
                              + (uint32_t)(ks*32) + ((lane >> 4) << 4);
                ldsm_x4(ah[mt][0], ah[mt][1], ah[mt][2], ah[mt][3], addr);
                ldsm_x4(al[mt][0], al[mt][1], al[mt][2], al[mt][3], addr + 10240);
            }
            #pragma unroll
            for (int ntp = 0; ntp < 4; ntp++) {
                uint32_t r0, r1, r2, r3;
                if (TRANSB) {
                    uint32_t addr = cb + BOFF
                                  + (uint32_t)(wn*64 + ntp*16 + (lane & 15)) * 80u
                                  + (uint32_t)(ks*32) + ((lane >> 4) << 4);
                    ldsm_x4(r0, r1, r2, r3, addr);
                    bh[2*ntp][0] = r0; bh[2*ntp+1][0] = r1;
                    bh[2*ntp][1] = r2; bh[2*ntp+1][1] = r3;
                    ldsm_x4(r0, r1, r2, r3, addr + BHI);
                    bl[2*ntp][0] = r0; bl[2*ntp+1][0] = r1;
                    bl[2*ntp][1] = r2; bl[2*ntp+1][1] = r3;
                } else {
                    uint32_t addr = cb + BOFF
                                  + (uint32_t)(ks*16 + (lane & 15)) * 272u
                                  + (uint32_t)(wn*64 + ntp*16) * 2u + ((lane >> 4) << 4);
                    ldsm_x4_t(r0, r1, r2, r3, addr);
                    bh[2*ntp][0] = r0; bh[2*ntp][1] = r1;
                    bh[2*ntp+1][0] = r2; bh[2*ntp+1][1] = r3;
                    ldsm_x4_t(r0, r1, r2, r3, addr + BHI);
                    bl[2*ntp][0] = r0; bl[2*ntp][1] = r1;
                    bl[2*ntp+1][0] = r2; bl[2*ntp+1][1] = r3;
                }
            }
            #pragma unroll
            for (int mt = 0; mt < 2; mt++)
                #pragma unroll
                for (int nt = 0; nt < 8; nt++) {
                    mma16816(acc[mt][nt], ah[mt], bh[nt]);
                    mma16816(acc[mt][nt], ah[mt], bl[nt]);
                    mma16816(acc[mt][nt], al[mt], bh[nt]);
                }
        }

        if (kc + 1 < NC) {
            unsigned char* nb = sm + (uint32_t)((kc + 1) & 1) * BUFSZ;
            #pragma unroll
            for (int p = 0; p < 4; p++) {
                uint32_t ao = aoff_t + (uint32_t)(32*p) * 80u;
                *(uint2*)(nb + ao)         = make_uint2(ra[p].x, ra[p].y);
                *(uint2*)(nb + 10240 + ao) = make_uint2(ra[p].z, ra[p].w);
                uint32_t bo = TRANSB ? (boff_t + (uint32_t)(32*p) * 80u)
                                     : (boff_t + (uint32_t)(8*p) * 272u);
                *(uint2*)(nb + BOFF + bo)       = make_uint2(rb[p].x, rb[p].y);
                *(uint2*)(nb + BOFF + BHI + bo) = make_uint2(rb[p].z, rb[p].w);
            }
            __syncthreads();
        }
    }

    const int mrow = m0 + wm*32;
    #pragma unroll
    for (int mt = 0; mt < 2; mt++) {
        #pragma unroll
        for (int nt = 0; nt < 8; nt++) {
            int col = n0 + wn*64 + nt*8 + tig*2;
            bool ok0 = (!TRANSB) || (col < N);
            bool ok1 = (!TRANSB) || (col + 1 < N);
            float b0v = 0.f, b1v = 0.f;
            if (bias) { if (ok0) b0v = bias[col]; if (ok1) b1v = bias[col+1]; }
            #pragma unroll
            for (int hh = 0; hh < 2; hh++) {
                int row = mrow + mt*16 + grp + hh*8;
                float v0 = acc[mt][nt][2*hh+0] + b0v;
                float v1 = acc[mt][nt][2*hh+1] + b1v;
                if (act) { v0 = gelu_exact(v0); v1 = gelu_exact(v1); }
                if (OUTSPLIT) {
                    float x2 = __shfl_down_sync(0xffffffffu, v0, 1);
                    float x3 = __shfl_down_sync(0xffffffffu, v1, 1);
                    if ((tig & 1) == 0) {
                        uint2 hi, lo;
                        split4(make_float4(v0, v1, x2, x3), hi, lo);
                        Cs[(size_t)row * (N >> 2) + (col >> 2)] = make_uint4(hi.x, hi.y, lo.x, lo.y);
                    }
                } else {
                    size_t base = (size_t)row * N + col;
                    if (res) { if (ok0) v0 += res[base]; if (ok1) v1 += res[base+1]; }
                    if (!TRANSB) {
                        float2 o; o.x = v0; o.y = v1;
                        *(float2*)(C + base) = o;
                    } else {
                        if (ok0) C[base] = v0;
                        if (ok1) C[base+1] = v1;
                    }
                }
            }
        }
    }
}

// ============ fused QKV GEMM: split in/out, double-buffered ============
__global__ void __launch_bounds__(256, 1)
qkv_gemm(const uint4* __restrict__ As,
         const uint4* __restrict__ Wqs, const uint4* __restrict__ Wks, const uint4* __restrict__ Wvs,
         const float* __restrict__ bq_, const float* __restrict__ bk_, const float* __restrict__ bv_,
         uint4* __restrict__ Cs)
{
    extern __shared__ __align__(16) unsigned char sm[];
    constexpr int BHI   = 8704;
    constexpr int BOFF  = 20480;
    constexpr int BUFSZ = BOFF + 2*BHI;   // 37888
    const int K4 = DD >> 2, N4 = DD >> 2;
    const uint32_t sbase = smem_u32(sm);
    const int tid = threadIdx.x, lane = tid & 31, wid = tid >> 5;
    const int wm = wid & 3, wn = wid >> 2;
    const int m0 = blockIdx.y << 7;
    const int sel = blockIdx.x / 6;
    const int n0 = (blockIdx.x % 6) << 7;
    const uint4* Bs   = (sel == 0) ? Wqs : (sel == 1) ? Wks : Wvs;
    const float* bias = (sel == 0) ? bq_ : (sel == 1) ? bk_ : bv_;
    const int grp = lane >> 2, tig = lane & 3;

    float acc[2][8][4];
    #pragma unroll
    for (int i = 0; i < 2; i++)
        #pragma unroll
        for (int j = 0; j < 8; j++)
            #pragma unroll
            for (int q = 0; q < 4; q++) acc[i][j][q] = 0.f;

    const int arow = tid >> 3, ak4 = tid & 7;
    const uint4* pa = As + (size_t)(m0 + arow) * K4 + ak4;
    const uint4* pb = Bs + (size_t)(tid >> 5) * N4 + (n0 >> 2) + (tid & 31);

    const int NC = DD >> 5;
    uint4 ra[4], rb[4];
    const uint32_t aoff_t = (uint32_t)arow * 80u + (uint32_t)ak4 * 8u;
    const uint32_t boff_t = (uint32_t)(tid >> 5) * 272u + (uint32_t)(tid & 31) * 8u;

    #pragma unroll
    for (int p = 0; p < 4; p++) {
        ra[p] = pa[(size_t)(32*p) * K4];
        rb[p] = pb[(size_t)(8*p) * N4];
    }
    #pragma unroll
    for (int p = 0; p < 4; p++) {
        uint32_t ao = aoff_t + (uint32_t)(32*p) * 80u;
        *(uint2*)(sm + ao)         = make_uint2(ra[p].x, ra[p].y);
        *(uint2*)(sm + 10240 + ao) = make_uint2(ra[p].z, ra[p].w);
        uint32_t bo = boff_t + (uint32_t)(8*p) * 272u;
        *(uint2*)(sm + BOFF + bo)       = make_uint2(rb[p].x, rb[p].y);
        *(uint2*)(sm + BOFF + BHI + bo) = make_uint2(rb[p].z, rb[p].w);
    }
    __syncthreads();

    for (int kc = 0; kc < NC; kc++) {
        if (kc + 1 < NC) {
            const int kg = (kc + 1) * 8;
            #pragma unroll
            for (int p = 0; p < 4; p++) {
                ra[p] = pa[(size_t)(32*p) * K4 + kg];
                rb[p] = pb[((size_t)(8*p) + (size_t)(kc+1)*32) * N4];
            }
        }

        const uint32_t cb = sbase + (uint32_t)(kc & 1) * BUFSZ;
        #pragma unroll
        for (int ks = 0; ks < 2; ks++) {
            uint32_t ah[2][4], al[2][4], bh[8][2], bl[8][2];
            #pragma unroll
            for (int mt = 0; mt < 2; mt++) {
                uint32_t addr = cb + (uint32_t)(wm*32 + mt*16 + (lane & 15)) * 80u
                              + (uint32_t)(ks*32) + ((lane >> 4) << 4);
                ldsm_x4(ah[mt][0], ah[mt][1], ah[mt][2], ah[mt][3], addr);
                ldsm_x4(al[mt][0], al[mt][1], al[mt][2], al[mt][3], addr + 10240);
            }
            #pragma unroll
            for (int ntp = 0; ntp < 4; ntp++) {
                uint32_t r0, r1, r2, r3;
                uint32_t addr = cb + BOFF
                              + (uint32_t)(ks*16 + (lane & 15)) * 272u
                              + (uint32_t)(wn*64 + ntp*16) * 2u + ((lane >> 4) << 4);
                ldsm_x4_t(r0, r1, r2, r3, addr);
                bh[2*ntp][0] = r0; bh[2*ntp][1] = r1;
                bh[2*ntp+1][0] = r2; bh[2*ntp+1][1] = r3;
                ldsm_x4_t(r0, r1, r2, r3, addr + BHI);
                bl[2*ntp][0] = r0; bl[2*ntp][1] = r1;
                bl[2*ntp+1][0] = r2; bl[2*ntp+1][1] = r3;
            }
            #pragma unroll
            for (int mt = 0; mt < 2; mt++)
                #pragma unroll
                for (int nt = 0; nt < 8; nt++) {
                    mma16816(acc[mt][nt], ah[mt], bh[nt]);
                    mma16816(acc[mt][nt], ah[mt], bl[nt]);
                    mma16816(acc[mt][nt], al[mt], bh[nt]);
                }
        }

        if (kc + 1 < NC) {
            unsigned char* nb = sm + (uint32_t)((kc + 1) & 1) * BUFSZ;
            #pragma unroll
            for (int p = 0; p < 4; p++) {
                uint32_t ao = aoff_t + (uint32_t)(32*p) * 80u;
                *(uint2*)(nb + ao)         = make_uint2(ra[p].x, ra[p].y);
                *(uint2*)(nb + 10240 + ao) = make_uint2(ra[p].z, ra[p].w);
                uint32_t bo = boff_t + (uint32_t)(8*p) * 272u;
                *(uint2*)(nb + BOFF + bo)       = make_uint2(rb[p].x, rb[p].y);
                *(uint2*)(nb + BOFF + BHI + bo) = make_uint2(rb[p].z, rb[p].w);
            }
            __syncthreads();
        }
    }

    const int mrow = m0 + wm*32;
    #pragma unroll
    for (int mt = 0; mt < 2; mt++) {
        #pragma unroll
        for (int nt = 0; nt < 8; nt++) {
            int col = n0 + wn*64 + nt*8 + tig*2;
            float b0v = bias[col], b1v = bias[col+1];
            #pragma unroll
            for (int hh = 0; hh < 2; hh++) {
                int row = mrow + mt*16 + grp + hh*8;
                float v0 = acc[mt][nt][2*hh+0] + b0v;
                float v1 = acc[mt][nt][2*hh+1] + b1v;
                float x2 = __shfl_down_sync(0xffffffffu, v0, 1);
                float x3 = __shfl_down_sync(0xffffffffu, v1, 1);
                if ((tig & 1) == 0) {
                    uint2 hi, lo;
                    split4(make_float4(v0, v1, x2, x3), hi, lo);
                    Cs[(size_t)row * 576 + (size_t)(sel*192) + (col >> 2)]
                        = make_uint4(hi.x, hi.y, lo.x, lo.y);
                }
            }
        }
    }
}

// ============ flash attention (split qkv input, split attn output) ============
__global__ void __launch_bounds__(128, 1)
flash_kernel(const uint4* __restrict__ qkvs, const float* __restrict__ amask,
             uint4* __restrict__ outs)
{
    __shared__ __align__(16) unsigned char sm[4*9216 + 256];
    const int KHo = 0, KLo = 9216, VHo = 18432, VLo = 27648, AMo = 36864;
    const uint32_t sbase = smem_u32(sm);
    const int tid = threadIdx.x, lane = tid & 31, w = tid >> 5;
    const int grp = lane >> 2, tig = lane & 3;
    const int qt = (int)gridDim.x - 1 - (int)blockIdx.x;
    const int bh = blockIdx.y, b = bh / HH, h = bh % HH;
    const int q0 = qt * 64;

    uint32_t qh[4][4], ql[4][4];
    #pragma unroll
    for (int ks = 0; ks < 4; ks++)
        #pragma unroll
        for (int j = 0; j < 4; j++) {
            int row = q0 + w*16 + grp + (j & 1) * 8;
            int col = h*64 + ks*16 + (j >> 1) * 8 + tig*2;
            uint4 g = qkvs[(size_t)(b*SS + row) * 576 + (col >> 2)];
            if ((col & 3) == 0) { qh[ks][j] = g.x; ql[ks][j] = g.z; }
            else                { qh[ks][j] = g.y; ql[ks][j] = g.w; }
        }

    float o[8][4];
    #pragma unroll
    for (int i = 0; i < 8; i++)
        #pragma unroll
        for (int j = 0; j < 4; j++) o[i][j] = 0.f;
    float mrow0 = -1e30f, mrow1 = -1e30f, lrow0 = 0.f, lrow1 = 0.f;
    const int qr0 = q0 + w*16 + grp, qr1 = qr0 + 8;

    for (int kt = 0; kt <= qt; kt++) {
        __syncthreads();
        const size_t kgbase = (size_t)(b*SS + kt*64) * 576 + 192 + h*16;
        for (int idx = tid; idx < 64*16; idx += 128) {
            int r = idx >> 4, c4 = idx & 15;
            uint4 kg = qkvs[kgbase + (size_t)r*576 + c4];
            *(uint2*)(sm + KHo + r*144 + c4*8) = make_uint2(kg.x, kg.y);
            *(uint2*)(sm + KLo + r*144 + c4*8) = make_uint2(kg.z, kg.w);
            uint4 vg = qkvs[kgbase + 192 + (size_t)r*576 + c4];
            *(uint2*)(sm + VHo + r*144 + c4*8) = make_uint2(vg.x, vg.y);
            *(uint2*)(sm + VLo + r*144 + c4*8) = make_uint2(vg.z, vg.w);
        }
        if (tid < 64) ((float*)(sm + AMo))[tid] = amask[b*SS + kt*64 + tid];
        __syncthreads();

        float s[8][4];
        #pragma unroll
        for (int i = 0; i < 8; i++)
            #pragma unroll
            for (int j = 0; j < 4; j++) s[i][j] = 0.f;
        #pragma unroll
        for (int ks = 0; ks < 4; ks++) {
            uint32_t kh_[8][2], kl_[8][2];
            #pragma unroll
            for (int ntp = 0; ntp < 4; ntp++) {
                uint32_t r0, r1, r2, r3;
                uint32_t addr = sbase + KHo + (uint32_t)(ntp*16 + (lane & 15)) * 144u
                              + (uint32_t)(ks*32) + ((lane >> 4) << 4);
                ldsm_x4(r0, r1, r2, r3, addr);
                kh_[2*ntp][0] = r0; kh_[2*ntp][1] = r2;
                kh_[2*ntp+1][0] = r1; kh_[2*ntp+1][1] = r3;
                ldsm_x4(r0, r1, r2, r3, addr + (KLo - KHo));
                kl_[2*ntp][0] = r0; kl_[2*ntp][1] = r2;
                kl_[2*ntp+1][0] = r1; kl_[2*ntp+1][1] = r3;
            }
            #pragma unroll
            for (int nt = 0; nt < 8; nt++) {
                mma16816(s[nt], qh[ks], kh_[nt]);
                mma16816(s[nt], qh[ks], kl_[nt]);
                mma16816(s[nt], ql[ks], kh_[nt]);
            }
        }
        const float* am = (const float*)(sm + AMo);
        #pragma unroll
        for (int nt = 0; nt < 8; nt++) {
            int c0 = nt*8 + tig*2;
            int kc0 = kt*64 + c0, kc1 = kc0 + 1;
            float a0 = am[c0], a1 = am[c0+1];
            s[nt][0] = (kc0 <= qr0 && a0 != 0.f) ? s[nt][0]*0.125f : -1e30f;
            s[nt][1] = (kc1 <= qr0 && a1 != 0.f) ? s[nt][1]*0.125f : -1e30f;
            s[nt][2] = (kc0 <= qr1 && a0 != 0.f) ? s[nt][2]*0.125f : -1e30f;
            s[nt][3] = (kc1 <= qr1 && a1 != 0.f) ? s[nt][3]*0.125f : -1e30f;
        }
        float mx0 = -1e30f, mx1 = -1e30f;
        #pragma unroll
        for (int nt = 0; nt < 8; nt++) {
            mx0 = fmaxf(mx0, fmaxf(s[nt][0], s[nt][1]));
            mx1 = fmaxf(mx1, fmaxf(s[nt][2], s[nt][3]));
        }
        mx0 = fmaxf(mx0, __shfl_xor_sync(0xffffffffu, mx0, 1));
        mx0 = fmaxf(mx0, __shfl_xor_sync(0xffffffffu, mx0, 2));
        mx1 = fmaxf(mx1, __shfl_xor_sync(0xffffffffu, mx1, 1));
        mx1 = fmaxf(mx1, __shfl_xor_sync(0xffffffffu, mx1, 2));
        float mn0 = fmaxf(mrow0, mx0), mn1 = fmaxf(mrow1, mx1);
        float sc0 = __expf(mrow0 - mn0), sc1 = __expf(mrow1 - mn1);
        mrow0 = mn0; mrow1 = mn1;
        float rs0 = 0.f, rs1 = 0.f;
        #pragma unroll
        for (int nt = 0; nt < 8; nt++) {
            s[nt][0] = __expf(s[nt][0] - mn0); rs0 += s[nt][0];
            s[nt][1] = __expf(s[nt][1] - mn0); rs0 += s[nt][1];
            s[nt][2] = __expf(s[nt][2] - mn1); rs1 += s[nt][2];
            s[nt][3] = __expf(s[nt][3] - mn1); rs1 += s[nt][3];
        }
        rs0 += __shfl_xor_sync(0xffffffffu, rs0, 1);
        rs0 += __shfl_xor_sync(0xffffffffu, rs0, 2);
        rs1 += __shfl_xor_sync(0xffffffffu, rs1, 1);
        rs1 += __shfl_xor_sync(0xffffffffu, rs1, 2);
        lrow0 = lrow0*sc0 + rs0; lrow1 = lrow1*sc1 + rs1;
        #pragma unroll
        for (int nt = 0; nt < 8; nt++) {
            o[nt][0] *= sc0; o[nt][1] *= sc0;
            o[nt][2] *= sc1; o[nt][3] *= sc1;
        }
        #pragma unroll
        for (int ks = 0; ks < 4; ks++) {
            uint32_t pah[4], pal[4];
            split2(s[2*ks][0],   s[2*ks][1],   pah[0], pal[0]);
            split2(s[2*ks][2],   s[2*ks][3],   pah[1], pal[1]);
            split2(s[2*ks+1][0], s[2*ks+1][1], pah[2], pal[2]);
            split2(s[2*ks+1][2], s[2*ks+1][3], pah[3], pal[3]);
            uint32_t vh_[8][2], vl_[8][2];
            #pragma unroll
            for (int ntp = 0; ntp < 4; ntp++) {
                uint32_t r0, r1, r2, r3;
                uint32_t addr = sbase + VHo + (uint32_t)(ks*16 + (lane & 15)) * 144u
                              + (uint32_t)(ntp*32) + ((lane >> 4) << 4);
                ldsm_x4_t(r0, r1, r2, r3, addr);
                vh_[2*ntp][0] = r0; vh_[2*ntp][1] = r1;
                vh_[2*ntp+1][0] = r2; vh_[2*ntp+1][1] = r3;
                ldsm_x4_t(r0, r1, r2, r3, addr + (VLo - VHo));
                vl_[2*ntp][0] = r0; vl_[2*ntp][1] = r1;
                vl_[2*ntp+1][0] = r2; vl_[2*ntp+1][1] = r3;
            }
            #pragma unroll
            for (int nt = 0; nt < 8; nt++) {
                mma16816(o[nt], pah, vh_[nt]);
                mma16816(o[nt], pah, vl_[nt]);
                mma16816(o[nt], pal, vh_[nt]);
            }
        }
    }
    float inv0 = 1.f / lrow0, inv1 = 1.f / lrow1;
    #pragma unroll
    for (int nt = 0; nt < 8; nt++) {
        int col = h*64 + nt*8 + tig*2;
        float v0 = o[nt][0]*inv0, v1 = o[nt][1]*inv0;
        float u0 = o[nt][2]*inv1, u1 = o[nt][3]*inv1;
        float x2 = __shfl_down_sync(0xffffffffu, v0, 1);
        float x3 = __shfl_down_sync(0xffffffffu, v1, 1);
        float y2 = __shfl_down_sync(0xffffffffu, u0, 1);
        float y3 = __shfl_down_sync(0xffffffffu, u1, 1);
        if ((tig & 1) == 0) {
            uint2 hi, lo;
            split4(make_float4(v0, v1, x2, x3), hi, lo);
            outs[(size_t)(b*SS + qr0) * 192 + (col >> 2)] = make_uint4(hi.x, hi.y, lo.x, lo.y);
            split4(make_float4(u0, u1, y2, y3), hi, lo);
            outs[(size_t)(b*SS + qr1) * 192 + (col >> 2)] = make_uint4(hi.x, hi.y, lo.x, lo.y);
        }
    }
}

// ---------------- position ids ----------------
__global__ void posids_kernel(const float* __restrict__ amask, int* __restrict__ pos) {
    int b = blockIdx.x;
    if (threadIdx.x == 0) {
        float c = 0.f;
        for (int s = 0; s < SS; s++) {
            float m = amask[b*SS + s];
            c += m;
            pos[b*SS + s] = (m == 0.f) ? 0 : (int)(c - 1.f);
        }
    }
}

// ---------------- embedding ----------------
__global__ void embed_kernel(const int* __restrict__ ids, const int* __restrict__ pos,
                             const float* __restrict__ tok, const float* __restrict__ pemb,
                             float* __restrict__ x) {
    int row = blockIdx.x;
    int id = ids[row];
    int p  = pos[row];
    int tid = threadIdx.x;
    #pragma unroll
    for (int t = 0; t < 3; t++) {
        int d = tid + t*256;
        x[(size_t)row*DD + d] = tok[(size_t)id*DD + d] + pemb[(size_t)p*DD + d];
    }
}

// ---------------- layernorm -> split output (192 threads) ----------------
__global__ void ln_split_kernel(const float* __restrict__ x, const float* __restrict__ g,
                                const float* __restrict__ b, uint4* __restrict__ ys) {
    __shared__ float pr[6];
    int row = blockIdx.x, tid = threadIdx.x;   // 192 threads
    float4 v = ((const float4*)(x + (size_t)row*DD))[tid];
    float s = v.x + v.y + v.z + v.w;
    #pragma unroll
    for (int o = 16; o; o >>= 1) s += __shfl_xor_sync(0xffffffffu, s, o);
    if ((tid & 31) == 0) pr[tid >> 5] = s;
    __syncthreads();
    float mu = (pr[0]+pr[1]+pr[2]+pr[3]+pr[4]+pr[5]) * (1.f/DD);
    float dx = v.x-mu, dy = v.y-mu, dz = v.z-mu, dw = v.w-mu;
    float s2 = dx*dx + dy*dy + dz*dz + dw*dw;
    #pragma unroll
    for (int o = 16; o; o >>= 1) s2 += __shfl_xor_sync(0xffffffffu, s2, o);
    __syncthreads();
    if ((tid & 31) == 0) pr[tid >> 5] = s2;
    __syncthreads();
    float rstd = rsqrtf((pr[0]+pr[1]+pr[2]+pr[3]+pr[4]+pr[5]) * (1.f/DD) + 1e-5f);
    float4 gg = ((const float4*)g)[tid], bb = ((const float4*)b)[tid];
    float4 y = make_float4(dx*rstd*gg.x + bb.x, dy*rstd*gg.y + bb.y,
                           dz*rstd*gg.z + bb.z, dw*rstd*gg.w + bb.w);
    uint2 hi, lo; split4(y, hi, lo);
    ys[(size_t)row*192 + tid] = make_uint4(hi.x, hi.y, lo.x, lo.y);
}

// ---------------- launch ----------------
extern "C" void kernel_launch(void* const* d_in, const int* in_sizes, int n_in,
                              void* d_out, int out_size) {
    const int*   ids   = (const int*)  d_in[0];
    const float* amask = (const float*)d_in[1];
    const float* tok   = (const float*)d_in[2];
    const float* pemb  = (const float*)d_in[3];
    const float* ln1g  = (const float*)d_in[4];
    const float* ln1b  = (const float*)d_in[5];
    const float* Wq    = (const float*)d_in[6];
    const float* bq    = (const float*)d_in[7];
    const float* Wk    = (const float*)d_in[8];
    const float* bk    = (const float*)d_in[9];
    const float* Wv    = (const float*)d_in[10];
    const float* bv    = (const float*)d_in[11];
    const float* Wp    = (const float*)d_in[12];
    const float* bp    = (const float*)d_in[13];
    const float* ln2g  = (const float*)d_in[14];
    const float* ln2b  = (const float*)d_in[15];
    const float* W1    = (const float*)d_in[16];
    const float* b1    = (const float*)d_in[17];
    const float* W2    = (const float*)d_in[18];
    const float* b2    = (const float*)d_in[19];
    const float* lnfg  = (const float*)d_in[20];
    const float* lnfb  = (const float*)d_in[21];
    float* out = (float*)d_out;

    float *xp, *partp; int* pidp;
    uint4 *hs, *qkvs, *as, *fs, *wqs, *wks, *wvs, *wps, *w1s, *w2s, *toks;
    cudaGetSymbolAddress((void**)&xp,   g_x);
    cudaGetSymbolAddress((void**)&partp, g_mlp2p);
    cudaGetSymbolAddress((void**)&pidp, g_pos);
    cudaGetSymbolAddress((void**)&hs,   g_h_s);
    cudaGetSymbolAddress((void**)&qkvs, g_qkv_s);
    cudaGetSymbolAddress((void**)&as,   g_attn_s);
    cudaGetSymbolAddress((void**)&fs,   g_ff_s);
    cudaGetSymbolAddress((void**)&wqs,  g_wq_s);
    cudaGetSymbolAddress((void**)&wks,  g_wk_s);
    cudaGetSymbolAddress((void**)&wvs,  g_wv_s);
    cudaGetSymbolAddress((void**)&wps,  g_wp_s);
    cudaGetSymbolAddress((void**)&w1s,  g_w1_s);
    cudaGetSymbolAddress((void**)&w2s,  g_w2_s);
    cudaGetSymbolAddress((void**)&toks, g_tok_s);

    const int SM_T0 = 2*(20480 + 2*8704);   // 75776
    const int SM_T1 = 2*(20480 + 2*10240);  // 81920
    cudaFuncSetAttribute(mma_gemm<0,0>, cudaFuncAttributeMaxDynamicSharedMemorySize, SM_T0);
    cudaFuncSetAttribute(mma_gemm<0,1>, cudaFuncAttributeMaxDynamicSharedMemorySize, SM_T0);
    cudaFuncSetAttribute(mma_gemm<1,0>, cudaFuncAttributeMaxDynamicSharedMemorySize, SM_T1);
    cudaFuncSetAttribute(qkv_gemm, cudaFuncAttributeMaxDynamicSharedMemorySize, SM_T0);

    const int SG = 1184;
    split_kernel<<<SG, 256>>>((const float4*)Wq, wqs, LL*DD*DD/4);
    split_kernel<<<SG, 256>>>((const float4*)Wk, wks, LL*DD*DD/4);
    split_kernel<<<SG, 256>>>((const float4*)Wv, wvs, LL*DD*DD/4);
    split_kernel<<<SG, 256>>>((const float4*)Wp, wps, LL*DD*DD/4);
    split_kernel<<<SG, 256>>>((const float4*)W1, w1s, LL*DD*FF/4);
    split_kernel<<<SG, 256>>>((const float4*)W2, w2s, LL*DD*FF/4);
    split_kernel<<<SG, 256>>>((const float4*)tok, toks, VV*DD/4);

    posids_kernel<<<BB, 32>>>(amask, pidp);
    embed_kernel<<<MM, 256>>>(ids, pidp, tok, pemb, xp);

    dim3 gQKV(18, MM/128);             // 18 x 16
    dim3 gF(FF/128, MM/128);           // 24 x 16
    dim3 gP(DD/128, MM/128, 3);        // 6 x 16 x 3  (proj split-K)
    dim3 gM2(DD/128, MM/128, 3);       // 6 x 16 x 3  (mlp2 split-K)
    dim3 gV(MM/128, (VV+127)/128);     // 16 x 393 (m fastest)
    dim3 gFA(SS/64, BB*HH);

    for (int l = 0; l < LL; l++) {
        const uint4* wql = wqs + (size_t)l*(DD*DD/4);
        const uint4* wkl = wks + (size_t)l*(DD*DD/4);
        const uint4* wvl = wvs + (size_t)l*(DD*DD/4);
        const uint4* wpl = wps + (size_t)l*(DD*DD/4);
        const uint4* w1l = w1s + (size_t)l*(DD*FF/4);
        const uint4* w2l = w2s + (size_t)l*(DD*FF/4);

        ln_split_kernel<<<MM, 192>>>(xp, ln1g + l*DD, ln1b + l*DD, hs);
        qkv_gemm<<<gQKV, 256, SM_T0>>>(hs, wql, wkl, wvl, bq + l*DD, bk + l*DD, bv + l*DD, qkvs);
        flash_kernel<<<gFA, 128>>>(qkvs, amask, as);
        // proj split-K=3: partials, then reduce (+bias +residual into x)
        mma_gemm<0,0><<<gP, 256, SM_T0>>>(as, wpl, nullptr, nullptr, partp, nullptr,
                                          MM, DD, DD/3, 0, DD/4);
        reduce3_kernel<<<1536, 256>>>((const float4*)partp, bp + l*DD, (float4*)xp);
        ln_split_kernel<<<MM, 192>>>(xp, ln2g + l*DD, ln2b + l*DD, hs);
        mma_gemm<0,1><<<gF, 256, SM_T0>>>(hs, w1l, b1 + l*FF, nullptr, nullptr, fs,
                                          MM, FF, DD, 1, DD/4);
        // MLP2 split-K=3
        mma_gemm<0,0><<<gM2, 256, SM_T0>>>(fs, w2l, nullptr, nullptr, partp, nullptr,
                                           MM, DD, FF/3, 0, FF/4);
        reduce3_kernel<<<1536, 256>>>((const float4*)partp, b2 + l*DD, (float4*)xp);
    }

    ln_split_kernel<<<MM, 192>>>(xp, lnfg, lnfb, hs);
    mma_gemm<1,0><<<gV, 256, SM_T1>>>(hs, toks, nullptr, nullptr, out, nullptr,
                                      MM, VV, DD, 0, DD/4);
}

// round 13
// speedup vs baseline: 1.5913x; 1.0091x over previous
#include <cuda_runtime.h>
#include <cuda_bf16.h>
#include <math.h>
#include <stdint.h>

#define BB 2
#define SS 1024
#define DD 768
#define HH 12
#define HDD 64
#define LL 12
#define VV 50257
#define FF 3072
#define MM (BB*SS)   // 2048

// ---------------- scratch (allocation-free) ----------------
// split format: uint4 group = {hi01, hi23, lo01, lo23} for 4 consecutive elems.
__device__ float g_x[MM*DD];
__device__ int   g_pos[BB*SS];
__device__ uint4 g_h_s[MM*DD/4];
__device__ uint4 g_qkv_s[MM*3*DD/4];
__device__ uint4 g_attn_s[MM*DD/4];
__device__ uint4 g_ff_s[MM*FF/4];
__device__ float g_mlp2p[3*MM*DD];     // split-K partials (MLP2 / proj)
__device__ uint4 g_wq_s[LL*DD*DD/4];
__device__ uint4 g_wk_s[LL*DD*DD/4];
__device__ uint4 g_wv_s[LL*DD*DD/4];
__device__ uint4 g_wp_s[LL*DD*DD/4];
__device__ uint4 g_w1_s[LL*DD*FF/4];
__device__ uint4 g_w2_s[LL*DD*FF/4];
__device__ uint4 g_tok_s[(size_t)VV*DD/4];

// ================= helpers =================
__device__ __forceinline__ uint32_t smem_u32(const void* p) {
    uint32_t a;
    asm("{ .reg .u64 t; cvta.to.shared.u64 t, %1; cvt.u32.u64 %0, t; }" : "=r"(a) : "l"(p));
    return a;
}
__device__ __forceinline__ void ldsm_x4(uint32_t& r0, uint32_t& r1, uint32_t& r2, uint32_t& r3,
                                        uint32_t addr) {
    asm volatile("ldmatrix.sync.aligned.m8n8.x4.shared.b16 {%0,%1,%2,%3}, [%4];"
                 : "=r"(r0), "=r"(r1), "=r"(r2), "=r"(r3) : "r"(addr));
}
__device__ __forceinline__ void ldsm_x4_t(uint32_t& r0, uint32_t& r1, uint32_t& r2, uint32_t& r3,
                                          uint32_t addr) {
    asm volatile("ldmatrix.sync.aligned.m8n8.x4.trans.shared.b16 {%0,%1,%2,%3}, [%4];"
                 : "=r"(r0), "=r"(r1), "=r"(r2), "=r"(r3) : "r"(addr));
}
__device__ __forceinline__ void mma16816(float* c, const uint32_t* a, const uint32_t* b) {
    asm volatile("mma.sync.aligned.m16n8k16.row.col.f32.bf16.bf16.f32 "
                 "{%0,%1,%2,%3}, {%4,%5,%6,%7}, {%8,%9}, {%0,%1,%2,%3};"
                 : "+f"(c[0]), "+f"(c[1]), "+f"(c[2]), "+f"(c[3])
                 : "r"(a[0]), "r"(a[1]), "r"(a[2]), "r"(a[3]), "r"(b[0]), "r"(b[1]));
}
__device__ __forceinline__ void split4(float4 v, uint2& hi, uint2& lo) {
    __nv_bfloat16 h0 = __float2bfloat16(v.x), h1 = __float2bfloat16(v.y);
    __nv_bfloat16 h2 = __float2bfloat16(v.z), h3 = __float2bfloat16(v.w);
    __nv_bfloat16 l0 = __float2bfloat16(v.x - __bfloat162float(h0));
    __nv_bfloat16 l1 = __float2bfloat16(v.y - __bfloat162float(h1));
    __nv_bfloat16 l2 = __float2bfloat16(v.z - __bfloat162float(h2));
    __nv_bfloat16 l3 = __float2bfloat16(v.w - __bfloat162float(h3));
    __nv_bfloat162 a = __nv_bfloat162(h0, h1), b = __nv_bfloat162(h2, h3);
    __nv_bfloat162 c = __nv_bfloat162(l0, l1), d = __nv_bfloat162(l2, l3);
    hi.x = *(uint32_t*)&a; hi.y = *(uint32_t*)&b;
    lo.x = *(uint32_t*)&c; lo.y = *(uint32_t*)&d;
}
__device__ __forceinline__ void split2(float a, float b, uint32_t& hi, uint32_t& lo) {
    __nv_bfloat16 h0 = __float2bfloat16(a), h1 = __float2bfloat16(b);
    __nv_bfloat16 l0 = __float2bfloat16(a - __bfloat162float(h0));
    __nv_bfloat16 l1 = __float2bfloat16(b - __bfloat162float(h1));
    __nv_bfloat162 H(h0, h1), L(l0, l1);
    hi = *(uint32_t*)&H; lo = *(uint32_t*)&L;
}
__device__ __forceinline__ float gelu_exact(float v) {
    return 0.5f * v * (1.0f + erff(v * 0.70710678118654752f));
}

// ---------------- fp32 -> split converter (grid-stride) ----------------
__global__ void split_kernel(const float4* __restrict__ src, uint4* __restrict__ dst, int n) {
    for (int i = blockIdx.x*blockDim.x + threadIdx.x; i < n; i += gridDim.x*blockDim.x) {
        uint2 hi, lo;
        split4(src[i], hi, lo);
        dst[i] = make_uint4(hi.x, hi.y, lo.x, lo.y);
    }
}

// ---------------- fused split-K reduce + layernorm + split ----------------
// x += p0+p1+p2 + bias; then ys = split(LN(x, g, b)). One block per row.
__global__ void reduce_ln_kernel(const float4* __restrict__ part, const float* __restrict__ bias,
                                 float4* __restrict__ x, const float* __restrict__ g,
                                 const float* __restrict__ b, uint4* __restrict__ ys) {
    __shared__ float pr[6];
    const int S = MM*DD/4;
    int row = blockIdx.x, tid = threadIdx.x;   // 192 threads
    int i = row*192 + tid;
    float4 p0 = part[i], p1 = part[i + S], p2 = part[i + 2*S];
    float4 bb4 = ((const float4*)bias)[tid];
    float4 v = x[i];
    v.x += p0.x + p1.x + p2.x + bb4.x;
    v.y += p0.y + p1.y + p2.y + bb4.y;
    v.z += p0.z + p1.z + p2.z + bb4.z;
    v.w += p0.w + p1.w + p2.w + bb4.w;
    x[i] = v;

    float s = v.x + v.y + v.z + v.w;
    #pragma unroll
    for (int o = 16; o; o >>= 1) s += __shfl_xor_sync(0xffffffffu, s, o);
    if ((tid & 31) == 0) pr[tid >> 5] = s;
    __syncthreads();
    float mu = (pr[0]+pr[1]+pr[2]+pr[3]+pr[4]+pr[5]) * (1.f/DD);
    float dx = v.x-mu, dy = v.y-mu, dz = v.z-mu, dw = v.w-mu;
    float s2 = dx*dx + dy*dy + dz*dz + dw*dw;
    #pragma unroll
    for (int o = 16; o; o >>= 1) s2 += __shfl_xor_sync(0xffffffffu, s2, o);
    __syncthreads();
    if ((tid & 31) == 0) pr[tid >> 5] = s2;
    __syncthreads();
    float rstd = rsqrtf((pr[0]+pr[1]+pr[2]+pr[3]+pr[4]+pr[5]) * (1.f/DD) + 1e-5f);
    float4 gg = ((const float4*)g)[tid], bb = ((const float4*)b)[tid];
    float4 y = make_float4(dx*rstd*gg.x + bb.x, dy*rstd*gg.y + bb.y,
                           dz*rstd*gg.z + bb.z, dw*rstd*gg.w + bb.w);
    uint2 hi, lo; split4(y, hi, lo);
    ys[i] = make_uint4(hi.x, hi.y, lo.x, lo.y);
}

// ============ split-bf16 GEMM, pre-split inputs, double-buffered smem ============
// lda4: A row stride in uint4 (K-major stride for A, and B when TRANSB=1).
// blockIdx.z = split-K slice: A/B advance by z*K along K; C advances by z*M*N.
template<int TRANSB, int OUTSPLIT>
__global__ void __launch_bounds__(256, 1)
mma_gemm(const uint4* __restrict__ As, const uint4* __restrict__ Bs,
         const float* __restrict__ bias, const float* __restrict__ res,
         float* __restrict__ C, uint4* __restrict__ Cs,
         int M, int N, int K, int act, int lda4)
{
    extern __shared__ __align__(16) unsigned char sm[];
    constexpr int BHI   = TRANSB ? 10240 : 8704;
    constexpr int BOFF  = 20480;                 // A hi+lo
    constexpr int BUFSZ = BOFF + 2*BHI;
    const uint32_t sbase = smem_u32(sm);
    const int tid = threadIdx.x, lane = tid & 31, wid = tid >> 5;
    const int wm = wid & 3, wn = wid >> 2;
    const int m0 = (TRANSB ? blockIdx.x : blockIdx.y) << 7;
    const int n0 = (TRANSB ? blockIdx.y : blockIdx.x) << 7;
    const int grp = lane >> 2, tig = lane & 3;
    const int N4 = N >> 2;

    // split-K slice offsets
    const int z = blockIdx.z;
    As += (size_t)z * (K >> 2);
    if (TRANSB) Bs += (size_t)z * (K >> 2);
    else        Bs += (size_t)z * K * N4;
    C  += (size_t)z * M * N;

    float acc[2][8][4];
    #pragma unroll
    for (int i = 0; i < 2; i++)
        #pragma unroll
        for (int j = 0; j < 8; j++)
            #pragma unroll
            for (int q = 0; q < 4; q++) acc[i][j][q] = 0.f;

    const int arow = tid >> 3, ak4 = tid & 7;
    const uint4* pa = As + (size_t)(m0 + arow) * lda4 + ak4;

    const uint4* pb;
    bool bpred[4];
    if (TRANSB) {
        #pragma unroll
        for (int p = 0; p < 4; p++) bpred[p] = (n0 + arow + 32*p) < N;
        pb = Bs + (size_t)(n0 + arow) * lda4 + ak4;
    } else {
        #pragma unroll
        for (int p = 0; p < 4; p++) bpred[p] = true;
        pb = Bs + (size_t)(tid >> 5) * N4 + (n0 >> 2) + (tid & 31);
    }

    const int NC = K >> 5;
    uint4 ra[4], rb[4];
    const uint4 z4 = make_uint4(0u, 0u, 0u, 0u);

    const uint32_t aoff_t = (uint32_t)arow * 80u + (uint32_t)ak4 * 8u;
    uint32_t boff_t;
    if (TRANSB) boff_t = aoff_t;
    else        boff_t = (uint32_t)(tid >> 5) * 272u + (uint32_t)(tid & 31) * 8u;

    // ---- load chunk 0 + store buffer 0 ----
    #pragma unroll
    for (int p = 0; p < 4; p++) {
        ra[p] = pa[(size_t)(32*p) * lda4];
        if (TRANSB) rb[p] = bpred[p] ? pb[(size_t)(32*p) * lda4] : z4;
        else        rb[p] = pb[(size_t)(8*p) * N4];
    }
    #pragma unroll
    for (int p = 0; p < 4; p++) {
        uint32_t ao = aoff_t + (uint32_t)(32*p) * 80u;
        *(uint2*)(sm + ao)         = make_uint2(ra[p].x, ra[p].y);
        *(uint2*)(sm + 10240 + ao) = make_uint2(ra[p].z, ra[p].w);
        uint32_t bo = TRANSB ? (boff_t + (uint32_t)(32*p) * 80u)
                             : (boff_t + (uint32_t)(8*p) * 272u);
        *(uint2*)(sm + BOFF + bo)       = make_uint2(rb[p].x, rb[p].y);
        *(uint2*)(sm + BOFF + BHI + bo) = make_uint2(rb[p].z, rb[p].w);
    }
    __syncthreads();

    for (int kc = 0; kc < NC; kc++) {
        if (kc + 1 < NC) {
            const int kg = (kc + 1) * 8;
            #pragma unroll
            for (int p = 0; p < 4; p++) {
                ra[p] = pa[(size_t)(32*p) * lda4 + kg];
                if (TRANSB) rb[p] = bpred[p] ? pb[(size_t)(32*p) * lda4 + kg] : z4;
                else        rb[p] = pb[((size_t)(8*p) + (size_t)(kc+1)*32) * N4];
            }
        }

        const uint32_t cb = sbase + (uint32_t)(kc & 1) * BUFSZ;
        #pragma unroll
        for (int ks = 0; ks < 2; ks++) {
            uint32_t ah[2][4], al[2][4], bh[8][2], bl[8][2];
            #pragma unroll
            for (int mt = 0; mt < 2; mt++) {
                uint32_t addr = cb + (uint32_t)(wm*32 + mt*16 + (lane & 15)) * 80u
                              + (uint32_t)(ks*32) + ((lane >> 4) << 4);
                ldsm_x4(ah[mt][0], ah[mt][1], ah[mt][2], ah[mt][3], addr);
                ldsm_x4(al[mt][0], al[mt][1], al[mt][2], al[mt][3], addr + 10240);
            }
            #pragma unroll
            for (int ntp = 0; ntp < 4; ntp++) {
                uint32_t r0, r1, r2, r3;
                if (TRANSB) {
                    uint32_t addr = cb + BOFF
                                  + (uint32_t)(wn*64 + ntp*16 + (lane & 15)) * 80u
                                  + (uint32_t)(ks*32) + ((lane >> 4) << 4);
                    ldsm_x4(r0, r1, r2, r3, addr);
                    bh[2*ntp][0] = r0; bh[2*ntp+1][0] = r1;
                    bh[2*ntp][1] = r2; bh[2*ntp+1][1] = r3;
                    ldsm_x4(r0, r1, r2, r3, addr + BHI);
                    bl[2*ntp][0] = r0; bl[2*ntp+1][0] = r1;
                    bl[2*ntp][1] = r2; bl[2*ntp+1][1] = r3;
                } else {
                    uint32_t addr = cb + BOFF
                                  + (uint32_t)(ks*16 + (lane & 15)) * 272u
                                  + (uint32_t)(wn*64 + ntp*16) * 2u + ((lane >> 4) << 4);
                    ldsm_x4_t(r0, r1, r2, r3, addr);
                    bh[2*ntp][0] = r0; bh[2*ntp][1] = r1;
                    bh[2*ntp+1][0] = r2; bh[2*ntp+1][1] = r3;
                    ldsm_x4_t(r0, r1, r2, r3, addr + BHI);
                    bl[2*ntp][0] = r0; bl[2*ntp][1] = r1;
                    bl[2*ntp+1][0] = r2; bl[2*ntp+1][1] = r3;
                }
            }
            #pragma unroll
            for (int mt = 0; mt < 2; mt++)
                #pragma unroll
                for (int nt = 0; nt < 8; nt++) {
                    mma16816(acc[mt][nt], ah[mt], bh[nt]);
                    mma16816(acc[mt][nt], ah[mt], bl[nt]);
                    mma16816(acc[mt][nt], al[mt], bh[nt]);
                }
        }

        if (kc + 1 < NC) {
            unsigned char* nb = sm + (uint32_t)((kc + 1) & 1) * BUFSZ;
            #pragma unroll
            for (int p = 0; p < 4; p++) {
                uint32_t ao = aoff_t + (uint32_t)(32*p) * 80u;
                *(uint2*)(nb + ao)         = make_uint2(ra[p].x, ra[p].y);
                *(uint2*)(nb + 10240 + ao) = make_uint2(ra[p].z, ra[p].w);
                uint32_t bo = TRANSB ? (boff_t + (uint32_t)(32*p) * 80u)
                                     : (boff_t + (uint32_t)(8*p) * 272u);
                *(uint2*)(nb + BOFF + bo)       = make_uint2(rb[p].x, rb[p].y);
                *(uint2*)(nb + BOFF + BHI + bo) = make_uint2(rb[p].z, rb[p].w);
            }
            __syncthreads();
        }
    }

    const int mrow = m0 + wm*32;
    #pragma unroll
    for (int mt = 0; mt < 2; mt++) {
        #pragma unroll
        for (int nt = 0; nt < 8; nt++) {
            int col = n0 + wn*64 + nt*8 + tig*2;
            bool ok0 = (!TRANSB) || (col < N);
            bool ok1 = (!TRANSB) || (col + 1 < N);
            float b0v = 0.f, b1v = 0.f;
            if (bias) { if (ok0) b0v = bias[col]; if (ok1) b1v = bias[col+1]; }
            #pragma unroll
            for (int hh = 0; hh < 2; hh++) {
                int row = mrow + mt*16 + grp + hh*8;
                float v0 = acc[mt][nt][2*hh+0] + b0v;
                float v1 = acc[mt][nt][2*hh+1] + b1v;
                if (act) { v0 = gelu_exact(v0); v1 = gelu_exact(v1); }
                if (OUTSPLIT) {
                    float x2 = __shfl_down_sync(0xffffffffu, v0, 1);
                    float x3 = __shfl_down_sync(0xffffffffu, v1, 1);
                    if ((tig & 1) == 0) {
                        uint2 hi, lo;
                        split4(make_float4(v0, v1, x2, x3), hi, lo);
                        Cs[(size_t)row * (N >> 2) + (col >> 2)] = make_uint4(hi.x, hi.y, lo.x, lo.y);
                    }
                } else {
                    size_t base = (size_t)row * N + col;
                    if (res) { if (ok0) v0 += res[base]; if (ok1) v1 += res[base+1]; }
                    if (!TRANSB) {
                        float2 o; o.x = v0; o.y = v1;
                        *(float2*)(C + base) = o;
                    } else {
                        if (ok0) C[base] = v0;
                        if (ok1) C[base+1] = v1;
                    }
                }
            }
        }
    }
}

// ============ fused QKV GEMM: split in/out, double-buffered ============
__global__ void __launch_bounds__(256, 1)
qkv_gemm(const uint4* __restrict__ As,
         const uint4* __restrict__ Wqs, const uint4* __restrict__ Wks, const uint4* __restrict__ Wvs,
         const float* __restrict__ bq_, const float* __restrict__ bk_, const float* __restrict__ bv_,
         uint4* __restrict__ Cs)
{
    extern __shared__ __align__(16) unsigned char sm[];
    constexpr int BHI   = 8704;
    constexpr int BOFF  = 20480;
    constexpr int BUFSZ = BOFF + 2*BHI;   // 37888
    const int K4 = DD >> 2, N4 = DD >> 2;
    const uint32_t sbase = smem_u32(sm);
    const int tid = threadIdx.x, lane = tid & 31, wid = tid >> 5;
    const int wm = wid & 3, wn = wid >> 2;
    const int m0 = blockIdx.y << 7;
    const int sel = blockIdx.x / 6;
    const int n0 = (blockIdx.x % 6) << 7;
    const uint4* Bs   = (sel == 0) ? Wqs : (sel == 1) ? Wks : Wvs;
    const float* bias = (sel == 0) ? bq_ : (sel == 1) ? bk_ : bv_;
    const int grp = lane >> 2, tig = lane & 3;

    float acc[2][8][4];
    #pragma unroll
    for (int i = 0; i < 2; i++)
        #pragma unroll
        for (int j = 0; j < 8; j++)
            #pragma unroll
            for (int q = 0; q < 4; q++) acc[i][j][q] = 0.f;

    const int arow = tid >> 3, ak4 = tid & 7;
    const uint4* pa = As + (size_t)(m0 + arow) * K4 + ak4;
    const uint4* pb = Bs + (size_t)(tid >> 5) * N4 + (n0 >> 2) + (tid & 31);

    const int NC = DD >> 5;
    uint4 ra[4], rb[4];
    const uint32_t aoff_t = (uint32_t)arow * 80u + (uint32_t)ak4 * 8u;
    const uint32_t boff_t = (uint32_t)(tid >> 5) * 272u + (uint32_t)(tid & 31) * 8u;

    #pragma unroll
    for (int p = 0; p < 4; p++) {
        ra[p] = pa[(size_t)(32*p) * K4];
        rb[p] = pb[(size_t)(8*p) * N4];
    }
    #pragma unroll
    for (int p = 0; p < 4; p++) {
        uint32_t ao = aoff_t + (uint32_t)(32*p) * 80u;
        *(uint2*)(sm + ao)         = make_uint2(ra[p].x, ra[p].y);
        *(uint2*)(sm + 10240 + ao) = make_uint2(ra[p].z, ra[p].w);
        uint32_t bo = boff_t + (uint32_t)(8*p) * 272u;
        *(uint2*)(sm + BOFF + bo)       = make_uint2(rb[p].x, rb[p].y);
        *(uint2*)(sm + BOFF + BHI + bo) = make_uint2(rb[p].z, rb[p].w);
    }
    __syncthreads();

    for (int kc = 0; kc < NC; kc++) {
        if (kc + 1 < NC) {
            const int kg = (kc + 1) * 8;
            #pragma unroll
            for (int p = 0; p < 4; p++) {
                ra[p] = pa[(size_t)(32*p) * K4 + kg];
                rb[p] = pb[((size_t)(8*p) + (size_t)(kc+1)*32) * N4];
            }
        }

        const uint32_t cb = sbase + (uint32_t)(kc & 1) * BUFSZ;
        #pragma unroll
        for (int ks = 0; ks < 2; ks++) {
            uint32_t ah[2][4], al[2][4], bh[8][2], bl[8][2];
            #pragma unroll
            for (int mt = 0; mt < 2; mt++) {
                uint32_t addr = cb + (uint32_t)(wm*32 + mt*16 + (lane & 15)) * 80u
                              + (uint32_t)(ks*32) + ((lane >> 4) << 4);
                ldsm_x4(ah[mt][0], ah[mt][1], ah[mt][2], ah[mt][3], addr);
                ldsm_x4(al[mt][0], al[mt][1], al[mt][2], al[mt][3], addr + 10240);
            }
            #pragma unroll
            for (int ntp = 0; ntp < 4; ntp++) {
                uint32_t r0, r1, r2, r3;
                uint32_t addr = cb + BOFF
                              + (uint32_t)(ks*16 + (lane & 15)) * 272u
                              + (uint32_t)(wn*64 + ntp*16) * 2u + ((lane >> 4) << 4);
                ldsm_x4_t(r0, r1, r2, r3, addr);
                bh[2*ntp][0] = r0; bh[2*ntp][1] = r1;
                bh[2*ntp+1][0] = r2; bh[2*ntp+1][1] = r3;
                ldsm_x4_t(r0, r1, r2, r3, addr + BHI);
                bl[2*ntp][0] = r0; bl[2*ntp][1] = r1;
                bl[2*ntp+1][0] = r2; bl[2*ntp+1][1] = r3;
            }
            #pragma unroll
            for (int mt = 0; mt < 2; mt++)
                #pragma unroll
                for (int nt = 0; nt < 8; nt++) {
                    mma16816(acc[mt][nt], ah[mt], bh[nt]);
                    mma16816(acc[mt][nt], ah[mt], bl[nt]);
                    mma16816(acc[mt][nt], al[mt], bh[nt]);
                }
        }

        if (kc + 1 < NC) {
            unsigned char* nb = sm + (uint32_t)((kc + 1) & 1) * BUFSZ;
            #pragma unroll
            for (int p = 0; p < 4; p++) {
                uint32_t ao = aoff_t + (uint32_t)(32*p) * 80u;
                *(uint2*)(nb + ao)         = make_uint2(ra[p].x, ra[p].y);
                *(uint2*)(nb + 10240 + ao) = make_uint2(ra[p].z, ra[p].w);
                uint32_t bo = boff_t + (uint32_t)(8*p) * 272u;
                *(uint2*)(nb + BOFF + bo)       = make_uint2(rb[p].x, rb[p].y);
                *(uint2*)(nb + BOFF + BHI + bo) = make_uint2(rb[p].z, rb[p].w);
            }
            __syncthreads();
        }
    }

    const int mrow = m0 + wm*32;
    #pragma unroll
    for (int mt = 0; mt < 2; mt++) {
        #pragma unroll
        for (int nt = 0; nt < 8; nt++) {
            int col = n0 + wn*64 + nt*8 + tig*2;
            float b0v = bias[col], b1v = bias[col+1];
            #pragma unroll
            for (int hh = 0; hh < 2; hh++) {
                int row = mrow + mt*16 + grp + hh*8;
                float v0 = acc[mt][nt][2*hh+0] + b0v;
                float v1 = acc[mt][nt][2*hh+1] + b1v;
                float x2 = __shfl_down_sync(0xffffffffu, v0, 1);
                float x3 = __shfl_down_sync(0xffffffffu, v1, 1);
                if ((tig & 1) == 0) {
                    uint2 hi, lo;
                    split4(make_float4(v0, v1, x2, x3), hi, lo);
                    Cs[(size_t)row * 576 + (size_t)(sel*192) + (col >> 2)]
                        = make_uint4(hi.x, hi.y, lo.x, lo.y);
                }
            }
        }
    }
}

// ============ flash attention (split qkv input, split attn output) ============
__global__ void __launch_bounds__(128, 1)
flash_kernel(const uint4* __restrict__ qkvs, const float* __restrict__ amask,
             uint4* __restrict__ outs)
{
    __shared__ __align__(16) unsigned char sm[4*9216 + 256];
    const int KHo = 0, KLo = 9216, VHo = 18432, VLo = 27648, AMo = 36864;
    const uint32_t sbase = smem_u32(sm);
    const int tid = threadIdx.x, lane = tid & 31, w = tid >> 5;
    const int grp = lane >> 2, tig = lane & 3;
    const int qt = (int)gridDim.x - 1 - (int)blockIdx.x;
    const int bh = blockIdx.y, b = bh / HH, h = bh % HH;
    const int q0 = qt * 64;

    uint32_t qh[4][4], ql[4][4];
    #pragma unroll
    for (int ks = 0; ks < 4; ks++)
        #pragma unroll
        for (int j = 0; j < 4; j++) {
            int row = q0 + w*16 + grp + (j & 1) * 8;
            int col = h*64 + ks*16 + (j >> 1) * 8 + tig*2;
            uint4 g = qkvs[(size_t)(b*SS + row) * 576 + (col >> 2)];
            if ((col & 3) == 0) { qh[ks][j] = g.x; ql[ks][j] = g.z; }
            else                { qh[ks][j] = g.y; ql[ks][j] = g.w; }
        }

    float o[8][4];
    #pragma unroll
    for (int i = 0; i < 8; i++)
        #pragma unroll
        for (int j = 0; j < 4; j++) o[i][j] = 0.f;
    float mrow0 = -1e30f, mrow1 = -1e30f, lrow0 = 0.f, lrow1 = 0.f;
    const int qr0 = q0 + w*16 + grp, qr1 = qr0 + 8;

    for (int kt = 0; kt <= qt; kt++) {
        __syncthreads();
        const size_t kgbase = (size_t)(b*SS + kt*64) * 576 + 192 + h*16;
        for (int idx = tid; idx < 64*16; idx += 128) {
            int r = idx >> 4, c4 = idx & 15;
            uint4 kg = qkvs[kgbase + (size_t)r*576 + c4];
            *(uint2*)(sm + KHo + r*144 + c4*8) = make_uint2(kg.x, kg.y);
            *(uint2*)(sm + KLo + r*144 + c4*8) = make_uint2(kg.z, kg.w);
            uint4 vg = qkvs[kgbase + 192 + (size_t)r*576 + c4];
            *(uint2*)(sm + VHo + r*144 + c4*8) = make_uint2(vg.x, vg.y);
            *(uint2*)(sm + VLo + r*144 + c4*8) = make_uint2(vg.z, vg.w);
        }
        if (tid < 64) ((float*)(sm + AMo))[tid] = amask[b*SS + kt*64 + tid];
        __syncthreads();

        float s[8][4];
        #pragma unroll
        for (int i = 0; i < 8; i++)
            #pragma unroll
            for (int j = 0; j < 4; j++) s[i][j] = 0.f;
        #pragma unroll
        for (int ks = 0; ks < 4; ks++) {
            uint32_t kh_[8][2], kl_[8][2];
            #pragma unroll
            for (int ntp = 0; ntp < 4; ntp++) {
                uint32_t r0, r1, r2, r3;
                uint32_t addr = sbase + KHo + (uint32_t)(ntp*16 + (lane & 15)) * 144u
                              + (uint32_t)(ks*32) + ((lane >> 4) << 4);
                ldsm_x4(r0, r1, r2, r3, addr);
                kh_[2*ntp][0] = r0; kh_[2*ntp][1] = r2;
                kh_[2*ntp+1][0] = r1; kh_[2*ntp+1][1] = r3;
                ldsm_x4(r0, r1, r2, r3, addr + (KLo - KHo));
                kl_[2*ntp][0] = r0; kl_[2*ntp][1] = r2;
                kl_[2*ntp+1][0] = r1; kl_[2*ntp+1][1] = r3;
            }
            #pragma unroll
            for (int nt = 0; nt < 8; nt++) {
                mma16816(s[nt], qh[ks], kh_[nt]);
                mma16816(s[nt], qh[ks], kl_[nt]);
                mma16816(s[nt], ql[ks], kh_[nt]);
            }
        }
        const float* am = (const float*)(sm + AMo);
        #pragma unroll
        for (int nt = 0; nt < 8; nt++) {
            int c0 = nt*8 + tig*2;
            int kc0 = kt*64 + c0, kc1 = kc0 + 1;
            float a0 = am[c0], a1 = am[c0+1];
            s[nt][0] = (kc0 <= qr0 && a0 != 0.f) ? s[nt][0]*0.125f : -1e30f;
            s[nt][1] = (kc1 <= qr0 && a1 != 0.f) ? s[nt][1]*0.125f : -1e30f;
            s[nt][2] = (kc0 <= qr1 && a0 != 0.f) ? s[nt][2]*0.125f : -1e30f;
            s[nt][3] = (kc1 <= qr1 && a1 != 0.f) ? s[nt][3]*0.125f : -1e30f;
        }
        float mx0 = -1e30f, mx1 = -1e30f;
        #pragma unroll
        for (int nt = 0; nt < 8; nt++) {
            mx0 = fmaxf(mx0, fmaxf(s[nt][0], s[nt][1]));
            mx1 = fmaxf(mx1, fmaxf(s[nt][2], s[nt][3]));
        }
        mx0 = fmaxf(mx0, __shfl_xor_sync(0xffffffffu, mx0, 1));
        mx0 = fmaxf(mx0, __shfl_xor_sync(0xffffffffu, mx0, 2));
        mx1 = fmaxf(mx1, __shfl_xor_sync(0xffffffffu, mx1, 1));
        mx1 = fmaxf(mx1, __shfl_xor_sync(0xffffffffu, mx1, 2));
        float mn0 = fmaxf(mrow0, mx0), mn1 = fmaxf(mrow1, mx1);
        float sc0 = __expf(mrow0 - mn0), sc1 = __expf(mrow1 - mn1);
        mrow0 = mn0; mrow1 = mn1;
        float rs0 = 0.f, rs1 = 0.f;
        #pragma unroll
        for (int nt = 0; nt < 8; nt++) {
            s[nt][0] = __expf(s[nt][0] - mn0); rs0 += s[nt][0];
            s[nt][1] = __expf(s[nt][1] - mn0); rs0 += s[nt][1];
            s[nt][2] = __expf(s[nt][2] - mn1); rs1 += s[nt][2];
            s[nt][3] = __expf(s[nt][3] - mn1); rs1 += s[nt][3];
        }
        rs0 += __shfl_xor_sync(0xffffffffu, rs0, 1);
        rs0 += __shfl_xor_sync(0xffffffffu, rs0, 2);
        rs1 += __shfl_xor_sync(0xffffffffu, rs1, 1);
        rs1 += __shfl_xor_sync(0xffffffffu, rs1, 2);
        lrow0 = lrow0*sc0 + rs0; lrow1 = lrow1*sc1 + rs1;
        #pragma unroll
        for (int nt = 0; nt < 8; nt++) {
            o[nt][0] *= sc0; o[nt][1] *= sc0;
            o[nt][2] *= sc1; o[nt][3] *= sc1;
        }
        #pragma unroll
        for (int ks = 0; ks < 4; ks++) {
            uint32_t pah[4], pal[4];
            split2(s[2*ks][0],   s[2*ks][1],   pah[0], pal[0]);
            split2(s[2*ks][2],   s[2*ks][3],   pah[1], pal[1]);
            split2(s[2*ks+1][0], s[2*ks+1][1], pah[2], pal[2]);
            split2(s[2*ks+1][2], s[2*ks+1][3], pah[3], pal[3]);
            uint32_t vh_[8][2], vl_[8][2];
            #pragma unroll
            for (int ntp = 0; ntp < 4; ntp++) {
                uint32_t r0, r1, r2, r3;
                uint32_t addr = sbase + VHo + (uint32_t)(ks*16 + (lane & 15)) * 144u
                              + (uint32_t)(ntp*32) + ((lane >> 4) << 4);
                ldsm_x4_t(r0, r1, r2, r3, addr);
                vh_[2*ntp][0] = r0; vh_[2*ntp][1] = r1;
                vh_[2*ntp+1][0] = r2; vh_[2*ntp+1][1] = r3;
                ldsm_x4_t(r0, r1, r2, r3, addr + (VLo - VHo));
                vl_[2*ntp][0] = r0; vl_[2*ntp][1] = r1;
                vl_[2*ntp+1][0] = r2; vl_[2*ntp+1][1] = r3;
            }
            #pragma unroll
            for (int nt = 0; nt < 8; nt++) {
                mma16816(o[nt], pah, vh_[nt]);
                mma16816(o[nt], pah, vl_[nt]);
                mma16816(o[nt], pal, vh_[nt]);
            }
        }
    }
    float inv0 = 1.f / lrow0, inv1 = 1.f / lrow1;
    #pragma unroll
    for (int nt = 0; nt < 8; nt++) {
        int col = h*64 + nt*8 + tig*2;
        float v0 = o[nt][0]*inv0, v1 = o[nt][1]*inv0;
        float u0 = o[nt][2]*inv1, u1 = o[nt][3]*inv1;
        float x2 = __shfl_down_sync(0xffffffffu, v0, 1);
        float x3 = __shfl_down_sync(0xffffffffu, v1, 1);
        float y2 = __shfl_down_sync(0xffffffffu, u0, 1);
        float y3 = __shfl_down_sync(0xffffffffu, u1, 1);
        if ((tig & 1) == 0) {
            uint2 hi, lo;
            split4(make_float4(v0, v1, x2, x3), hi, lo);
            outs[(size_t)(b*SS + qr0) * 192 + (col >> 2)] = make_uint4(hi.x, hi.y, lo.x, lo.y);
            split4(make_float4(u0, u1, y2, y3), hi, lo);
            outs[(size_t)(b*SS + qr1) * 192 + (col >> 2)] = make_uint4(hi.x, hi.y, lo.x, lo.y);
        }
    }
}

// ---------------- position ids ----------------
__global__ void posids_kernel(const float* __restrict__ amask, int* __restrict__ pos) {
    int b = blockIdx.x;
    if (threadIdx.x == 0) {
        float c = 0.f;
        for (int s = 0; s < SS; s++) {
            float m = amask[b*SS + s];
            c += m;
            pos[b*SS + s] = (m == 0.f) ? 0 : (int)(c - 1.f);
        }
    }
}

// ---------------- embedding ----------------
__global__ void embed_kernel(const int* __restrict__ ids, const int* __restrict__ pos,
                             const float* __restrict__ tok, const float* __restrict__ pemb,
                             float* __restrict__ x) {
    int row = blockIdx.x;
    int id = ids[row];
    int p  = pos[row];
    int tid = threadIdx.x;
    #pragma unroll
    for (int t = 0; t < 3; t++) {
        int d = tid + t*256;
        x[(size_t)row*DD + d] = tok[(size_t)id*DD + d] + pemb[(size_t)p*DD + d];
    }
}

// ---------------- layernorm -> split output (192 threads) ----------------
__global__ void ln_split_kernel(const float* __restrict__ x, const float* __restrict__ g,
                                const float* __restrict__ b, uint4* __restrict__ ys) {
    __shared__ float pr[6];
    int row = blockIdx.x, tid = threadIdx.x;   // 192 threads
    float4 v = ((const float4*)(x + (size_t)row*DD))[tid];
    float s = v.x + v.y + v.z + v.w;
    #pragma unroll
    for (int o = 16; o; o >>= 1) s += __shfl_xor_sync(0xffffffffu, s, o);
    if ((tid & 31) == 0) pr[tid >> 5] = s;
    __syncthreads();
    float mu = (pr[0]+pr[1]+pr[2]+pr[3]+pr[4]+pr[5]) * (1.f/DD);
    float dx = v.x-mu, dy = v.y-mu, dz = v.z-mu, dw = v.w-mu;
    float s2 = dx*dx + dy*dy + dz*dz + dw*dw;
    #pragma unroll
    for (int o = 16; o; o >>= 1) s2 += __shfl_xor_sync(0xffffffffu, s2, o);
    __syncthreads();
    if ((tid & 31) == 0) pr[tid >> 5] = s2;
    __syncthreads();
    float rstd = rsqrtf((pr[0]+pr[1]+pr[2]+pr[3]+pr[4]+pr[5]) * (1.f/DD) + 1e-5f);
    float4 gg = ((const float4*)g)[tid], bb = ((const float4*)b)[tid];
    float4 y = make_float4(dx*rstd*gg.x + bb.x, dy*rstd*gg.y + bb.y,
                           dz*rstd*gg.z + bb.z, dw*rstd*gg.w + bb.w);
    uint2 hi, lo; split4(y, hi, lo);
    ys[(size_t)row*192 + tid] = make_uint4(hi.x, hi.y, lo.x, lo.y);
}

// ---------------- launch ----------------
extern "C" void kernel_launch(void* const* d_in, const int* in_sizes, int n_in,
                              void* d_out, int out_size) {
    const int*   ids   = (const int*)  d_in[0];
    const float* amask = (const float*)d_in[1];
    const float* tok   = (const float*)d_in[2];
    const float* pemb  = (const float*)d_in[3];
    const float* ln1g  = (const float*)d_in[4];
    const float* ln1b  = (const float*)d_in[5];
    const float* Wq    = (const float*)d_in[6];
    const float* bq    = (const float*)d_in[7];
    const float* Wk    = (const float*)d_in[8];
    const float* bk    = (const float*)d_in[9];
    const float* Wv    = (const float*)d_in[10];
    const float* bv    = (const float*)d_in[11];
    const float* Wp    = (const float*)d_in[12];
    const float* bp    = (const float*)d_in[13];
    const float* ln2g  = (const float*)d_in[14];
    const float* ln2b  = (const float*)d_in[15];
    const float* W1    = (const float*)d_in[16];
    const float* b1    = (const float*)d_in[17];
    const float* W2    = (const float*)d_in[18];
    const float* b2    = (const float*)d_in[19];
    const float* lnfg  = (const float*)d_in[20];
    const float* lnfb  = (const float*)d_in[21];
    float* out = (float*)d_out;

    float *xp, *partp; int* pidp;
    uint4 *hs, *qkvs, *as, *fs, *wqs, *wks, *wvs, *wps, *w1s, *w2s, *toks;
    cudaGetSymbolAddress((void**)&xp,   g_x);
    cudaGetSymbolAddress((void**)&partp, g_mlp2p);
    cudaGetSymbolAddress((void**)&pidp, g_pos);
    cudaGetSymbolAddress((void**)&hs,   g_h_s);
    cudaGetSymbolAddress((void**)&qkvs, g_qkv_s);
    cudaGetSymbolAddress((void**)&as,   g_attn_s);
    cudaGetSymbolAddress((void**)&fs,   g_ff_s);
    cudaGetSymbolAddress((void**)&wqs,  g_wq_s);
    cudaGetSymbolAddress((void**)&wks,  g_wk_s);
    cudaGetSymbolAddress((void**)&wvs,  g_wv_s);
    cudaGetSymbolAddress((void**)&wps,  g_wp_s);
    cudaGetSymbolAddress((void**)&w1s,  g_w1_s);
    cudaGetSymbolAddress((void**)&w2s,  g_w2_s);
    cudaGetSymbolAddress((void**)&toks, g_tok_s);

    const int SM_T0 = 2*(20480 + 2*8704);   // 75776
    const int SM_T1 = 2*(20480 + 2*10240);  // 81920
    cudaFuncSetAttribute(mma_gemm<0,0>, cudaFuncAttributeMaxDynamicSharedMemorySize, SM_T0);
    cudaFuncSetAttribute(mma_gemm<0,1>, cudaFuncAttributeMaxDynamicSharedMemorySize, SM_T0);
    cudaFuncSetAttribute(mma_gemm<1,0>, cudaFuncAttributeMaxDynamicSharedMemorySize, SM_T1);
    cudaFuncSetAttribute(qkv_gemm, cudaFuncAttributeMaxDynamicSharedMemorySize, SM_T0);

    const int SG = 1184;
    split_kernel<<<SG, 256>>>((const float4*)Wq, wqs, LL*DD*DD/4);
    split_kernel<<<SG, 256>>>((const float4*)Wk, wks, LL*DD*DD/4);
    split_kernel<<<SG, 256>>>((const float4*)Wv, wvs, LL*DD*DD/4);
    split_kernel<<<SG, 256>>>((const float4*)Wp, wps, LL*DD*DD/4);
    split_kernel<<<SG, 256>>>((const float4*)W1, w1s, LL*DD*FF/4);
    split_kernel<<<SG, 256>>>((const float4*)W2, w2s, LL*DD*FF/4);
    split_kernel<<<SG, 256>>>((const float4*)tok, toks, VV*DD/4);

    posids_kernel<<<BB, 32>>>(amask, pidp);
    embed_kernel<<<MM, 256>>>(ids, pidp, tok, pemb, xp);

    dim3 gQKV(18, MM/128);             // 18 x 16
    dim3 gF(FF/128, MM/128);           // 24 x 16
    dim3 gP(DD/128, MM/128, 3);        // 6 x 16 x 3  (proj split-K)
    dim3 gM2(DD/128, MM/128, 3);       // 6 x 16 x 3  (mlp2 split-K)
    dim3 gV(MM/128, (VV+127)/128);     // 16 x 393 (m fastest)
    dim3 gFA(SS/64, BB*HH);

    // layer-0 ln1 (subsequent ln1/ln2/lnf are fused into the split-K reduces)
    ln_split_kernel<<<MM, 192>>>(xp, ln1g, ln1b, hs);

    for (int l = 0; l < LL; l++) {
        const uint4* wql = wqs + (size_t)l*(DD*DD/4);
        const uint4* wkl = wks + (size_t)l*(DD*DD/4);
        const uint4* wvl = wvs + (size_t)l*(DD*DD/4);
        const uint4* wpl = wps + (size_t)l*(DD*DD/4);
        const uint4* w1l = w1s + (size_t)l*(DD*FF/4);
        const uint4* w2l = w2s + (size_t)l*(DD*FF/4);

        qkv_gemm<<<gQKV, 256, SM_T0>>>(hs, wql, wkl, wvl, bq + l*DD, bk + l*DD, bv + l*DD, qkvs);
        flash_kernel<<<gFA, 128>>>(qkvs, amask, as);
        // proj split-K=3: partials, then fused reduce(+bias+residual) + ln2
        mma_gemm<0,0><<<gP, 256, SM_T0>>>(as, wpl, nullptr, nullptr, partp, nullptr,
                                          MM, DD, DD/3, 0, DD/4);
        reduce_ln_kernel<<<MM, 192>>>((const float4*)partp, bp + l*DD, (float4*)xp,
                                      ln2g + l*DD, ln2b + l*DD, hs);
        mma_gemm<0,1><<<gF, 256, SM_T0>>>(hs, w1l, b1 + l*FF, nullptr, nullptr, fs,
                                          MM, FF, DD, 1, DD/4);
        // MLP2 split-K=3, fused reduce + (next ln1 | lnf)
        mma_gemm<0,0><<<gM2, 256, SM_T0>>>(fs, w2l, nullptr, nullptr, partp, nullptr,
                                           MM, DD, FF/3, 0, FF/4);
        const float* ng = (l + 1 < LL) ? (ln1g + (l+1)*DD) : lnfg;
        const float* nb = (l + 1 < LL) ? (ln1b + (l+1)*DD) : lnfb;
        reduce_ln_kernel<<<MM, 192>>>((const float4*)partp, b2 + l*DD, (float4*)xp,
                                      ng, nb, hs);
    }

    mma_gemm<1,0><<<gV, 256, SM_T1>>>(hs, toks, nullptr, nullptr, out, nullptr,
                                      MM, VV, DD, 0, DD/4);
}

// round 14
// speedup vs baseline: 1.5984x; 1.0045x over previous
#include <cuda_runtime.h>
#include <cuda_bf16.h>
#include <math.h>
#include <stdint.h>

#define BB 2
#define SS 1024
#define DD 768
#define HH 12
#define HDD 64
#define LL 12
#define VV 50257
#define FF 3072
#define MM (BB*SS)   // 2048

// ---------------- scratch (allocation-free) ----------------
// split format: uint4 group = {hi01, hi23, lo01, lo23} for 4 consecutive elems.
__device__ float g_x[MM*DD];
__device__ int   g_pos[BB*SS];
__device__ uint4 g_h_s[MM*DD/4];
__device__ uint4 g_qkv_s[MM*3*DD/4];
__device__ uint4 g_attn_s[MM*DD/4];
__device__ uint4 g_ff_s[MM*FF/4];
__device__ float g_mlp2p[3*MM*DD];     // split-K partials (MLP2 / proj)
__device__ uint4 g_wq_s[LL*DD*DD/4];
__device__ uint4 g_wk_s[LL*DD*DD/4];
__device__ uint4 g_wv_s[LL*DD*DD/4];
__device__ uint4 g_wp_s[LL*DD*DD/4];
__device__ uint4 g_w1_s[LL*DD*FF/4];
__device__ uint4 g_w2_s[LL*DD*FF/4];
__device__ uint4 g_tok_s[(size_t)VV*DD/4];

// ================= helpers =================
__device__ __forceinline__ uint32_t smem_u32(const void* p) {
    uint32_t a;
    asm("{ .reg .u64 t; cvta.to.shared.u64 t, %1; cvt.u32.u64 %0, t; }" : "=r"(a) : "l"(p));
    return a;
}
__device__ __forceinline__ void ldsm_x4(uint32_t& r0, uint32_t& r1, uint32_t& r2, uint32_t& r3,
                                        uint32_t addr) {
    asm volatile("ldmatrix.sync.aligned.m8n8.x4.shared.b16 {%0,%1,%2,%3}, [%4];"
                 : "=r"(r0), "=r"(r1), "=r"(r2), "=r"(r3) : "r"(addr));
}
__device__ __forceinline__ void ldsm_x4_t(uint32_t& r0, uint32_t& r1, uint32_t& r2, uint32_t& r3,
                                          uint32_t addr) {
    asm volatile("ldmatrix.sync.aligned.m8n8.x4.trans.shared.b16 {%0,%1,%2,%3}, [%4];"
                 : "=r"(r0), "=r"(r1), "=r"(r2), "=r"(r3) : "r"(addr));
}
__device__ __forceinline__ void mma16816(float* c, const uint32_t* a, const uint32_t* b) {
    asm volatile("mma.sync.aligned.m16n8k16.row.col.f32.bf16.bf16.f32 "
                 "{%0,%1,%2,%3}, {%4,%5,%6,%7}, {%8,%9}, {%0,%1,%2,%3};"
                 : "+f"(c[0]), "+f"(c[1]), "+f"(c[2]), "+f"(c[3])
                 : "r"(a[0]), "r"(a[1]), "r"(a[2]), "r"(a[3]), "r"(b[0]), "r"(b[1]));
}
__device__ __forceinline__ void split4(float4 v, uint2& hi, uint2& lo) {
    __nv_bfloat16 h0 = __float2bfloat16(v.x), h1 = __float2bfloat16(v.y);
    __nv_bfloat16 h2 = __float2bfloat16(v.z), h3 = __float2bfloat16(v.w);
    __nv_bfloat16 l0 = __float2bfloat16(v.x - __bfloat162float(h0));
    __nv_bfloat16 l1 = __float2bfloat16(v.y - __bfloat162float(h1));
    __nv_bfloat16 l2 = __float2bfloat16(v.z - __bfloat162float(h2));
    __nv_bfloat16 l3 = __float2bfloat16(v.w - __bfloat162float(h3));
    __nv_bfloat162 a = __nv_bfloat162(h0, h1), b = __nv_bfloat162(h2, h3);
    __nv_bfloat162 c = __nv_bfloat162(l0, l1), d = __nv_bfloat162(l2, l3);
    hi.x = *(uint32_t*)&a; hi.y = *(uint32_t*)&b;
    lo.x = *(uint32_t*)&c; lo.y = *(uint32_t*)&d;
}
__device__ __forceinline__ void split2(float a, float b, uint32_t& hi, uint32_t& lo) {
    __nv_bfloat16 h0 = __float2bfloat16(a), h1 = __float2bfloat16(b);
    __nv_bfloat16 l0 = __float2bfloat16(a - __bfloat162float(h0));
    __nv_bfloat16 l1 = __float2bfloat16(b - __bfloat162float(h1));
    __nv_bfloat162 H(h0, h1), L(l0, l1);
    hi = *(uint32_t*)&H; lo = *(uint32_t*)&L;
}
__device__ __forceinline__ float gelu_exact(float v) {
    return 0.5f * v * (1.0f + erff(v * 0.70710678118654752f));
}

// ---------------- fp32 -> split converter (one elem/thread, max MLP) ----------------
__global__ void split_kernel(const float4* __restrict__ src, uint4* __restrict__ dst, int n) {
    int i = blockIdx.x*blockDim.x + threadIdx.x;
    if (i < n) {
        uint2 hi, lo;
        split4(src[i], hi, lo);
        dst[i] = make_uint4(hi.x, hi.y, lo.x, lo.y);
    }
}

// ---------------- fused split-K reduce + layernorm + split ----------------
__global__ void reduce_ln_kernel(const float4* __restrict__ part, const float* __restrict__ bias,
                                 float4* __restrict__ x, const float* __restrict__ g,
                                 const float* __restrict__ b, uint4* __restrict__ ys) {
    __shared__ float pr[6];
    const int S = MM*DD/4;
    int row = blockIdx.x, tid = threadIdx.x;   // 192 threads
    int i = row*192 + tid;
    float4 p0 = part[i], p1 = part[i + S], p2 = part[i + 2*S];
    float4 bb4 = ((const float4*)bias)[tid];
    float4 v = x[i];
    v.x += p0.x + p1.x + p2.x + bb4.x;
    v.y += p0.y + p1.y + p2.y + bb4.y;
    v.z += p0.z + p1.z + p2.z + bb4.z;
    v.w += p0.w + p1.w + p2.w + bb4.w;
    x[i] = v;

    float s = v.x + v.y + v.z + v.w;
    #pragma unroll
    for (int o = 16; o; o >>= 1) s += __shfl_xor_sync(0xffffffffu, s, o);
    if ((tid & 31) == 0) pr[tid >> 5] = s;
    __syncthreads();
    float mu = (pr[0]+pr[1]+pr[2]+pr[3]+pr[4]+pr[5]) * (1.f/DD);
    float dx = v.x-mu, dy = v.y-mu, dz = v.z-mu, dw = v.w-mu;
    float s2 = dx*dx + dy*dy + dz*dz + dw*dw;
    #pragma unroll
    for (int o = 16; o; o >>= 1) s2 += __shfl_xor_sync(0xffffffffu, s2, o);
    __syncthreads();
    if ((tid & 31) == 0) pr[tid >> 5] = s2;
    __syncthreads();
    float rstd = rsqrtf((pr[0]+pr[1]+pr[2]+pr[3]+pr[4]+pr[5]) * (1.f/DD) + 1e-5f);
    float4 gg = ((const float4*)g)[tid], bb = ((const float4*)b)[tid];
    float4 y = make_float4(dx*rstd*gg.x + bb.x, dy*rstd*gg.y + bb.y,
                           dz*rstd*gg.z + bb.z, dw*rstd*gg.w + bb.w);
    uint2 hi, lo; split4(y, hi, lo);
    ys[i] = make_uint4(hi.x, hi.y, lo.x, lo.y);
}

// ============ split-bf16 GEMM, pre-split inputs, double-buffered smem ============
template<int TRANSB, int OUTSPLIT>
__global__ void __launch_bounds__(256, 1)
mma_gemm(const uint4* __restrict__ As, const uint4* __restrict__ Bs,
         const float* __restrict__ bias, const float* __restrict__ res,
         float* __restrict__ C, uint4* __restrict__ Cs,
         int M, int N, int K, int act, int lda4)
{
    extern __shared__ __align__(16) unsigned char sm[];
    constexpr int BHI   = TRANSB ? 10240 : 8704;
    constexpr int BOFF  = 20480;                 // A hi+lo
    constexpr int BUFSZ = BOFF + 2*BHI;
    const uint32_t sbase = smem_u32(sm);
    const int tid = threadIdx.x, lane = tid & 31, wid = tid >> 5;
    const int wm = wid & 3, wn = wid >> 2;
    const int m0 = (TRANSB ? blockIdx.x : blockIdx.y) << 7;
    const int n0 = (TRANSB ? blockIdx.y : blockIdx.x) << 7;
    const int grp = lane >> 2, tig = lane & 3;
    const int N4 = N >> 2;

    const int z = blockIdx.z;
    As += (size_t)z * (K >> 2);
    if (TRANSB) Bs += (size_t)z * (K >> 2);
    else        Bs += (size_t)z * K * N4;
    C  += (size_t)z * M * N;

    float acc[2][8][4];
    #pragma unroll
    for (int i = 0; i < 2; i++)
        #pragma unroll
        for (int j = 0; j < 8; j++)
            #pragma unroll
            for (int q = 0; q < 4; q++) acc[i][j][q] = 0.f;

    const int arow = tid >> 3, ak4 = tid & 7;
    const uint4* pa = As + (size_t)(m0 + arow) * lda4 + ak4;

    const uint4* pb;
    bool bpred[4];
    if (TRANSB) {
        #pragma unroll
        for (int p = 0; p < 4; p++) bpred[p] = (n0 + arow + 32*p) < N;
        pb = Bs + (size_t)(n0 + arow) * lda4 + ak4;
    } else {
        #pragma unroll
        for (int p = 0; p < 4; p++) bpred[p] = true;
        pb = Bs + (size_t)(tid >> 5) * N4 + (n0 >> 2) + (tid & 31);
    }

    const int NC = K >> 5;
    uint4 ra[4], rb[4];
    const uint4 z4 = make_uint4(0u, 0u, 0u, 0u);

    const uint32_t aoff_t = (uint32_t)arow * 80u + (uint32_t)ak4 * 8u;
    uint32_t boff_t;
    if (TRANSB) boff_t = aoff_t;
    else        boff_t = (uint32_t)(tid >> 5) * 272u + (uint32_t)(tid & 31) * 8u;

    #pragma unroll
    for (int p = 0; p < 4; p++) {
        ra[p] = pa[(size_t)(32*p) * lda4];
        if (TRANSB) rb[p] = bpred[p] ? pb[(size_t)(32*p) * lda4] : z4;
        else        rb[p] = pb[(size_t)(8*p) * N4];
    }
    #pragma unroll
    for (int p = 0; p < 4; p++) {
        uint32_t ao = aoff_t + (uint32_t)(32*p) * 80u;
        *(uint2*)(sm + ao)         = make_uint2(ra[p].x, ra[p].y);
        *(uint2*)(sm + 10240 + ao) = make_uint2(ra[p].z, ra[p].w);
        uint32_t bo = TRANSB ? (boff_t + (uint32_t)(32*p) * 80u)
                             : (boff_t + (uint32_t)(8*p) * 272u);
        *(uint2*)(sm + BOFF + bo)       = make_uint2(rb[p].x, rb[p].y);
        *(uint2*)(sm + BOFF + BHI + bo) = make_uint2(rb[p].z, rb[p].w);
    }
    __syncthreads();

    for (int kc = 0; kc < NC; kc++) {
        if (kc + 1 < NC) {
            const int kg = (kc + 1) * 8;
            #pragma unroll
            for (int p = 0; p < 4; p++) {
                ra[p] = pa[(size_t)(32*p) * lda4 + kg];
                if (TRANSB) rb[p] = bpred[p] ? pb[(size_t)(32*p) * lda4 + kg] : z4;
                else        rb[p] = pb[((size_t)(8*p) + (size_t)(kc+1)*32) * N4];
            }
        }

        const uint32_t cb = sbase + (uint32_t)(kc & 1) * BUFSZ;
        #pragma unroll
        for (int ks = 0; ks < 2; ks++) {
            uint32_t ah[2][4], al[2][4], bh[8][2], bl[8][2];
            #pragma unroll
            for (int mt = 0; mt < 2; mt++) {
                uint32_t addr = cb + (uint32_t)(wm*32 + mt*16 + (lane & 15)) * 80u
                              + (uint32_t)(ks*32) + ((lane >> 4) << 4);
                ldsm_x4(ah[mt][0], ah[mt][1], ah[mt][2], ah[mt][3], addr);
                ldsm_x4(al[mt][0], al[mt][1], al[mt][2], al[mt][3], addr + 10240);
            }
            #pragma unroll
            for (int ntp = 0; ntp < 4; ntp++) {
                uint32_t r0, r1, r2, r3;
                if (TRANSB) {
                    uint32_t addr = cb + BOFF
                                  + (uint32_t)(wn*64 + ntp*16 + (lane & 15)) * 80u
                                  + (uint32_t)(ks*32) + ((lane >> 4) << 4);
                    ldsm_x4(r0, r1, r2, r3, addr);
                    bh[2*ntp][0] = r0; bh[2*ntp+1][0] = r1;
                    bh[2*ntp][1] = r2; bh[2*ntp+1][1] = r3;
                    ldsm_x4(r0, r1, r2, r3, addr + BHI);
                    bl[2*ntp][0] = r0; bl[2*ntp+1][0] = r1;
                    bl[2*ntp][1] = r2; bl[2*ntp+1][1] = r3;
                } else {
                    uint32_t addr = cb + BOFF
                                  + (uint32_t)(ks*16 + (lane & 15)) * 272u
                                  + (uint32_t)(wn*64 + ntp*16) * 2u + ((lane >> 4) << 4);
                    ldsm_x4_t(r0, r1, r2, r3, addr);
                    bh[2*ntp][0] = r0; bh[2*ntp][1] = r1;
                    bh[2*ntp+1][0] = r2; bh[2*ntp+1][1] = r3;
                    ldsm_x4_t(r0, r1, r2, r3, addr + BHI);
                    bl[2*ntp][0] = r0; bl[2*ntp][1] = r1;
                    bl[2*ntp+1][0] = r2; bl[2*ntp+1][1] = r3;
                }
            }
            #pragma unroll
            for (int mt = 0; mt < 2; mt++)
                #pragma unroll
                for (int nt = 0; nt < 8; nt++) {
                    mma16816(acc[mt][nt], ah[mt], bh[nt]);
                    mma16816(acc[mt][nt], ah[mt], bl[nt]);
                    mma16816(acc[mt][nt], al[mt], bh[nt]);
                }
        }

        if (kc + 1 < NC) {
            unsigned char* nb = sm + (uint32_t)((kc + 1) & 1) * BUFSZ;
            #pragma unroll
            for (int p = 0; p < 4; p++) {
                uint32_t ao = aoff_t + (uint32_t)(32*p) * 80u;
                *(uint2*)(nb + ao)         = make_uint2(ra[p].x, ra[p].y);
                *(uint2*)(nb + 10240 + ao) = make_uint2(ra[p].z, ra[p].w);
                uint32_t bo = TRANSB ? (boff_t + (uint32_t)(32*p) * 80u)
                                     : (boff_t + (uint32_t)(8*p) * 272u);
                *(uint2*)(nb + BOFF + bo)       = make_uint2(rb[p].x, rb[p].y);
                *(uint2*)(nb + BOFF + BHI + bo) = make_uint2(rb[p].z, rb[p].w);
            }
            __syncthreads();
        }
    }

    const int mrow = m0 + wm*32;
    #pragma unroll
    for (int mt = 0; mt < 2; mt++) {
        #pragma unroll
        for (int nt = 0; nt < 8; nt++) {
            int col = n0 + wn*64 + nt*8 + tig*2;
            bool ok0 = (!TRANSB) || (col < N);
            bool ok1 = (!TRANSB) || (col + 1 < N);
            float b0v = 0.f, b1v = 0.f;
            if (bias) { if (ok0) b0v = bias[col]; if (ok1) b1v = bias[col+1]; }
            #pragma unroll
            for (int hh = 0; hh < 2; hh++) {
                int row = mrow + mt*16 + grp + hh*8;
                float v0 = acc[mt][nt][2*hh+0] + b0v;
                float v1 = acc[mt][nt][2*hh+1] + b1v;
                if (act) { v0 = gelu_exact(v0); v1 = gelu_exact(v1); }
                if (OUTSPLIT) {
                    float x2 = __shfl_down_sync(0xffffffffu, v0, 1);
                    float x3 = __shfl_down_sync(0xffffffffu, v1, 1);
                    if ((tig & 1) == 0) {
                        uint2 hi, lo;
                        split4(make_float4(v0, v1, x2, x3), hi, lo);
                        Cs[(size_t)row * (N >> 2) + (col >> 2)] = make_uint4(hi.x, hi.y, lo.x, lo.y);
                    }
                } else {
                    size_t base = (size_t)row * N + col;
                    if (res) { if (ok0) v0 += res[base]; if (ok1) v1 += res[base+1]; }
                    if (!TRANSB) {
                        float2 o; o.x = v0; o.y = v1;
                        *(float2*)(C + base) = o;
                    } else {
                        if (ok0) C[base] = v0;
                        if (ok1) C[base+1] = v1;
                    }
                }
            }
        }
    }
}

// ============ fused QKV GEMM: split in/out, double-buffered ============
__global__ void __launch_bounds__(256, 1)
qkv_gemm(const uint4* __restrict__ As,
         const uint4* __restrict__ Wqs, const uint4* __restrict__ Wks, const uint4* __restrict__ Wvs,
         const float* __restrict__ bq_, const float* __restrict__ bk_, const float* __restrict__ bv_,
         uint4* __restrict__ Cs)
{
    extern __shared__ __align__(16) unsigned char sm[];
    constexpr int BHI   = 8704;
    constexpr int BOFF  = 20480;
    constexpr int BUFSZ = BOFF + 2*BHI;   // 37888
    const int K4 = DD >> 2, N4 = DD >> 2;
    const uint32_t sbase = smem_u32(sm);
    const int tid = threadIdx.x, lane = tid & 31, wid = tid >> 5;
    const int wm = wid & 3, wn = wid >> 2;
    const int m0 = blockIdx.y << 7;
    const int sel = blockIdx.x / 6;
    const int n0 = (blockIdx.x % 6) << 7;
    const uint4* Bs   = (sel == 0) ? Wqs : (sel == 1) ? Wks : Wvs;
    const float* bias = (sel == 0) ? bq_ : (sel == 1) ? bk_ : bv_;
    const int grp = lane >> 2, tig = lane & 3;

    float acc[2][8][4];
    #pragma unroll
    for (int i = 0; i < 2; i++)
        #pragma unroll
        for (int j = 0; j < 8; j++)
            #pragma unroll
            for (int q = 0; q < 4; q++) acc[i][j][q] = 0.f;

    const int arow = tid >> 3, ak4 = tid & 7;
    const uint4* pa = As + (size_t)(m0 + arow) * K4 + ak4;
    const uint4* pb = Bs + (size_t)(tid >> 5) * N4 + (n0 >> 2) + (tid & 31);

    const int NC = DD >> 5;
    uint4 ra[4], rb[4];
    const uint32_t aoff_t = (uint32_t)arow * 80u + (uint32_t)ak4 * 8u;
    const uint32_t boff_t = (uint32_t)(tid >> 5) * 272u + (uint32_t)(tid & 31) * 8u;

    #pragma unroll
    for (int p = 0; p < 4; p++) {
        ra[p] = pa[(size_t)(32*p) * K4];
        rb[p] = pb[(size_t)(8*p) * N4];
    }
    #pragma unroll
    for (int p = 0; p < 4; p++) {
        uint32_t ao = aoff_t + (uint32_t)(32*p) * 80u;
        *(uint2*)(sm + ao)         = make_uint2(ra[p].x, ra[p].y);
        *(uint2*)(sm + 10240 + ao) = make_uint2(ra[p].z, ra[p].w);
        uint32_t bo = boff_t + (uint32_t)(8*p) * 272u;
        *(uint2*)(sm + BOFF + bo)       = make_uint2(rb[p].x, rb[p].y);
        *(uint2*)(sm + BOFF + BHI + bo) = make_uint2(rb[p].z, rb[p].w);
    }
    __syncthreads();

    for (int kc = 0; kc < NC; kc++) {
        if (kc + 1 < NC) {
            const int kg = (kc + 1) * 8;
            #pragma unroll
            for (int p = 0; p < 4; p++) {
                ra[p] = pa[(size_t)(32*p) * K4 + kg];
                rb[p] = pb[((size_t)(8*p) + (size_t)(kc+1)*32) * N4];
            }
        }

        const uint32_t cb = sbase + (uint32_t)(kc & 1) * BUFSZ;
        #pragma unroll
        for (int ks = 0; ks < 2; ks++) {
            uint32_t ah[2][4], al[2][4], bh[8][2], bl[8][2];
            #pragma unroll
            for (int mt = 0; mt < 2; mt++) {
                uint32_t addr = cb + (uint32_t)(wm*32 + mt*16 + (lane & 15)) * 80u
                              + (uint32_t)(ks*32) + ((lane >> 4) << 4);
                ldsm_x4(ah[mt][0], ah[mt][1], ah[mt][2], ah[mt][3], addr);
                ldsm_x4(al[mt][0], al[mt][1], al[mt][2], al[mt][3], addr + 10240);
            }
            #pragma unroll
            for (int ntp = 0; ntp < 4; ntp++) {
                uint32_t r0, r1, r2, r3;
                uint32_t addr = cb + BOFF
                              + (uint32_t)(ks*16 + (lane & 15)) * 272u
                              + (uint32_t)(wn*64 + ntp*16) * 2u + ((lane >> 4) << 4);
                ldsm_x4_t(r0, r1, r2, r3, addr);
                bh[2*ntp][0] = r0; bh[2*ntp][1] = r1;
                bh[2*ntp+1][0] = r2; bh[2*ntp+1][1] = r3;
                ldsm_x4_t(r0, r1, r2, r3, addr + BHI);
                bl[2*ntp][0] = r0; bl[2*ntp][1] = r1;
                bl[2*ntp+1][0] = r2; bl[2*ntp+1][1] = r3;
            }
            #pragma unroll
            for (int mt = 0; mt < 2; mt++)
                #pragma unroll
                for (int nt = 0; nt < 8; nt++) {
                    mma16816(acc[mt][nt], ah[mt], bh[nt]);
                    mma16816(acc[mt][nt], ah[mt], bl[nt]);
                    mma16816(acc[mt][nt], al[mt], bh[nt]);
                }
        }

        if (kc + 1 < NC) {
            unsigned char* nb = sm + (uint32_t)((kc + 1) & 1) * BUFSZ;
            #pragma unroll
            for (int p = 0; p < 4; p++) {
                uint32_t ao = aoff_t + (uint32_t)(32*p) * 80u;
                *(uint2*)(nb + ao)         = make_uint2(ra[p].x, ra[p].y);
                *(uint2*)(nb + 10240 + ao) = make_uint2(ra[p].z, ra[p].w);
                uint32_t bo = boff_t + (uint32_t)(8*p) * 272u;
                *(uint2*)(nb + BOFF + bo)       = make_uint2(rb[p].x, rb[p].y);
                *(uint2*)(nb + BOFF + BHI + bo) = make_uint2(rb[p].z, rb[p].w);
            }
            __syncthreads();
        }
    }

    const int mrow = m0 + wm*32;
    #pragma unroll
    for (int mt = 0; mt < 2; mt++) {
        #pragma unroll
        for (int nt = 0; nt < 8; nt++) {
            int col = n0 + wn*64 + nt*8 + tig*2;
            float b0v = bias[col], b1v = bias[col+1];
            #pragma unroll
            for (int hh = 0; hh < 2; hh++) {
                int row = mrow + mt*16 + grp + hh*8;
                float v0 = acc[mt][nt][2*hh+0] + b0v;
                float v1 = acc[mt][nt][2*hh+1] + b1v;
                float x2 = __shfl_down_sync(0xffffffffu, v0, 1);
                float x3 = __shfl_down_sync(0xffffffffu, v1, 1);
                if ((tig & 1) == 0) {
                    uint2 hi, lo;
                    split4(make_float4(v0, v1, x2, x3), hi, lo);
                    Cs[(size_t)row * 576 + (size_t)(sel*192) + (col >> 2)]
                        = make_uint4(hi.x, hi.y, lo.x, lo.y);
                }
            }
        }
    }
}

// ============ flash attention (split qkv input, split attn output) ============
__global__ void __launch_bounds__(128, 1)
flash_kernel(const uint4* __restrict__ qkvs, const float* __restrict__ amask,
             uint4* __restrict__ outs)
{
    __shared__ __align__(16) unsigned char sm[4*9216 + 256];
    const int KHo = 0, KLo = 9216, VHo = 18432, VLo = 27648, AMo = 36864;
    const uint32_t sbase = smem_u32(sm);
    const int tid = threadIdx.x, lane = tid & 31, w = tid >> 5;
    const int grp = lane >> 2, tig = lane & 3;
    const int qt = (int)gridDim.x - 1 - (int)blockIdx.x;
    const int bh = blockIdx.y, b = bh / HH, h = bh % HH;
    const int q0 = qt * 64;

    uint32_t qh[4][4], ql[4][4];
    #pragma unroll
    for (int ks = 0; ks < 4; ks++)
        #pragma unroll
        for (int j = 0; j < 4; j++) {
            int row = q0 + w*16 + grp + (j & 1) * 8;
            int col = h*64 + ks*16 + (j >> 1) * 8 + tig*2;
            uint4 g = qkvs[(size_t)(b*SS + row) * 576 + (col >> 2)];
            if ((col & 3) == 0) { qh[ks][j] = g.x; ql[ks][j] = g.z; }
            else                { qh[ks][j] = g.y; ql[ks][j] = g.w; }
        }

    float o[8][4];
    #pragma unroll
    for (int i = 0; i < 8; i++)
        #pragma unroll
        for (int j = 0; j < 4; j++) o[i][j] = 0.f;
    float mrow0 = -1e30f, mrow1 = -1e30f, lrow0 = 0.f, lrow1 = 0.f;
    const int qr0 = q0 + w*16 + grp, qr1 = qr0 + 8;

    for (int kt = 0; kt <= qt; kt++) {
        __syncthreads();
        const size_t kgbase = (size_t)(b*SS + kt*64) * 576 + 192 + h*16;
        for (int idx = tid; idx < 64*16; idx += 128) {
            int r = idx >> 4, c4 = idx & 15;
            uint4 kg = qkvs[kgbase + (size_t)r*576 + c4];
            *(uint2*)(sm + KHo + r*144 + c4*8) = make_uint2(kg.x, kg.y);
            *(uint2*)(sm + KLo + r*144 + c4*8) = make_uint2(kg.z, kg.w);
            uint4 vg = qkvs[kgbase + 192 + (size_t)r*576 + c4];
            *(uint2*)(sm + VHo + r*144 + c4*8) = make_uint2(vg.x, vg.y);
            *(uint2*)(sm + VLo + r*144 + c4*8) = make_uint2(vg.z, vg.w);
        }
        if (tid < 64) ((float*)(sm + AMo))[tid] = amask[b*SS + kt*64 + tid];
        __syncthreads();

        float s[8][4];
        #pragma unroll
        for (int i = 0; i < 8; i++)
            #pragma unroll
            for (int j = 0; j < 4; j++) s[i][j] = 0.f;
        #pragma unroll
        for (int ks = 0; ks < 4; ks++) {
            uint32_t kh_[8][2], kl_[8][2];
            #pragma unroll
            for (int ntp = 0; ntp < 4; ntp++) {
                uint32_t r0, r1, r2, r3;
                uint32_t addr = sbase + KHo + (uint32_t)(ntp*16 + (lane & 15)) * 144u
                              + (uint32_t)(ks*32) + ((lane >> 4) << 4);
                ldsm_x4(r0, r1, r2, r3, addr);
                kh_[2*ntp][0] = r0; kh_[2*ntp][1] = r2;
                kh_[2*ntp+1][0] = r1; kh_[2*ntp+1][1] = r3;
                ldsm_x4(r0, r1, r2, r3, addr + (KLo - KHo));
                kl_[2*ntp][0] = r0; kl_[2*ntp][1] = r2;
                kl_[2*ntp+1][0] = r1; kl_[2*ntp+1][1] = r3;
            }
            #pragma unroll
            for (int nt = 0; nt < 8; nt++) {
                mma16816(s[nt], qh[ks], kh_[nt]);
                mma16816(s[nt], qh[ks], kl_[nt]);
                mma16816(s[nt], ql[ks], kh_[nt]);
            }
        }
        const float* am = (const float*)(sm + AMo);
        #pragma unroll
        for (int nt = 0; nt < 8; nt++) {
            int c0 = nt*8 + tig*2;
            int kc0 = kt*64 + c0, kc1 = kc0 + 1;
            float a0 = am[c0], a1 = am[c0+1];
            s[nt][0] = (kc0 <= qr0 && a0 != 0.f) ? s[nt][0]*0.125f : -1e30f;
            s[nt][1] = (kc1 <= qr0 && a1 != 0.f) ? s[nt][1]*0.125f : -1e30f;
            s[nt][2] = (kc0 <= qr1 && a0 != 0.f) ? s[nt][2]*0.125f : -1e30f;
            s[nt][3] = (kc1 <= qr1 && a1 != 0.f) ? s[nt][3]*0.125f : -1e30f;
        }
        float mx0 = -1e30f, mx1 = -1e30f;
        #pragma unroll
        for (int nt = 0; nt < 8; nt++) {
            mx0 = fmaxf(mx0, fmaxf(s[nt][0], s[nt][1]));
            mx1 = fmaxf(mx1, fmaxf(s[nt][2], s[nt][3]));
        }
        mx0 = fmaxf(mx0, __shfl_xor_sync(0xffffffffu, mx0, 1));
        mx0 = fmaxf(mx0, __shfl_xor_sync(0xffffffffu, mx0, 2));
        mx1 = fmaxf(mx1, __shfl_xor_sync(0xffffffffu, mx1, 1));
        mx1 = fmaxf(mx1, __shfl_xor_sync(0xffffffffu, mx1, 2));
        float mn0 = fmaxf(mrow0, mx0), mn1 = fmaxf(mrow1, mx1);
        float sc0 = __expf(mrow0 - mn0), sc1 = __expf(mrow1 - mn1);
        mrow0 = mn0; mrow1 = mn1;
        float rs0 = 0.f, rs1 = 0.f;
        #pragma unroll
        for (int nt = 0; nt < 8; nt++) {
            s[nt][0] = __expf(s[nt][0] - mn0); rs0 += s[nt][0];
            s[nt][1] = __expf(s[nt][1] - mn0); rs0 += s[nt][1];
            s[nt][2] = __expf(s[nt][2] - mn1); rs1 += s[nt][2];
            s[nt][3] = __expf(s[nt][3] - mn1); rs1 += s[nt][3];
        }
        rs0 += __shfl_xor_sync(0xffffffffu, rs0, 1);
        rs0 += __shfl_xor_sync(0xffffffffu, rs0, 2);
        rs1 += __shfl_xor_sync(0xffffffffu, rs1, 1);
        rs1 += __shfl_xor_sync(0xffffffffu, rs1, 2);
        lrow0 = lrow0*sc0 + rs0; lrow1 = lrow1*sc1 + rs1;
        #pragma unroll
        for (int nt = 0; nt < 8; nt++) {
            o[nt][0] *= sc0; o[nt][1] *= sc0;
            o[nt][2] *= sc1; o[nt][3] *= sc1;
        }
        #pragma unroll
        for (int ks = 0; ks < 4; ks++) {
            uint32_t pah[4], pal[4];
            split2(s[2*ks][0],   s[2*ks][1],   pah[0], pal[0]);
            split2(s[2*ks][2],   s[2*ks][3],   pah[1], pal[1]);
            split2(s[2*ks+1][0], s[2*ks+1][1], pah[2], pal[2]);
            split2(s[2*ks+1][2], s[2*ks+1][3], pah[3], pal[3]);
            uint32_t vh_[8][2], vl_[8][2];
            #pragma unroll
            for (int ntp = 0; ntp < 4; ntp++) {
                uint32_t r0, r1, r2, r3;
                uint32_t addr = sbase + VHo + (uint32_t)(ks*16 + (lane & 15)) * 144u
                              + (uint32_t)(ntp*32) + ((lane >> 4) << 4);
                ldsm_x4_t(r0, r1, r2, r3, addr);
                vh_[2*ntp][0] = r0; vh_[2*ntp][1] = r1;
                vh_[2*ntp+1][0] = r2; vh_[2*ntp+1][1] = r3;
                ldsm_x4_t(r0, r1, r2, r3, addr + (VLo - VHo));
                vl_[2*ntp][0] = r0; vl_[2*ntp][1] = r1;
                vl_[2*ntp+1][0] = r2; vl_[2*ntp+1][1] = r3;
            }
            #pragma unroll
            for (int nt = 0; nt < 8; nt++) {
                mma16816(o[nt], pah, vh_[nt]);
                mma16816(o[nt], pah, vl_[nt]);
                mma16816(o[nt], pal, vh_[nt]);
            }
        }
    }
    float inv0 = 1.f / lrow0, inv1 = 1.f / lrow1;
    #pragma unroll
    for (int nt = 0; nt < 8; nt++) {
        int col = h*64 + nt*8 + tig*2;
        float v0 = o[nt][0]*inv0, v1 = o[nt][1]*inv0;
        float u0 = o[nt][2]*inv1, u1 = o[nt][3]*inv1;
        float x2 = __shfl_down_sync(0xffffffffu, v0, 1);
        float x3 = __shfl_down_sync(0xffffffffu, v1, 1);
        float y2 = __shfl_down_sync(0xffffffffu, u0, 1);
        float y3 = __shfl_down_sync(0xffffffffu, u1, 1);
        if ((tig & 1) == 0) {
            uint2 hi, lo;
            split4(make_float4(v0, v1, x2, x3), hi, lo);
            outs[(size_t)(b*SS + qr0) * 192 + (col >> 2)] = make_uint4(hi.x, hi.y, lo.x, lo.y);
            split4(make_float4(u0, u1, y2, y3), hi, lo);
            outs[(size_t)(b*SS + qr1) * 192 + (col >> 2)] = make_uint4(hi.x, hi.y, lo.x, lo.y);
        }
    }
}

// ---------------- position ids (parallel block scan) ----------------
__global__ void posids_kernel(const float* __restrict__ amask, int* __restrict__ pos) {
    __shared__ float ws[32];
    int b = blockIdx.x, t = threadIdx.x;   // 1024 threads
    float m = amask[b*SS + t];
    float v = m;
    #pragma unroll
    for (int o = 1; o < 32; o <<= 1) {
        float u = __shfl_up_sync(0xffffffffu, v, o);
        if ((t & 31) >= o) v += u;
    }
    if ((t & 31) == 31) ws[t >> 5] = v;
    __syncthreads();
    if (t < 32) {
        float w2 = ws[t];
        #pragma unroll
        for (int o = 1; o < 32; o <<= 1) {
            float u = __shfl_up_sync(0xffffffffu, w2, o);
            if (t >= o) w2 += u;
        }
        ws[t] = w2;
    }
    __syncthreads();
    float total = v + ((t >> 5) ? ws[(t >> 5) - 1] : 0.f);
    pos[b*SS + t] = (m == 0.f) ? 0 : (int)(total - 1.f);
}

// ---------------- embedding ----------------
__global__ void embed_kernel(const int* __restrict__ ids, const int* __restrict__ pos,
                             const float* __restrict__ tok, const float* __restrict__ pemb,
                             float* __restrict__ x) {
    int row = blockIdx.x;
    int id = ids[row];
    int p  = pos[row];
    int tid = threadIdx.x;
    #pragma unroll
    for (int t = 0; t < 3; t++) {
        int d = tid + t*256;
        x[(size_t)row*DD + d] = tok[(size_t)id*DD + d] + pemb[(size_t)p*DD + d];
    }
}

// ---------------- layernorm -> split output (192 threads) ----------------
__global__ void ln_split_kernel(const float* __restrict__ x, const float* __restrict__ g,
                                const float* __restrict__ b, uint4* __restrict__ ys) {
    __shared__ float pr[6];
    int row = blockIdx.x, tid = threadIdx.x;   // 192 threads
    float4 v = ((const float4*)(x + (size_t)row*DD))[tid];
    float s = v.x + v.y + v.z + v.w;
    #pragma unroll
    for (int o = 16; o; o >>= 1) s += __shfl_xor_sync(0xffffffffu, s, o);
    if ((tid & 31) == 0) pr[tid >> 5] = s;
    __syncthreads();
    float mu = (pr[0]+pr[1]+pr[2]+pr[3]+pr[4]+pr[5]) * (1.f/DD);
    float dx = v.x-mu, dy = v.y-mu, dz = v.z-mu, dw = v.w-mu;
    float s2 = dx*dx + dy*dy + dz*dz + dw*dw;
    #pragma unroll
    for (int o = 16; o; o >>= 1) s2 += __shfl_xor_sync(0xffffffffu, s2, o);
    __syncthreads();
    if ((tid & 31) == 0) pr[tid >> 5] = s2;
    __syncthreads();
    float rstd = rsqrtf((pr[0]+pr[1]+pr[2]+pr[3]+pr[4]+pr[5]) * (1.f/DD) + 1e-5f);
    float4 gg = ((const float4*)g)[tid], bb = ((const float4*)b)[tid];
    float4 y = make_float4(dx*rstd*gg.x + bb.x, dy*rstd*gg.y + bb.y,
                           dz*rstd*gg.z + bb.z, dw*rstd*gg.w + bb.w);
    uint2 hi, lo; split4(y, hi, lo);
    ys[(size_t)row*192 + tid] = make_uint4(hi.x, hi.y, lo.x, lo.y);
}

// ---------------- launch ----------------
extern "C" void kernel_launch(void* const* d_in, const int* in_sizes, int n_in,
                              void* d_out, int out_size) {
    const int*   ids   = (const int*)  d_in[0];
    const float* amask = (const float*)d_in[1];
    const float* tok   = (const float*)d_in[2];
    const float* pemb  = (const float*)d_in[3];
    const float* ln1g  = (const float*)d_in[4];
    const float* ln1b  = (const float*)d_in[5];
    const float* Wq    = (const float*)d_in[6];
    const float* bq    = (const float*)d_in[7];
    const float* Wk    = (const float*)d_in[8];
    const float* bk    = (const float*)d_in[9];
    const float* Wv    = (const float*)d_in[10];
    const float* bv    = (const float*)d_in[11];
    const float* Wp    = (const float*)d_in[12];
    const float* bp    = (const float*)d_in[13];
    const float* ln2g  = (const float*)d_in[14];
    const float* ln2b  = (const float*)d_in[15];
    const float* W1    = (const float*)d_in[16];
    const float* b1    = (const float*)d_in[17];
    const float* W2    = (const float*)d_in[18];
    const float* b2    = (const float*)d_in[19];
    const float* lnfg  = (const float*)d_in[20];
    const float* lnfb  = (const float*)d_in[21];
    float* out = (float*)d_out;

    float *xp, *partp; int* pidp;
    uint4 *hs, *qkvs, *as, *fs, *wqs, *wks, *wvs, *wps, *w1s, *w2s, *toks;
    cudaGetSymbolAddress((void**)&xp,   g_x);
    cudaGetSymbolAddress((void**)&partp, g_mlp2p);
    cudaGetSymbolAddress((void**)&pidp, g_pos);
    cudaGetSymbolAddress((void**)&hs,   g_h_s);
    cudaGetSymbolAddress((void**)&qkvs, g_qkv_s);
    cudaGetSymbolAddress((void**)&as,   g_attn_s);
    cudaGetSymbolAddress((void**)&fs,   g_ff_s);
    cudaGetSymbolAddress((void**)&wqs,  g_wq_s);
    cudaGetSymbolAddress((void**)&wks,  g_wk_s);
    cudaGetSymbolAddress((void**)&wvs,  g_wv_s);
    cudaGetSymbolAddress((void**)&wps,  g_wp_s);
    cudaGetSymbolAddress((void**)&w1s,  g_w1_s);
    cudaGetSymbolAddress((void**)&w2s,  g_w2_s);
    cudaGetSymbolAddress((void**)&toks, g_tok_s);

    const int SM_T0 = 2*(20480 + 2*8704);   // 75776
    const int SM_T1 = 2*(20480 + 2*10240);  // 81920
    cudaFuncSetAttribute(mma_gemm<0,0>, cudaFuncAttributeMaxDynamicSharedMemorySize, SM_T0);
    cudaFuncSetAttribute(mma_gemm<0,1>, cudaFuncAttributeMaxDynamicSharedMemorySize, SM_T0);
    cudaFuncSetAttribute(mma_gemm<1,0>, cudaFuncAttributeMaxDynamicSharedMemorySize, SM_T1);
    cudaFuncSetAttribute(qkv_gemm, cudaFuncAttributeMaxDynamicSharedMemorySize, SM_T0);

    // exact-grid splits (1 elem/thread => max MLP, DRAM-saturating)
    const int nW  = LL*DD*DD/4;
    const int nW1 = LL*DD*FF/4;
    const int nT  = VV*DD/4;
    split_kernel<<<(nW +255)/256, 256>>>((const float4*)Wq, wqs, nW);
    split_kernel<<<(nW +255)/256, 256>>>((const float4*)Wk, wks, nW);
    split_kernel<<<(nW +255)/256, 256>>>((const float4*)Wv, wvs, nW);
    split_kernel<<<(nW +255)/256, 256>>>((const float4*)Wp, wps, nW);
    split_kernel<<<(nW1+255)/256, 256>>>((const float4*)W1, w1s, nW1);
    split_kernel<<<(nW1+255)/256, 256>>>((const float4*)W2, w2s, nW1);
    split_kernel<<<(nT +255)/256, 256>>>((const float4*)tok, toks, nT);

    posids_kernel<<<BB, 1024>>>(amask, pidp);
    embed_kernel<<<MM, 256>>>(ids, pidp, tok, pemb, xp);

    dim3 gQKV(18, MM/128);             // 18 x 16
    dim3 gF(FF/128, MM/128);           // 24 x 16
    dim3 gP(DD/128, MM/128, 3);        // 6 x 16 x 3  (proj split-K)
    dim3 gM2(DD/128, MM/128, 3);       // 6 x 16 x 3  (mlp2 split-K)
    dim3 gV(MM/128, (VV+127)/128);     // 16 x 393 (m fastest)
    dim3 gFA(SS/64, BB*HH);

    // layer-0 ln1 (subsequent ln1/ln2/lnf are fused into the split-K reduces)
    ln_split_kernel<<<MM, 192>>>(xp, ln1g, ln1b, hs);

    for (int l = 0; l < LL; l++) {
        const uint4* wql = wqs + (size_t)l*(DD*DD/4);
        const uint4* wkl = wks + (size_t)l*(DD*DD/4);
        const uint4* wvl = wvs + (size_t)l*(DD*DD/4);
        const uint4* wpl = wps + (size_t)l*(DD*DD/4);
        const uint4* w1l = w1s + (size_t)l*(DD*FF/4);
        const uint4* w2l = w2s + (size_t)l*(DD*FF/4);

        qkv_gemm<<<gQKV, 256, SM_T0>>>(hs, wql, wkl, wvl, bq + l*DD, bk + l*DD, bv + l*DD, qkvs);
        flash_kernel<<<gFA, 128>>>(qkvs, amask, as);
        mma_gemm<0,0><<<gP, 256, SM_T0>>>(as, wpl, nullptr, nullptr, partp, nullptr,
                                          MM, DD, DD/3, 0, DD/4);
        reduce_ln_kernel<<<MM, 192>>>((const float4*)partp, bp + l*DD, (float4*)xp,
                                      ln2g + l*DD, ln2b + l*DD, hs);
        mma_gemm<0,1><<<gF, 256, SM_T0>>>(hs, w1l, b1 + l*FF, nullptr, nullptr, fs,
                                          MM, FF, DD, 1, DD/4);
        mma_gemm<0,0><<<gM2, 256, SM_T0>>>(fs, w2l, nullptr, nullptr, partp, nullptr,
                                           MM, DD, FF/3, 0, FF/4);
        const float* ng = (l + 1 < LL) ? (ln1g + (l+1)*DD) : lnfg;
        const float* nb = (l + 1 < LL) ? (ln1b + (l+1)*DD) : lnfb;
        reduce_ln_kernel<<<MM, 192>>>((const float4*)partp, b2 + l*DD, (float4*)xp,
                                      ng, nb, hs);
    }

    mma_gemm<1,0><<<gV, 256, SM_T1>>>(hs, toks, nullptr, nullptr, out, nullptr,
                                      MM, VV, DD, 0, DD/4);
}

// round 15
// speedup vs baseline: 1.6121x; 1.0085x over previous
#include <cuda_runtime.h>
#include <cuda_bf16.h>
#include <math.h>
#include <stdint.h>

#define BB 2
#define SS 1024
#define DD 768
#define HH 12
#define HDD 64
#define LL 12
#define VV 50257
#define FF 3072
#define MM (BB*SS)   // 2048

// ---------------- scratch (allocation-free) ----------------
// split format (GEMM operands): uint4 = {hi01, hi23, lo01, lo23} per 4 elems.
// qkv uses separate hi/lo planes (uint2 per 4 elems) for cp.async in flash.
__device__ float g_x[MM*DD];
__device__ int   g_pos[BB*SS];
__device__ uint4 g_h_s[MM*DD/4];
__device__ uint2 g_qkv_hi[MM*576];
__device__ uint2 g_qkv_lo[MM*576];
__device__ uint4 g_attn_s[MM*DD/4];
__device__ uint4 g_ff_s[MM*FF/4];
__device__ float g_mlp2p[3*MM*DD];     // split-K partials (MLP2 / proj)
__device__ uint4 g_wq_s[LL*DD*DD/4];
__device__ uint4 g_wk_s[LL*DD*DD/4];
__device__ uint4 g_wv_s[LL*DD*DD/4];
__device__ uint4 g_wp_s[LL*DD*DD/4];
__device__ uint4 g_w1_s[LL*DD*FF/4];
__device__ uint4 g_w2_s[LL*DD*FF/4];
__device__ uint4 g_tok_s[(size_t)VV*DD/4];

// ================= helpers =================
__device__ __forceinline__ uint32_t smem_u32(const void* p) {
    uint32_t a;
    asm("{ .reg .u64 t; cvta.to.shared.u64 t, %1; cvt.u32.u64 %0, t; }" : "=r"(a) : "l"(p));
    return a;
}
__device__ __forceinline__ void ldsm_x4(uint32_t& r0, uint32_t& r1, uint32_t& r2, uint32_t& r3,
                                        uint32_t addr) {
    asm volatile("ldmatrix.sync.aligned.m8n8.x4.shared.b16 {%0,%1,%2,%3}, [%4];"
                 : "=r"(r0), "=r"(r1), "=r"(r2), "=r"(r3) : "r"(addr));
}
__device__ __forceinline__ void ldsm_x4_t(uint32_t& r0, uint32_t& r1, uint32_t& r2, uint32_t& r3,
                                          uint32_t addr) {
    asm volatile("ldmatrix.sync.aligned.m8n8.x4.trans.shared.b16 {%0,%1,%2,%3}, [%4];"
                 : "=r"(r0), "=r"(r1), "=r"(r2), "=r"(r3) : "r"(addr));
}
__device__ __forceinline__ void mma16816(float* c, const uint32_t* a, const uint32_t* b) {
    asm volatile("mma.sync.aligned.m16n8k16.row.col.f32.bf16.bf16.f32 "
                 "{%0,%1,%2,%3}, {%4,%5,%6,%7}, {%8,%9}, {%0,%1,%2,%3};"
                 : "+f"(c[0]), "+f"(c[1]), "+f"(c[2]), "+f"(c[3])
                 : "r"(a[0]), "r"(a[1]), "r"(a[2]), "r"(a[3]), "r"(b[0]), "r"(b[1]));
}
__device__ __forceinline__ void cp16(uint32_t saddr, const void* gptr) {
    asm volatile("cp.async.cg.shared.global [%0], [%1], 16;" :: "r"(saddr), "l"(gptr));
}
#define CP_COMMIT() asm volatile("cp.async.commit_group;" ::: "memory")
#define CP_WAIT1()  asm volatile("cp.async.wait_group 1;" ::: "memory")
#define CP_WAIT0()  asm volatile("cp.async.wait_group 0;" ::: "memory")

__device__ __forceinline__ void split4(float4 v, uint2& hi, uint2& lo) {
    __nv_bfloat16 h0 = __float2bfloat16(v.x), h1 = __float2bfloat16(v.y);
    __nv_bfloat16 h2 = __float2bfloat16(v.z), h3 = __float2bfloat16(v.w);
    __nv_bfloat16 l0 = __float2bfloat16(v.x - __bfloat162float(h0));
    __nv_bfloat16 l1 = __float2bfloat16(v.y - __bfloat162float(h1));
    __nv_bfloat16 l2 = __float2bfloat16(v.z - __bfloat162float(h2));
    __nv_bfloat16 l3 = __float2bfloat16(v.w - __bfloat162float(h3));
    __nv_bfloat162 a = __nv_bfloat162(h0, h1), b = __nv_bfloat162(h2, h3);
    __nv_bfloat162 c = __nv_bfloat162(l0, l1), d = __nv_bfloat162(l2, l3);
    hi.x = *(uint32_t*)&a; hi.y = *(uint32_t*)&b;
    lo.x = *(uint32_t*)&c; lo.y = *(uint32_t*)&d;
}
__device__ __forceinline__ void split2(float a, float b, uint32_t& hi, uint32_t& lo) {
    __nv_bfloat16 h0 = __float2bfloat16(a), h1 = __float2bfloat16(b);
    __nv_bfloat16 l0 = __float2bfloat16(a - __bfloat162float(h0));
    __nv_bfloat16 l1 = __float2bfloat16(b - __bfloat162float(h1));
    __nv_bfloat162 H(h0, h1), L(l0, l1);
    hi = *(uint32_t*)&H; lo = *(uint32_t*)&L;
}
__device__ __forceinline__ float gelu_exact(float v) {
    return 0.5f * v * (1.0f + erff(v * 0.70710678118654752f));
}

// ---------------- fp32 -> split converter ----------------
__global__ void split_kernel(const float4* __restrict__ src, uint4* __restrict__ dst, int n) {
    int i = blockIdx.x*blockDim.x + threadIdx.x;
    if (i < n) {
        uint2 hi, lo;
        split4(src[i], hi, lo);
        dst[i] = make_uint4(hi.x, hi.y, lo.x, lo.y);
    }
}

// ---------------- fused split-K reduce + layernorm + split ----------------
__global__ void reduce_ln_kernel(const float4* __restrict__ part, const float* __restrict__ bias,
                                 float4* __restrict__ x, const float* __restrict__ g,
                                 const float* __restrict__ b, uint4* __restrict__ ys) {
    __shared__ float pr[6];
    const int S = MM*DD/4;
    int row = blockIdx.x, tid = threadIdx.x;   // 192 threads
    int i = row*192 + tid;
    float4 p0 = part[i], p1 = part[i + S], p2 = part[i + 2*S];
    float4 bb4 = ((const float4*)bias)[tid];
    float4 v = x[i];
    v.x += p0.x + p1.x + p2.x + bb4.x;
    v.y += p0.y + p1.y + p2.y + bb4.y;
    v.z += p0.z + p1.z + p2.z + bb4.z;
    v.w += p0.w + p1.w + p2.w + bb4.w;
    x[i] = v;

    float s = v.x + v.y + v.z + v.w;
    #pragma unroll
    for (int o = 16; o; o >>= 1) s += __shfl_xor_sync(0xffffffffu, s, o);
    if ((tid & 31) == 0) pr[tid >> 5] = s;
    __syncthreads();
    float mu = (pr[0]+pr[1]+pr[2]+pr[3]+pr[4]+pr[5]) * (1.f/DD);
    float dx = v.x-mu, dy = v.y-mu, dz = v.z-mu, dw = v.w-mu;
    float s2 = dx*dx + dy*dy + dz*dz + dw*dw;
    #pragma unroll
    for (int o = 16; o; o >>= 1) s2 += __shfl_xor_sync(0xffffffffu, s2, o);
    __syncthreads();
    if ((tid & 31) == 0) pr[tid >> 5] = s2;
    __syncthreads();
    float rstd = rsqrtf((pr[0]+pr[1]+pr[2]+pr[3]+pr[4]+pr[5]) * (1.f/DD) + 1e-5f);
    float4 gg = ((const float4*)g)[tid], bb = ((const float4*)b)[tid];
    float4 y = make_float4(dx*rstd*gg.x + bb.x, dy*rstd*gg.y + bb.y,
                           dz*rstd*gg.z + bb.z, dw*rstd*gg.w + bb.w);
    uint2 hi, lo; split4(y, hi, lo);
    ys[i] = make_uint4(hi.x, hi.y, lo.x, lo.y);
}

// ============ split-bf16 GEMM, pre-split inputs, double-buffered smem ============
template<int TRANSB, int OUTSPLIT>
__global__ void __launch_bounds__(256, 1)
mma_gemm(const uint4* __restrict__ As, const uint4* __restrict__ Bs,
         const float* __restrict__ bias, const float* __restrict__ res,
         float* __restrict__ C, uint4* __restrict__ Cs,
         int M, int N, int K, int act, int lda4)
{
    extern __shared__ __align__(16) unsigned char sm[];
    constexpr int BHI   = TRANSB ? 10240 : 8704;
    constexpr int BOFF  = 20480;                 // A hi+lo
    constexpr int BUFSZ = BOFF + 2*BHI;
    const uint32_t sbase = smem_u32(sm);
    const int tid = threadIdx.x, lane = tid & 31, wid = tid >> 5;
    const int wm = wid & 3, wn = wid >> 2;
    const int m0 = (TRANSB ? blockIdx.x : blockIdx.y) << 7;
    const int n0 = (TRANSB ? blockIdx.y : blockIdx.x) << 7;
    const int grp = lane >> 2, tig = lane & 3;
    const int N4 = N >> 2;

    const int z = blockIdx.z;
    As += (size_t)z * (K >> 2);
    if (TRANSB) Bs += (size_t)z * (K >> 2);
    else        Bs += (size_t)z * K * N4;
    C  += (size_t)z * M * N;

    float acc[2][8][4];
    #pragma unroll
    for (int i = 0; i < 2; i++)
        #pragma unroll
        for (int j = 0; j < 8; j++)
            #pragma unroll
            for (int q = 0; q < 4; q++) acc[i][j][q] = 0.f;

    const int arow = tid >> 3, ak4 = tid & 7;
    const uint4* pa = As + (size_t)(m0 + arow) * lda4 + ak4;

    const uint4* pb;
    bool bpred[4];
    if (TRANSB) {
        #pragma unroll
        for (int p = 0; p < 4; p++) bpred[p] = (n0 + arow + 32*p) < N;
        pb = Bs + (size_t)(n0 + arow) * lda4 + ak4;
    } else {
        #pragma unroll
        for (int p = 0; p < 4; p++) bpred[p] = true;
        pb = Bs + (size_t)(tid >> 5) * N4 + (n0 >> 2) + (tid & 31);
    }

    const int NC = K >> 5;
    uint4 ra[4], rb[4];
    const uint4 z4 = make_uint4(0u, 0u, 0u, 0u);

    const uint32_t aoff_t = (uint32_t)arow * 80u + (uint32_t)ak4 * 8u;
    uint32_t boff_t;
    if (TRANSB) boff_t = aoff_t;
    else        boff_t = (uint32_t)(tid >> 5) * 272u + (uint32_t)(tid & 31) * 8u;

    #pragma unroll
    for (int p = 0; p < 4; p++) {
        ra[p] = pa[(size_t)(32*p) * lda4];
        if (TRANSB) rb[p] = bpred[p] ? pb[(size_t)(32*p) * lda4] : z4;
        else        rb[p] = pb[(size_t)(8*p) * N4];
    }
    #pragma unroll
    for (int p = 0; p < 4; p++) {
        uint32_t ao = aoff_t + (uint32_t)(32*p) * 80u;
        *(uint2*)(sm + ao)         = make_uint2(ra[p].x, ra[p].y);
        *(uint2*)(sm + 10240 + ao) = make_uint2(ra[p].z, ra[p].w);
        uint32_t bo = TRANSB ? (boff_t + (uint32_t)(32*p) * 80u)
                             : (boff_t + (uint32_t)(8*p) * 272u);
        *(uint2*)(sm + BOFF + bo)       = make_uint2(rb[p].x, rb[p].y);
        *(uint2*)(sm + BOFF + BHI + bo) = make_uint2(rb[p].z, rb[p].w);
    }
    __syncthreads();

    for (int kc = 0; kc < NC; kc++) {
        if (kc + 1 < NC) {
            const int kg = (kc + 1) * 8;
            #pragma unroll
            for (int p = 0; p < 4; p++) {
                ra[p] = pa[(size_t)(32*p) * lda4 + kg];
                if (TRANSB) rb[p] = bpred[p] ? pb[(size_t)(32*p) * lda4 + kg] : z4;
                else        rb[p] = pb[((size_t)(8*p) + (size_t)(kc+1)*32) * N4];
            }
        }

        const uint32_t cb = sbase + (uint32_t)(kc & 1) * BUFSZ;
        #pragma unroll
        for (int ks = 0; ks < 2; ks++) {
            uint32_t ah[2][4], al[2][4], bh[8][2], bl[8][2];
            #pragma unroll
            for (int mt = 0; mt < 2; mt++) {
                uint32_t addr = cb + (uint32_t)(wm*32 + mt*16 + (lane & 15)) * 80u
                              + (uint32_t)(ks*32) + ((lane >> 4) << 4);
                ldsm_x4(ah[mt][0], ah[mt][1], ah[mt][2], ah[mt][3], addr);
                ldsm_x4(al[mt][0], al[mt][1], al[mt][2], al[mt][3], addr + 10240);
            }
            #pragma unroll
            for (int ntp = 0; ntp < 4; ntp++) {
                uint32_t r0, r1, r2, r3;
                if (TRANSB) {
                    uint32_t addr = cb + BOFF
                                  + (uint32_t)(wn*64 + ntp*16 + (lane & 15)) * 80u
                                  + (uint32_t)(ks*32) + ((lane >> 4) << 4);
                    ldsm_x4(r0, r1, r2, r3, addr);
                    bh[2*ntp][0] = r0; bh[2*ntp+1][0] = r1;
                    bh[2*ntp][1] = r2; bh[2*ntp+1][1] = r3;
                    ldsm_x4(r0, r1, r2, r3, addr + BHI);
                    bl[2*ntp][0] = r0; bl[2*ntp+1][0] = r1;
                    bl[2*ntp][1] = r2; bl[2*ntp+1][1] = r3;
                } else {
                    uint32_t addr = cb + BOFF
                                  + (uint32_t)(ks*16 + (lane & 15)) * 272u
                                  + (uint32_t)(wn*64 + ntp*16) * 2u + ((lane >> 4) << 4);
                    ldsm_x4_t(r0, r1, r2, r3, addr);
                    bh[2*ntp][0] = r0; bh[2*ntp][1] = r1;
                    bh[2*ntp+1][0] = r2; bh[2*ntp+1][1] = r3;
                    ldsm_x4_t(r0, r1, r2, r3, addr + BHI);
                    bl[2*ntp][0] = r0; bl[2*ntp][1] = r1;
                    bl[2*ntp+1][0] = r2; bl[2*ntp+1][1] = r3;
                }
            }
            #pragma unroll
            for (int mt = 0; mt < 2; mt++)
                #pragma unroll
                for (int nt = 0; nt < 8; nt++) {
                    mma16816(acc[mt][nt], ah[mt], bh[nt]);
                    mma16816(acc[mt][nt], ah[mt], bl[nt]);
                    mma16816(acc[mt][nt], al[mt], bh[nt]);
                }
        }

        if (kc + 1 < NC) {
            unsigned char* nb = sm + (uint32_t)((kc + 1) & 1) * BUFSZ;
            #pragma unroll
            for (int p = 0; p < 4; p++) {
                uint32_t ao = aoff_t + (uint32_t)(32*p) * 80u;
                *(uint2*)(nb + ao)         = make_uint2(ra[p].x, ra[p].y);
                *(uint2*)(nb + 10240 + ao) = make_uint2(ra[p].z, ra[p].w);
                uint32_t bo = TRANSB ? (boff_t + (uint32_t)(32*p) * 80u)
                                     : (boff_t + (uint32_t)(8*p) * 272u);
                *(uint2*)(nb + BOFF + bo)       = make_uint2(rb[p].x, rb[p].y);
                *(uint2*)(nb + BOFF + BHI + bo) = make_uint2(rb[p].z, rb[p].w);
            }
            __syncthreads();
        }
    }

    const int mrow = m0 + wm*32;
    #pragma unroll
    for (int mt = 0; mt < 2; mt++) {
        #pragma unroll
        for (int nt = 0; nt < 8; nt++) {
            int col = n0 + wn*64 + nt*8 + tig*2;
            bool ok0 = (!TRANSB) || (col < N);
            bool ok1 = (!TRANSB) || (col + 1 < N);
            float b0v = 0.f, b1v = 0.f;
            if (bias) { if (ok0) b0v = bias[col]; if (ok1) b1v = bias[col+1]; }
            #pragma unroll
            for (int hh = 0; hh < 2; hh++) {
                int row = mrow + mt*16 + grp + hh*8;
                float v0 = acc[mt][nt][2*hh+0] + b0v;
                float v1 = acc[mt][nt][2*hh+1] + b1v;
                if (act) { v0 = gelu_exact(v0); v1 = gelu_exact(v1); }
                if (OUTSPLIT) {
                    float x2 = __shfl_down_sync(0xffffffffu, v0, 1);
                    float x3 = __shfl_down_sync(0xffffffffu, v1, 1);
                    if ((tig & 1) == 0) {
                        uint2 hi, lo;
                        split4(make_float4(v0, v1, x2, x3), hi, lo);
                        Cs[(size_t)row * (N >> 2) + (col >> 2)] = make_uint4(hi.x, hi.y, lo.x, lo.y);
                    }
                } else {
                    size_t base = (size_t)row * N + col;
                    if (res) { if (ok0) v0 += res[base]; if (ok1) v1 += res[base+1]; }
                    if (!TRANSB) {
                        float2 o; o.x = v0; o.y = v1;
                        *(float2*)(C + base) = o;
                    } else {
                        if (ok0) C[base] = v0;
                        if (ok1) C[base+1] = v1;
                    }
                }
            }
        }
    }
}

// ============ fused QKV GEMM: split in, hi/lo planes out ============
__global__ void __launch_bounds__(256, 1)
qkv_gemm(const uint4* __restrict__ As,
         const uint4* __restrict__ Wqs, const uint4* __restrict__ Wks, const uint4* __restrict__ Wvs,
         const float* __restrict__ bq_, const float* __restrict__ bk_, const float* __restrict__ bv_,
         uint2* __restrict__ Chi, uint2* __restrict__ Clo)
{
    extern __shared__ __align__(16) unsigned char sm[];
    constexpr int BHI   = 8704;
    constexpr int BOFF  = 20480;
    constexpr int BUFSZ = BOFF + 2*BHI;   // 37888
    const int K4 = DD >> 2, N4 = DD >> 2;
    const uint32_t sbase = smem_u32(sm);
    const int tid = threadIdx.x, lane = tid & 31, wid = tid >> 5;
    const int wm = wid & 3, wn = wid >> 2;
    const int m0 = blockIdx.y << 7;
    const int sel = blockIdx.x / 6;
    const int n0 = (blockIdx.x % 6) << 7;
    const uint4* Bs   = (sel == 0) ? Wqs : (sel == 1) ? Wks : Wvs;
    const float* bias = (sel == 0) ? bq_ : (sel == 1) ? bk_ : bv_;
    const int grp = lane >> 2, tig = lane & 3;

    float acc[2][8][4];
    #pragma unroll
    for (int i = 0; i < 2; i++)
        #pragma unroll
        for (int j = 0; j < 8; j++)
            #pragma unroll
            for (int q = 0; q < 4; q++) acc[i][j][q] = 0.f;

    const int arow = tid >> 3, ak4 = tid & 7;
    const uint4* pa = As + (size_t)(m0 + arow) * K4 + ak4;
    const uint4* pb = Bs + (size_t)(tid >> 5) * N4 + (n0 >> 2) + (tid & 31);

    const int NC = DD >> 5;
    uint4 ra[4], rb[4];
    const uint32_t aoff_t = (uint32_t)arow * 80u + (uint32_t)ak4 * 8u;
    const uint32_t boff_t = (uint32_t)(tid >> 5) * 272u + (uint32_t)(tid & 31) * 8u;

    #pragma unroll
    for (int p = 0; p < 4; p++) {
        ra[p] = pa[(size_t)(32*p) * K4];
        rb[p] = pb[(size_t)(8*p) * N4];
    }
    #pragma unroll
    for (int p = 0; p < 4; p++) {
        uint32_t ao = aoff_t + (uint32_t)(32*p) * 80u;
        *(uint2*)(sm + ao)         = make_uint2(ra[p].x, ra[p].y);
        *(uint2*)(sm + 10240 + ao) = make_uint2(ra[p].z, ra[p].w);
        uint32_t bo = boff_t + (uint32_t)(8*p) * 272u;
        *(uint2*)(sm + BOFF + bo)       = make_uint2(rb[p].x, rb[p].y);
        *(uint2*)(sm + BOFF + BHI + bo) = make_uint2(rb[p].z, rb[p].w);
    }
    __syncthreads();

    for (int kc = 0; kc < NC; kc++) {
        if (kc + 1 < NC) {
            const int kg = (kc + 1) * 8;
            #pragma unroll
            for (int p = 0; p < 4; p++) {
                ra[p] = pa[(size_t)(32*p) * K4 + kg];
                rb[p] = pb[((size_t)(8*p) + (size_t)(kc+1)*32) * N4];
            }
        }

        const uint32_t cb = sbase + (uint32_t)(kc & 1) * BUFSZ;
        #pragma unroll
        for (int ks = 0; ks < 2; ks++) {
            uint32_t ah[2][4], al[2][4], bh[8][2], bl[8][2];
            #pragma unroll
            for (int mt = 0; mt < 2; mt++) {
                uint32_t addr = cb + (uint32_t)(wm*32 + mt*16 + (lane & 15)) * 80u
                              + (uint32_t)(ks*32) + ((lane >> 4) << 4);
                ldsm_x4(ah[mt][0], ah[mt][1], ah[mt][2], ah[mt][3], addr);
                ldsm_x4(al[mt][0], al[mt][1], al[mt][2], al[mt][3], addr + 10240);
            }
            #pragma unroll
            for (int ntp = 0; ntp < 4; ntp++) {
                uint32_t r0, r1, r2, r3;
                uint32_t addr = cb + BOFF
                              + (uint32_t)(ks*16 + (lane & 15)) * 272u
                              + (uint32_t)(wn*64 + ntp*16) * 2u + ((lane >> 4) << 4);
                ldsm_x4_t(r0, r1, r2, r3, addr);
                bh[2*ntp][0] = r0; bh[2*ntp][1] = r1;
                bh[2*ntp+1][0] = r2; bh[2*ntp+1][1] = r3;
                ldsm_x4_t(r0, r1, r2, r3, addr + BHI);
                bl[2*ntp][0] = r0; bl[2*ntp][1] = r1;
                bl[2*ntp+1][0] = r2; bl[2*ntp+1][1] = r3;
            }
            #pragma unroll
            for (int mt = 0; mt < 2; mt++)
                #pragma unroll
                for (int nt = 0; nt < 8; nt++) {
                    mma16816(acc[mt][nt], ah[mt], bh[nt]);
                    mma16816(acc[mt][nt], ah[mt], bl[nt]);
                    mma16816(acc[mt][nt], al[mt], bh[nt]);
                }
        }

        if (kc + 1 < NC) {
            unsigned char* nb = sm + (uint32_t)((kc + 1) & 1) * BUFSZ;
            #pragma unroll
            for (int p = 0; p < 4; p++) {
                uint32_t ao = aoff_t + (uint32_t)(32*p) * 80u;
                *(uint2*)(nb + ao)         = make_uint2(ra[p].x, ra[p].y);
                *(uint2*)(nb + 10240 + ao) = make_uint2(ra[p].z, ra[p].w);
                uint32_t bo = boff_t + (uint32_t)(8*p) * 272u;
                *(uint2*)(nb + BOFF + bo)       = make_uint2(rb[p].x, rb[p].y);
                *(uint2*)(nb + BOFF + BHI + bo) = make_uint2(rb[p].z, rb[p].w);
            }
            __syncthreads();
        }
    }

    const int mrow = m0 + wm*32;
    #pragma unroll
    for (int mt = 0; mt < 2; mt++) {
        #pragma unroll
        for (int nt = 0; nt < 8; nt++) {
            int col = n0 + wn*64 + nt*8 + tig*2;
            float b0v = bias[col], b1v = bias[col+1];
            #pragma unroll
            for (int hh = 0; hh < 2; hh++) {
                int row = mrow + mt*16 + grp + hh*8;
                float v0 = acc[mt][nt][2*hh+0] + b0v;
                float v1 = acc[mt][nt][2*hh+1] + b1v;
                float x2 = __shfl_down_sync(0xffffffffu, v0, 1);
                float x3 = __shfl_down_sync(0xffffffffu, v1, 1);
                if ((tig & 1) == 0) {
                    uint2 hi, lo;
                    split4(make_float4(v0, v1, x2, x3), hi, lo);
                    size_t idx = (size_t)row * 576 + (size_t)(sel*192) + (col >> 2);
                    Chi[idx] = hi;
                    Clo[idx] = lo;
                }
            }
        }
    }
}

// ============ flash attention: cp.async double-buffered K/V ============
#define FKH 0
#define FKL 9216
#define FVH 18432
#define FVL 27648
#define FAM 36864
#define FBUF 37120

__global__ void __launch_bounds__(128, 1)
flash_kernel(const uint2* __restrict__ qhi, const uint2* __restrict__ qlo,
             const float* __restrict__ amask, uint4* __restrict__ outs)
{
    extern __shared__ __align__(16) unsigned char sm[];
    const uint32_t sbase = smem_u32(sm);
    const int tid = threadIdx.x, lane = tid & 31, w = tid >> 5;
    const int grp = lane >> 2, tig = lane & 3;
    const int qt = (int)gridDim.x - 1 - (int)blockIdx.x;
    const int bh = blockIdx.y, b = bh / HH, h = bh % HH;
    const int q0 = qt * 64;

    // Q fragments from hi/lo planes
    uint32_t qh[4][4], ql[4][4];
    #pragma unroll
    for (int ks = 0; ks < 4; ks++)
        #pragma unroll
        for (int j = 0; j < 4; j++) {
            int row = q0 + w*16 + grp + (j & 1) * 8;
            int col = h*64 + ks*16 + (j >> 1) * 8 + tig*2;
            size_t gi = (size_t)(b*SS + row) * 576 + (col >> 2);
            uint2 gh = qhi[gi], gl = qlo[gi];
            qh[ks][j] = ((col & 3) == 0) ? gh.x : gh.y;
            ql[ks][j] = ((col & 3) == 0) ? gl.x : gl.y;
        }

    float o[8][4];
    #pragma unroll
    for (int i = 0; i < 8; i++)
        #pragma unroll
        for (int j = 0; j < 4; j++) o[i][j] = 0.f;
    float mrow0 = -1e30f, mrow1 = -1e30f, lrow0 = 0.f, lrow1 = 0.f;
    const int qr0 = q0 + w*16 + grp, qr1 = qr0 + 8;

    // issue K/V/mask tile kt into buffer at base bb (one commit group)
    auto issue_tile = [&](int kt, uint32_t bb) {
        const size_t rowbase = (size_t)(b*SS + kt*64) * 576 + 192 + h*16;
        #pragma unroll
        for (int it = 0; it < 4; it++) {
            int idx = tid + it*128;           // 0..511
            int r = idx >> 3, c = idx & 7;    // row, 16B chunk
            size_t go = rowbase + (size_t)r*576 + c*2;
            uint32_t so = (uint32_t)r*144u + (uint32_t)c*16u;
            cp16(bb + FKH + so, qhi + go);
            cp16(bb + FKL + so, qlo + go);
            cp16(bb + FVH + so, qhi + go + 192);
            cp16(bb + FVL + so, qlo + go + 192);
        }
        if (tid < 16) cp16(bb + FAM + tid*16, amask + b*SS + kt*64 + tid*4);
    };

    issue_tile(0, sbase);
    CP_COMMIT();

    for (int kt = 0; kt <= qt; kt++) {
        if (kt < qt) {
            issue_tile(kt + 1, sbase + (uint32_t)((kt + 1) & 1) * FBUF);
            CP_COMMIT();
            CP_WAIT1();
        } else {
            CP_WAIT0();
        }
        __syncthreads();
        const uint32_t cbuf = sbase + (uint32_t)(kt & 1) * FBUF;

        float s[8][4];
        #pragma unroll
        for (int i = 0; i < 8; i++)
            #pragma unroll
            for (int j = 0; j < 4; j++) s[i][j] = 0.f;
        #pragma unroll
        for (int ks = 0; ks < 4; ks++) {
            uint32_t kh_[8][2], kl_[8][2];
            #pragma unroll
            for (int ntp = 0; ntp < 4; ntp++) {
                uint32_t r0, r1, r2, r3;
                uint32_t addr = cbuf + FKH + (uint32_t)(ntp*16 + (lane & 15)) * 144u
                              + (uint32_t)(ks*32) + ((lane >> 4) << 4);
                ldsm_x4(r0, r1, r2, r3, addr);
                kh_[2*ntp][0] = r0; kh_[2*ntp][1] = r2;
                kh_[2*ntp+1][0] = r1; kh_[2*ntp+1][1] = r3;
                ldsm_x4(r0, r1, r2, r3, addr + (FKL - FKH));
                kl_[2*ntp][0] = r0; kl_[2*ntp][1] = r2;
                kl_[2*ntp+1][0] = r1; kl_[2*ntp+1][1] = r3;
            }
            #pragma unroll
            for (int nt = 0; nt < 8; nt++) {
                mma16816(s[nt], qh[ks], kh_[nt]);
                mma16816(s[nt], qh[ks], kl_[nt]);
                mma16816(s[nt], ql[ks], kh_[nt]);
            }
        }
        const float* am = (const float*)(sm + (size_t)(kt & 1) * FBUF + FAM);
        #pragma unroll
        for (int nt = 0; nt < 8; nt++) {
            int c0 = nt*8 + tig*2;
            int kc0 = kt*64 + c0, kc1 = kc0 + 1;
            float a0 = am[c0], a1 = am[c0+1];
            s[nt][0] = (kc0 <= qr0 && a0 != 0.f) ? s[nt][0]*0.125f : -1e30f;
            s[nt][1] = (kc1 <= qr0 && a1 != 0.f) ? s[nt][1]*0.125f : -1e30f;
            s[nt][2] = (kc0 <= qr1 && a0 != 0.f) ? s[nt][2]*0.125f : -1e30f;
            s[nt][3] = (kc1 <= qr1 && a1 != 0.f) ? s[nt][3]*0.125f : -1e30f;
        }
        float mx0 = -1e30f, mx1 = -1e30f;
        #pragma unroll
        for (int nt = 0; nt < 8; nt++) {
            mx0 = fmaxf(mx0, fmaxf(s[nt][0], s[nt][1]));
            mx1 = fmaxf(mx1, fmaxf(s[nt][2], s[nt][3]));
        }
        mx0 = fmaxf(mx0, __shfl_xor_sync(0xffffffffu, mx0, 1));
        mx0 = fmaxf(mx0, __shfl_xor_sync(0xffffffffu, mx0, 2));
        mx1 = fmaxf(mx1, __shfl_xor_sync(0xffffffffu, mx1, 1));
        mx1 = fmaxf(mx1, __shfl_xor_sync(0xffffffffu, mx1, 2));
        float mn0 = fmaxf(mrow0, mx0), mn1 = fmaxf(mrow1, mx1);
        float sc0 = __expf(mrow0 - mn0), sc1 = __expf(mrow1 - mn1);
        mrow0 = mn0; mrow1 = mn1;
        float rs0 = 0.f, rs1 = 0.f;
        #pragma unroll
        for (int nt = 0; nt < 8; nt++) {
            s[nt][0] = __expf(s[nt][0] - mn0); rs0 += s[nt][0];
            s[nt][1] = __expf(s[nt][1] - mn0); rs0 += s[nt][1];
            s[nt][2] = __expf(s[nt][2] - mn1); rs1 += s[nt][2];
            s[nt][3] = __expf(s[nt][3] - mn1); rs1 += s[nt][3];
        }
        rs0 += __shfl_xor_sync(0xffffffffu, rs0, 1);
        rs0 += __shfl_xor_sync(0xffffffffu, rs0, 2);
        rs1 += __shfl_xor_sync(0xffffffffu, rs1, 1);
        rs1 += __shfl_xor_sync(0xffffffffu, rs1, 2);
        lrow0 = lrow0*sc0 + rs0; lrow1 = lrow1*sc1 + rs1;
        #pragma unroll
        for (int nt = 0; nt < 8; nt++) {
            o[nt][0] *= sc0; o[nt][1] *= sc0;
            o[nt][2] *= sc1; o[nt][3] *= sc1;
        }
        #pragma unroll
        for (int ks = 0; ks < 4; ks++) {
            uint32_t pah[4], pal[4];
            split2(s[2*ks][0],   s[2*ks][1],   pah[0], pal[0]);
            split2(s[2*ks][2],   s[2*ks][3],   pah[1], pal[1]);
            split2(s[2*ks+1][0], s[2*ks+1][1], pah[2], pal[2]);
            split2(s[2*ks+1][2], s[2*ks+1][3], pah[3], pal[3]);
            uint32_t vh_[8][2], vl_[8][2];
            #pragma unroll
            for (int ntp = 0; ntp < 4; ntp++) {
                uint32_t r0, r1, r2, r3;
                uint32_t addr = cbuf + FVH + (uint32_t)(ks*16 + (lane & 15)) * 144u
                              + (uint32_t)(ntp*32) + ((lane >> 4) << 4);
                ldsm_x4_t(r0, r1, r2, r3, addr);
                vh_[2*ntp][0] = r0; vh_[2*ntp][1] = r1;
                vh_[2*ntp+1][0] = r2; vh_[2*ntp+1][1] = r3;
                ldsm_x4_t(r0, r1, r2, r3, addr + (FVL - FVH));
                vl_[2*ntp][0] = r0; vl_[2*ntp][1] = r1;
                vl_[2*ntp+1][0] = r2; vl_[2*ntp+1][1] = r3;
            }
            #pragma unroll
            for (int nt = 0; nt < 8; nt++) {
                mma16816(o[nt], pah, vh_[nt]);
                mma16816(o[nt], pah, vl_[nt]);
                mma16816(o[nt], pal, vh_[nt]);
            }
        }
        __syncthreads();
    }
    float inv0 = 1.f / lrow0, inv1 = 1.f / lrow1;
    #pragma unroll
    for (int nt = 0; nt < 8; nt++) {
        int col = h*64 + nt*8 + tig*2;
        float v0 = o[nt][0]*inv0, v1 = o[nt][1]*inv0;
        float u0 = o[nt][2]*inv1, u1 = o[nt][3]*inv1;
        float x2 = __shfl_down_sync(0xffffffffu, v0, 1);
        float x3 = __shfl_down_sync(0xffffffffu, v1, 1);
        float y2 = __shfl_down_sync(0xffffffffu, u0, 1);
        float y3 = __shfl_down_sync(0xffffffffu, u1, 1);
        if ((tig & 1) == 0) {
            uint2 hi, lo;
            split4(make_float4(v0, v1, x2, x3), hi, lo);
            outs[(size_t)(b*SS + qr0) * 192 + (col >> 2)] = make_uint4(hi.x, hi.y, lo.x, lo.y);
            split4(make_float4(u0, u1, y2, y3), hi, lo);
            outs[(size_t)(b*SS + qr1) * 192 + (col >> 2)] = make_uint4(hi.x, hi.y, lo.x, lo.y);
        }
    }
}

// ---------------- position ids (parallel block scan) ----------------
__global__ void posids_kernel(const float* __restrict__ amask, int* __restrict__ pos) {
    __shared__ float ws[32];
    int b = blockIdx.x, t = threadIdx.x;   // 1024 threads
    float m = amask[b*SS + t];
    float v = m;
    #pragma unroll
    for (int o = 1; o < 32; o <<= 1) {
        float u = __shfl_up_sync(0xffffffffu, v, o);
        if ((t & 31) >= o) v += u;
    }
    if ((t & 31) == 31) ws[t >> 5] = v;
    __syncthreads();
    if (t < 32) {
        float w2 = ws[t];
        #pragma unroll
        for (int o = 1; o < 32; o <<= 1) {
            float u = __shfl_up_sync(0xffffffffu, w2, o);
            if (t >= o) w2 += u;
        }
        ws[t] = w2;
    }
    __syncthreads();
    float total = v + ((t >> 5) ? ws[(t >> 5) - 1] : 0.f);
    pos[b*SS + t] = (m == 0.f) ? 0 : (int)(total - 1.f);
}

// ---------------- embedding ----------------
__global__ void embed_kernel(const int* __restrict__ ids, const int* __restrict__ pos,
                             const float* __restrict__ tok, const float* __restrict__ pemb,
                             float* __restrict__ x) {
    int row = blockIdx.x;
    int id = ids[row];
    int p  = pos[row];
    int tid = threadIdx.x;
    #pragma unroll
    for (int t = 0; t < 3; t++) {
        int d = tid + t*256;
        x[(size_t)row*DD + d] = tok[(size_t)id*DD + d] + pemb[(size_t)p*DD + d];
    }
}

// ---------------- layernorm -> split output (192 threads) ----------------
__global__ void ln_split_kernel(const float* __restrict__ x, const float* __restrict__ g,
                                const float* __restrict__ b, uint4* __restrict__ ys) {
    __shared__ float pr[6];
    int row = blockIdx.x, tid = threadIdx.x;   // 192 threads
    float4 v = ((const float4*)(x + (size_t)row*DD))[tid];
    float s = v.x + v.y + v.z + v.w;
    #pragma unroll
    for (int o = 16; o; o >>= 1) s += __shfl_xor_sync(0xffffffffu, s, o);
    if ((tid & 31) == 0) pr[tid >> 5] = s;
    __syncthreads();
    float mu = (pr[0]+pr[1]+pr[2]+pr[3]+pr[4]+pr[5]) * (1.f/DD);
    float dx = v.x-mu, dy = v.y-mu, dz = v.z-mu, dw = v.w-mu;
    float s2 = dx*dx + dy*dy + dz*dz + dw*dw;
    #pragma unroll
    for (int o = 16; o; o >>= 1) s2 += __shfl_xor_sync(0xffffffffu, s2, o);
    __syncthreads();
    if ((tid & 31) == 0) pr[tid >> 5] = s2;
    __syncthreads();
    float rstd = rsqrtf((pr[0]+pr[1]+pr[2]+pr[3]+pr[4]+pr[5]) * (1.f/DD) + 1e-5f);
    float4 gg = ((const float4*)g)[tid], bb = ((const float4*)b)[tid];
    float4 y = make_float4(dx*rstd*gg.x + bb.x, dy*rstd*gg.y + bb.y,
                           dz*rstd*gg.z + bb.z, dw*rstd*gg.w + bb.w);
    uint2 hi, lo; split4(y, hi, lo);
    ys[(size_t)row*192 + tid] = make_uint4(hi.x, hi.y, lo.x, lo.y);
}

// ---------------- launch ----------------
extern "C" void kernel_launch(void* const* d_in, const int* in_sizes, int n_in,
                              void* d_out, int out_size) {
    const int*   ids   = (const int*)  d_in[0];
    const float* amask = (const float*)d_in[1];
    const float* tok   = (const float*)d_in[2];
    const float* pemb  = (const float*)d_in[3];
    const float* ln1g  = (const float*)d_in[4];
    const float* ln1b  = (const float*)d_in[5];
    const float* Wq    = (const float*)d_in[6];
    const float* bq    = (const float*)d_in[7];
    const float* Wk    = (const float*)d_in[8];
    const float* bk    = (const float*)d_in[9];
    const float* Wv    = (const float*)d_in[10];
    const float* bv    = (const float*)d_in[11];
    const float* Wp    = (const float*)d_in[12];
    const float* bp    = (const float*)d_in[13];
    const float* ln2g  = (const float*)d_in[14];
    const float* ln2b  = (const float*)d_in[15];
    const float* W1    = (const float*)d_in[16];
    const float* b1    = (const float*)d_in[17];
    const float* W2    = (const float*)d_in[18];
    const float* b2    = (const float*)d_in[19];
    const float* lnfg  = (const float*)d_in[20];
    const float* lnfb  = (const float*)d_in[21];
    float* out = (float*)d_out;

    float *xp, *partp; int* pidp;
    uint2 *qhi, *qlo;
    uint4 *hs, *as, *fs, *wqs, *wks, *wvs, *wps, *w1s, *w2s, *toks;
    cudaGetSymbolAddress((void**)&xp,   g_x);
    cudaGetSymbolAddress((void**)&partp, g_mlp2p);
    cudaGetSymbolAddress((void**)&pidp, g_pos);
    cudaGetSymbolAddress((void**)&hs,   g_h_s);
    cudaGetSymbolAddress((void**)&qhi,  g_qkv_hi);
    cudaGetSymbolAddress((void**)&qlo,  g_qkv_lo);
    cudaGetSymbolAddress((void**)&as,   g_attn_s);
    cudaGetSymbolAddress((void**)&fs,   g_ff_s);
    cudaGetSymbolAddress((void**)&wqs,  g_wq_s);
    cudaGetSymbolAddress((void**)&wks,  g_wk_s);
    cudaGetSymbolAddress((void**)&wvs,  g_wv_s);
    cudaGetSymbolAddress((void**)&wps,  g_wp_s);
    cudaGetSymbolAddress((void**)&w1s,  g_w1_s);
    cudaGetSymbolAddress((void**)&w2s,  g_w2_s);
    cudaGetSymbolAddress((void**)&toks, g_tok_s);

    const int SM_T0 = 2*(20480 + 2*8704);   // 75776
    const int SM_T1 = 2*(20480 + 2*10240);  // 81920
    const int SM_FA = 2*FBUF;               // 74240
    cudaFuncSetAttribute(mma_gemm<0,0>, cudaFuncAttributeMaxDynamicSharedMemorySize, SM_T0);
    cudaFuncSetAttribute(mma_gemm<0,1>, cudaFuncAttributeMaxDynamicSharedMemorySize, SM_T0);
    cudaFuncSetAttribute(mma_gemm<1,0>, cudaFuncAttributeMaxDynamicSharedMemorySize, SM_T1);
    cudaFuncSetAttribute(qkv_gemm, cudaFuncAttributeMaxDynamicSharedMemorySize, SM_T0);
    cudaFuncSetAttribute(flash_kernel, cudaFuncAttributeMaxDynamicSharedMemorySize, SM_FA);

    const int nW  = LL*DD*DD/4;
    const int nW1 = LL*DD*FF/4;
    const int nT  = VV*DD/4;
    split_kernel<<<(nW +255)/256, 256>>>((const float4*)Wq, wqs, nW);
    split_kernel<<<(nW +255)/256, 256>>>((const float4*)Wk, wks, nW);
    split_kernel<<<(nW +255)/256, 256>>>((const float4*)Wv, wvs, nW);
    split_kernel<<<(nW +255)/256, 256>>>((const float4*)Wp, wps, nW);
    split_kernel<<<(nW1+255)/256, 256>>>((const float4*)W1, w1s, nW1);
    split_kernel<<<(nW1+255)/256, 256>>>((const float4*)W2, w2s, nW1);
    split_kernel<<<(nT +255)/256, 256>>>((const float4*)tok, toks, nT);

    posids_kernel<<<BB, 1024>>>(amask, pidp);
    embed_kernel<<<MM, 256>>>(ids, pidp, tok, pemb, xp);

    dim3 gQKV(18, MM/128);             // 18 x 16
    dim3 gF(FF/128, MM/128);           // 24 x 16
    dim3 gP(DD/128, MM/128, 3);        // proj split-K
    dim3 gM2(DD/128, MM/128, 3);       // mlp2 split-K
    dim3 gV(MM/128, (VV+127)/128);     // m fastest
    dim3 gFA(SS/64, BB*HH);

    ln_split_kernel<<<MM, 192>>>(xp, ln1g, ln1b, hs);

    for (int l = 0; l < LL; l++) {
        const uint4* wql = wqs + (size_t)l*(DD*DD/4);
        const uint4* wkl = wks + (size_t)l*(DD*DD/4);
        const uint4* wvl = wvs + (size_t)l*(DD*DD/4);
        const uint4* wpl = wps + (size_t)l*(DD*DD/4);
        const uint4* w1l = w1s + (size_t)l*(DD*FF/4);
        const uint4* w2l = w2s + (size_t)l*(DD*FF/4);

        qkv_gemm<<<gQKV, 256, SM_T0>>>(hs, wql, wkl, wvl, bq + l*DD, bk + l*DD, bv + l*DD,
                                       qhi, qlo);
        flash_kernel<<<gFA, 128, SM_FA>>>(qhi, qlo, amask, as);
        mma_gemm<0,0><<<gP, 256, SM_T0>>>(as, wpl, nullptr, nullptr, partp, nullptr,
                                          MM, DD, DD/3, 0, DD/4);
        reduce_ln_kernel<<<MM, 192>>>((const float4*)partp, bp + l*DD, (float4*)xp,
                                      ln2g + l*DD, ln2b + l*DD, hs);
        mma_gemm<0,1><<<gF, 256, SM_T0>>>(hs, w1l, b1 + l*FF, nullptr, nullptr, fs,
                                          MM, FF, DD, 1, DD/4);
        mma_gemm<0,0><<<gM2, 256, SM_T0>>>(fs, w2l, nullptr, nullptr, partp, nullptr,
                                           MM, DD, FF/3, 0, FF/4);
        const float* ng = (l + 1 < LL) ? (ln1g + (l+1)*DD) : lnfg;
        const float* nb = (l + 1 < LL) ? (ln1b + (l+1)*DD) : lnfb;
        reduce_ln_kernel<<<MM, 192>>>((const float4*)partp, b2 + l*DD, (float4*)xp,
                                      ng, nb, hs);
    }

    mma_gemm<1,0><<<gV, 256, SM_T1>>>(hs, toks, nullptr, nullptr, out, nullptr,
                                      MM, VV, DD, 0, DD/4);
}

// round 16
// speedup vs baseline: 1.6186x; 1.0040x over previous
#include <cuda_runtime.h>
#include <cuda_bf16.h>
#include <math.h>
#include <stdint.h>

#define BB 2
#define SS 1024
#define DD 768
#define HH 12
#define HDD 64
#define LL 12
#define VV 50257
#define FF 3072
#define MM (BB*SS)   // 2048

// ---------------- scratch (allocation-free) ----------------
__device__ float g_x[MM*DD];
__device__ int   g_pos[BB*SS];
__device__ uint4 g_h_s[MM*DD/4];
__device__ uint2 g_qkv_hi[MM*576];
__device__ uint2 g_qkv_lo[MM*576];
__device__ uint4 g_attn_s[MM*DD/4];
__device__ uint4 g_ff_s[MM*FF/4];
__device__ float g_mlp2p[3*MM*DD];
__device__ uint4 g_wq_s[LL*DD*DD/4];
__device__ uint4 g_wk_s[LL*DD*DD/4];
__device__ uint4 g_wv_s[LL*DD*DD/4];
__device__ uint4 g_wp_s[LL*DD*DD/4];
__device__ uint4 g_w1_s[LL*DD*FF/4];
__device__ uint4 g_w2_s[LL*DD*FF/4];
__device__ uint4 g_tok_s[(size_t)VV*DD/4];

// ================= helpers =================
__device__ __forceinline__ uint32_t smem_u32(const void* p) {
    uint32_t a;
    asm("{ .reg .u64 t; cvta.to.shared.u64 t, %1; cvt.u32.u64 %0, t; }" : "=r"(a) : "l"(p));
    return a;
}
__device__ __forceinline__ void ldsm_x4(uint32_t& r0, uint32_t& r1, uint32_t& r2, uint32_t& r3,
                                        uint32_t addr) {
    asm volatile("ldmatrix.sync.aligned.m8n8.x4.shared.b16 {%0,%1,%2,%3}, [%4];"
                 : "=r"(r0), "=r"(r1), "=r"(r2), "=r"(r3) : "r"(addr));
}
__device__ __forceinline__ void ldsm_x4_t(uint32_t& r0, uint32_t& r1, uint32_t& r2, uint32_t& r3,
                                          uint32_t addr) {
    asm volatile("ldmatrix.sync.aligned.m8n8.x4.trans.shared.b16 {%0,%1,%2,%3}, [%4];"
                 : "=r"(r0), "=r"(r1), "=r"(r2), "=r"(r3) : "r"(addr));
}
__device__ __forceinline__ void mma16816(float* c, const uint32_t* a, const uint32_t* b) {
    asm volatile("mma.sync.aligned.m16n8k16.row.col.f32.bf16.bf16.f32 "
                 "{%0,%1,%2,%3}, {%4,%5,%6,%7}, {%8,%9}, {%0,%1,%2,%3};"
                 : "+f"(c[0]), "+f"(c[1]), "+f"(c[2]), "+f"(c[3])
                 : "r"(a[0]), "r"(a[1]), "r"(a[2]), "r"(a[3]), "r"(b[0]), "r"(b[1]));
}
__device__ __forceinline__ void cp16(uint32_t saddr, const void* gptr) {
    asm volatile("cp.async.cg.shared.global [%0], [%1], 16;" :: "r"(saddr), "l"(gptr));
}
#define CP_COMMIT() asm volatile("cp.async.commit_group;" ::: "memory")
#define CP_WAIT1()  asm volatile("cp.async.wait_group 1;" ::: "memory")
#define CP_WAIT0()  asm volatile("cp.async.wait_group 0;" ::: "memory")

__device__ __forceinline__ void split4(float4 v, uint2& hi, uint2& lo) {
    __nv_bfloat16 h0 = __float2bfloat16(v.x), h1 = __float2bfloat16(v.y);
    __nv_bfloat16 h2 = __float2bfloat16(v.z), h3 = __float2bfloat16(v.w);
    __nv_bfloat16 l0 = __float2bfloat16(v.x - __bfloat162float(h0));
    __nv_bfloat16 l1 = __float2bfloat16(v.y - __bfloat162float(h1));
    __nv_bfloat16 l2 = __float2bfloat16(v.z - __bfloat162float(h2));
    __nv_bfloat16 l3 = __float2bfloat16(v.w - __bfloat162float(h3));
    __nv_bfloat162 a = __nv_bfloat162(h0, h1), b = __nv_bfloat162(h2, h3);
    __nv_bfloat162 c = __nv_bfloat162(l0, l1), d = __nv_bfloat162(l2, l3);
    hi.x = *(uint32_t*)&a; hi.y = *(uint32_t*)&b;
    lo.x = *(uint32_t*)&c; lo.y = *(uint32_t*)&d;
}
__device__ __forceinline__ void split2(float a, float b, uint32_t& hi, uint32_t& lo) {
    __nv_bfloat16 h0 = __float2bfloat16(a), h1 = __float2bfloat16(b);
    __nv_bfloat16 l0 = __float2bfloat16(a - __bfloat162float(h0));
    __nv_bfloat16 l1 = __float2bfloat16(b - __bfloat162float(h1));
    __nv_bfloat162 H(h0, h1), L(l0, l1);
    hi = *(uint32_t*)&H; lo = *(uint32_t*)&L;
}
__device__ __forceinline__ float gelu_exact(float v) {
    return 0.5f * v * (1.0f + erff(v * 0.70710678118654752f));
}

// ---------------- fp32 -> split converter ----------------
__global__ void split_kernel(const float4* __restrict__ src, uint4* __restrict__ dst, int n) {
    int i = blockIdx.x*blockDim.x + threadIdx.x;
    if (i < n) {
        uint2 hi, lo;
        split4(src[i], hi, lo);
        dst[i] = make_uint4(hi.x, hi.y, lo.x, lo.y);
    }
}

// ---------------- common LN tail: v -> store x? -> hs ----------------
__device__ __forceinline__ void ln_tail(float4 v, int i, int tid,
                                        const float* __restrict__ g,
                                        const float* __restrict__ b,
                                        uint4* __restrict__ ys, float* pr) {
    float s = v.x + v.y + v.z + v.w;
    #pragma unroll
    for (int o = 16; o; o >>= 1) s += __shfl_xor_sync(0xffffffffu, s, o);
    if ((tid & 31) == 0) pr[tid >> 5] = s;
    __syncthreads();
    float mu = (pr[0]+pr[1]+pr[2]+pr[3]+pr[4]+pr[5]) * (1.f/DD);
    float dx = v.x-mu, dy = v.y-mu, dz = v.z-mu, dw = v.w-mu;
    float s2 = dx*dx + dy*dy + dz*dz + dw*dw;
    #pragma unroll
    for (int o = 16; o; o >>= 1) s2 += __shfl_xor_sync(0xffffffffu, s2, o);
    __syncthreads();
    if ((tid & 31) == 0) pr[tid >> 5] = s2;
    __syncthreads();
    float rstd = rsqrtf((pr[0]+pr[1]+pr[2]+pr[3]+pr[4]+pr[5]) * (1.f/DD) + 1e-5f);
    float4 gg = ((const float4*)g)[tid], bb = ((const float4*)b)[tid];
    float4 y = make_float4(dx*rstd*gg.x + bb.x, dy*rstd*gg.y + bb.y,
                           dz*rstd*gg.z + bb.z, dw*rstd*gg.w + bb.w);
    uint2 hi, lo; split4(y, hi, lo);
    ys[i] = make_uint4(hi.x, hi.y, lo.x, lo.y);
}

// ---------------- fused embed + layer0 ln1 (192 threads/row) ----------------
__global__ void embed_ln_kernel(const int* __restrict__ ids, const int* __restrict__ pos,
                                const float* __restrict__ tok, const float* __restrict__ pemb,
                                float* __restrict__ x, const float* __restrict__ g,
                                const float* __restrict__ b, uint4* __restrict__ ys) {
    __shared__ float pr[6];
    int row = blockIdx.x, tid = threadIdx.x;
    int id = ids[row], p = pos[row];
    float4 t4 = ((const float4*)(tok + (size_t)id*DD))[tid];
    float4 p4 = ((const float4*)(pemb + (size_t)p*DD))[tid];
    float4 v = make_float4(t4.x+p4.x, t4.y+p4.y, t4.z+p4.z, t4.w+p4.w);
    int i = row*192 + tid;
    ((float4*)x)[i] = v;
    ln_tail(v, i, tid, g, b, ys, pr);
}

// ---------------- fused split-K reduce + layernorm + split ----------------
__global__ void reduce_ln_kernel(const float4* __restrict__ part, const float* __restrict__ bias,
                                 float4* __restrict__ x, const float* __restrict__ g,
                                 const float* __restrict__ b, uint4* __restrict__ ys) {
    __shared__ float pr[6];
    const int S = MM*DD/4;
    int row = blockIdx.x, tid = threadIdx.x;
    int i = row*192 + tid;
    float4 p0 = part[i], p1 = part[i + S], p2 = part[i + 2*S];
    float4 bb4 = ((const float4*)bias)[tid];
    float4 v = x[i];
    v.x += p0.x + p1.x + p2.x + bb4.x;
    v.y += p0.y + p1.y + p2.y + bb4.y;
    v.z += p0.z + p1.z + p2.z + bb4.z;
    v.w += p0.w + p1.w + p2.w + bb4.w;
    x[i] = v;
    ln_tail(v, i, tid, g, b, ys, pr);
}

// ============ split-bf16 GEMM, pre-split inputs, double-buffered smem ============
template<int TRANSB, int OUTSPLIT>
__global__ void __launch_bounds__(256, 1)
mma_gemm(const uint4* __restrict__ As, const uint4* __restrict__ Bs,
         const float* __restrict__ bias, const float* __restrict__ res,
         float* __restrict__ C, uint4* __restrict__ Cs,
         int M, int N, int K, int act, int lda4)
{
    extern __shared__ __align__(16) unsigned char sm[];
    constexpr int BHI   = TRANSB ? 10240 : 8704;
    constexpr int BOFF  = 20480;
    constexpr int BUFSZ = BOFF + 2*BHI;
    const uint32_t sbase = smem_u32(sm);
    const int tid = threadIdx.x, lane = tid & 31, wid = tid >> 5;
    const int wm = wid & 3, wn = wid >> 2;
    const int m0 = (TRANSB ? blockIdx.x : blockIdx.y) << 7;
    const int n0 = (TRANSB ? blockIdx.y : blockIdx.x) << 7;
    const int grp = lane >> 2, tig = lane & 3;
    const int N4 = N >> 2;

    const int z = blockIdx.z;
    As += (size_t)z * (K >> 2);
    if (TRANSB) Bs += (size_t)z * (K >> 2);
    else        Bs += (size_t)z * K * N4;
    C  += (size_t)z * M * N;

    float acc[2][8][4];
    #pragma unroll
    for (int i = 0; i < 2; i++)
        #pragma unroll
        for (int j = 0; j < 8; j++)
            #pragma unroll
            for (int q = 0; q < 4; q++) acc[i][j][q] = 0.f;

    const int arow = tid >> 3, ak4 = tid & 7;
    const uint4* pa = As + (size_t)(m0 + arow) * lda4 + ak4;

    const uint4* pb;
    bool bpred[4];
    if (TRANSB) {
        #pragma unroll
        for (int p = 0; p < 4; p++) bpred[p] = (n0 + arow + 32*p) < N;
        pb = Bs + (size_t)(n0 + arow) * lda4 + ak4;
    } else {
        #pragma unroll
        for (int p = 0; p < 4; p++) bpred[p] = true;
        pb = Bs + (size_t)(tid >> 5) * N4 + (n0 >> 2) + (tid & 31);
    }

    const int NC = K >> 5;
    uint4 ra[4], rb[4];
    const uint4 z4 = make_uint4(0u, 0u, 0u, 0u);

    const uint32_t aoff_t = (uint32_t)arow * 80u + (uint32_t)ak4 * 8u;
    uint32_t boff_t;
    if (TRANSB) boff_t = aoff_t;
    else        boff_t = (uint32_t)(tid >> 5) * 272u + (uint32_t)(tid & 31) * 8u;

    #pragma unroll
    for (int p = 0; p < 4; p++) {
        ra[p] = pa[(size_t)(32*p) * lda4];
        if (TRANSB) rb[p] = bpred[p] ? pb[(size_t)(32*p) * lda4] : z4;
        else        rb[p] = pb[(size_t)(8*p) * N4];
    }
    #pragma unroll
    for (int p = 0; p < 4; p++) {
        uint32_t ao = aoff_t + (uint32_t)(32*p) * 80u;
        *(uint2*)(sm + ao)         = make_uint2(ra[p].x, ra[p].y);
        *(uint2*)(sm + 10240 + ao) = make_uint2(ra[p].z, ra[p].w);
        uint32_t bo = TRANSB ? (boff_t + (uint32_t)(32*p) * 80u)
                             : (boff_t + (uint32_t)(8*p) * 272u);
        *(uint2*)(sm + BOFF + bo)       = make_uint2(rb[p].x, rb[p].y);
        *(uint2*)(sm + BOFF + BHI + bo) = make_uint2(rb[p].z, rb[p].w);
    }
    __syncthreads();

    for (int kc = 0; kc < NC; kc++) {
        if (kc + 1 < NC) {
            const int kg = (kc + 1) * 8;
            #pragma unroll
            for (int p = 0; p < 4; p++) {
                ra[p] = pa[(size_t)(32*p) * lda4 + kg];
                if (TRANSB) rb[p] = bpred[p] ? pb[(size_t)(32*p) * lda4 + kg] : z4;
                else        rb[p] = pb[((size_t)(8*p) + (size_t)(kc+1)*32) * N4];
            }
        }

        const uint32_t cb = sbase + (uint32_t)(kc & 1) * BUFSZ;
        #pragma unroll
        for (int ks = 0; ks < 2; ks++) {
            uint32_t ah[2][4], al[2][4], bh[8][2], bl[8][2];
            #pragma unroll
            for (int mt = 0; mt < 2; mt++) {
                uint32_t addr = cb + (uint32_t)(wm*32 + mt*16 + (lane & 15)) * 80u
                              + (uint32_t)(ks*32) + ((lane >> 4) << 4);
                ldsm_x4(ah[mt][0], ah[mt][1], ah[mt][2], ah[mt][3], addr);
                ldsm_x4(al[mt][0], al[mt][1], al[mt][2], al[mt][3], addr + 10240);
            }
            #pragma unroll
            for (int ntp = 0; ntp < 4; ntp++) {
                uint32_t r0, r1, r2, r3;
                if (TRANSB) {
                    uint32_t addr = cb + BOFF
                                  + (uint32_t)(wn*64 + ntp*16 + (lane & 15)) * 80u
                                  + (uint32_t)(ks*32) + ((lane >> 4) << 4);
                    ldsm_x4(r0, r1, r2, r3, addr);
                    bh[2*ntp][0] = r0; bh[2*ntp+1][0] = r1;
                    bh[2*ntp][1] = r2; bh[2*ntp+1][1] = r3;
                    ldsm_x4(r0, r1, r2, r3, addr + BHI);
                    bl[2*ntp][0] = r0; bl[2*ntp+1][0] = r1;
                    bl[2*ntp][1] = r2; bl[2*ntp+1][1] = r3;
                } else {
                    uint32_t addr = cb + BOFF
                                  + (uint32_t)(ks*16 + (lane & 15)) * 272u
                                  + (uint32_t)(wn*64 + ntp*16) * 2u + ((lane >> 4) << 4);
                    ldsm_x4_t(r0, r1, r2, r3, addr);
                    bh[2*ntp][0] = r0; bh[2*ntp][1] = r1;
                    bh[2*ntp+1][0] = r2; bh[2*ntp+1][1] = r3;
                    ldsm_x4_t(r0, r1, r2, r3, addr + BHI);
                    bl[2*ntp][0] = r0; bl[2*ntp][1] = r1;
                    bl[2*ntp+1][0] = r2; bl[2*ntp+1][1] = r3;
                }
            }
            #pragma unroll
            for (int mt = 0; mt < 2; mt++)
                #pragma unroll
                for (int nt = 0; nt < 8; nt++) {
                    mma16816(acc[mt][nt], ah[mt], bh[nt]);
                    mma16816(acc[mt][nt], ah[mt], bl[nt]);
                    mma16816(acc[mt][nt], al[mt], bh[nt]);
                }
        }

        if (kc + 1 < NC) {
            unsigned char* nb = sm + (uint32_t)((kc + 1) & 1) * BUFSZ;
            #pragma unroll
            for (int p = 0; p < 4; p++) {
                uint32_t ao = aoff_t + (uint32_t)(32*p) * 80u;
                *(uint2*)(nb + ao)         = make_uint2(ra[p].x, ra[p].y);
                *(uint2*)(nb + 10240 + ao) = make_uint2(ra[p].z, ra[p].w);
                uint32_t bo = TRANSB ? (boff_t + (uint32_t)(32*p) * 80u)
                                     : (boff_t + (uint32_t)(8*p) * 272u);
                *(uint2*)(nb + BOFF + bo)       = make_uint2(rb[p].x, rb[p].y);
                *(uint2*)(nb + BOFF + BHI + bo) = make_uint2(rb[p].z, rb[p].w);
            }
            __syncthreads();
        }
    }

    const int mrow = m0 + wm*32;
    #pragma unroll
    for (int mt = 0; mt < 2; mt++) {
        #pragma unroll
        for (int nt = 0; nt < 8; nt++) {
            int col = n0 + wn*64 + nt*8 + tig*2;
            bool ok0 = (!TRANSB) || (col < N);
            bool ok1 = (!TRANSB) || (col + 1 < N);
            float b0v = 0.f, b1v = 0.f;
            if (bias) { if (ok0) b0v = bias[col]; if (ok1) b1v = bias[col+1]; }
            #pragma unroll
            for (int hh = 0; hh < 2; hh++) {
                int row = mrow + mt*16 + grp + hh*8;
                float v0 = acc[mt][nt][2*hh+0] + b0v;
                float v1 = acc[mt][nt][2*hh+1] + b1v;
                if (act) { v0 = gelu_exact(v0); v1 = gelu_exact(v1); }
                if (OUTSPLIT) {
                    float x2 = __shfl_down_sync(0xffffffffu, v0, 1);
                    float x3 = __shfl_down_sync(0xffffffffu, v1, 1);
                    if ((tig & 1) == 0) {
                        uint2 hi, lo;
                        split4(make_float4(v0, v1, x2, x3), hi, lo);
                        Cs[(size_t)row * (N >> 2) + (col >> 2)] = make_uint4(hi.x, hi.y, lo.x, lo.y);
                    }
                } else {
                    size_t base = (size_t)row * N + col;
                    if (res) { if (ok0) v0 += res[base]; if (ok1) v1 += res[base+1]; }
                    if (!TRANSB) {
                        float2 o; o.x = v0; o.y = v1;
                        *(float2*)(C + base) = o;
                    } else {
                        if (ok0) C[base] = v0;
                        if (ok1) C[base+1] = v1;
                    }
                }
            }
        }
    }
}

// ============ fused QKV GEMM: split in, hi/lo planes out ============
__global__ void __launch_bounds__(256, 1)
qkv_gemm(const uint4* __restrict__ As,
         const uint4* __restrict__ Wqs, const uint4* __restrict__ Wks, const uint4* __restrict__ Wvs,
         const float* __restrict__ bq_, const float* __restrict__ bk_, const float* __restrict__ bv_,
         uint2* __restrict__ Chi, uint2* __restrict__ Clo)
{
    extern __shared__ __align__(16) unsigned char sm[];
    constexpr int BHI   = 8704;
    constexpr int BOFF  = 20480;
    constexpr int BUFSZ = BOFF + 2*BHI;
    const int K4 = DD >> 2, N4 = DD >> 2;
    const uint32_t sbase = smem_u32(sm);
    const int tid = threadIdx.x, lane = tid & 31, wid = tid >> 5;
    const int wm = wid & 3, wn = wid >> 2;
    const int m0 = blockIdx.y << 7;
    const int sel = blockIdx.x / 6;
    const int n0 = (blockIdx.x % 6) << 7;
    const uint4* Bs   = (sel == 0) ? Wqs : (sel == 1) ? Wks : Wvs;
    const float* bias = (sel == 0) ? bq_ : (sel == 1) ? bk_ : bv_;
    const int grp = lane >> 2, tig = lane & 3;

    float acc[2][8][4];
    #pragma unroll
    for (int i = 0; i < 2; i++)
        #pragma unroll
        for (int j = 0; j < 8; j++)
            #pragma unroll
            for (int q = 0; q < 4; q++) acc[i][j][q] = 0.f;

    const int arow = tid >> 3, ak4 = tid & 7;
    const uint4* pa = As + (size_t)(m0 + arow) * K4 + ak4;
    const uint4* pb = Bs + (size_t)(tid >> 5) * N4 + (n0 >> 2) + (tid & 31);

    const int NC = DD >> 5;
    uint4 ra[4], rb[4];
    const uint32_t aoff_t = (uint32_t)arow * 80u + (uint32_t)ak4 * 8u;
    const uint32_t boff_t = (uint32_t)(tid >> 5) * 272u + (uint32_t)(tid & 31) * 8u;

    #pragma unroll
    for (int p = 0; p < 4; p++) {
        ra[p] = pa[(size_t)(32*p) * K4];
        rb[p] = pb[(size_t)(8*p) * N4];
    }
    #pragma unroll
    for (int p = 0; p < 4; p++) {
        uint32_t ao = aoff_t + (uint32_t)(32*p) * 80u;
        *(uint2*)(sm + ao)         = make_uint2(ra[p].x, ra[p].y);
        *(uint2*)(sm + 10240 + ao) = make_uint2(ra[p].z, ra[p].w);
        uint32_t bo = boff_t + (uint32_t)(8*p) * 272u;
        *(uint2*)(sm + BOFF + bo)       = make_uint2(rb[p].x, rb[p].y);
        *(uint2*)(sm + BOFF + BHI + bo) = make_uint2(rb[p].z, rb[p].w);
    }
    __syncthreads();

    for (int kc = 0; kc < NC; kc++) {
        if (kc + 1 < NC) {
            const int kg = (kc + 1) * 8;
            #pragma unroll
            for (int p = 0; p < 4; p++) {
                ra[p] = pa[(size_t)(32*p) * K4 + kg];
                rb[p] = pb[((size_t)(8*p) + (size_t)(kc+1)*32) * N4];
            }
        }

        const uint32_t cb = sbase + (uint32_t)(kc & 1) * BUFSZ;
        #pragma unroll
        for (int ks = 0; ks < 2; ks++) {
            uint32_t ah[2][4], al[2][4], bh[8][2], bl[8][2];
            #pragma unroll
            for (int mt = 0; mt < 2; mt++) {
                uint32_t addr = cb + (uint32_t)(wm*32 + mt*16 + (lane & 15)) * 80u
                              + (uint32_t)(ks*32) + ((lane >> 4) << 4);
                ldsm_x4(ah[mt][0], ah[mt][1], ah[mt][2], ah[mt][3], addr);
                ldsm_x4(al[mt][0], al[mt][1], al[mt][2], al[mt][3], addr + 10240);
            }
            #pragma unroll
            for (int ntp = 0; ntp < 4; ntp++) {
                uint32_t r0, r1, r2, r3;
                uint32_t addr = cb + BOFF
                              + (uint32_t)(ks*16 + (lane & 15)) * 272u
                              + (uint32_t)(wn*64 + ntp*16) * 2u + ((lane >> 4) << 4);
                ldsm_x4_t(r0, r1, r2, r3, addr);
                bh[2*ntp][0] = r0; bh[2*ntp][1] = r1;
                bh[2*ntp+1][0] = r2; bh[2*ntp+1][1] = r3;
                ldsm_x4_t(r0, r1, r2, r3, addr + BHI);
                bl[2*ntp][0] = r0; bl[2*ntp][1] = r1;
                bl[2*ntp+1][0] = r2; bl[2*ntp+1][1] = r3;
            }
            #pragma unroll
            for (int mt = 0; mt < 2; mt++)
                #pragma unroll
                for (int nt = 0; nt < 8; nt++) {
                    mma16816(acc[mt][nt], ah[mt], bh[nt]);
                    mma16816(acc[mt][nt], ah[mt], bl[nt]);
                    mma16816(acc[mt][nt], al[mt], bh[nt]);
                }
        }

        if (kc + 1 < NC) {
            unsigned char* nb = sm + (uint32_t)((kc + 1) & 1) * BUFSZ;
            #pragma unroll
            for (int p = 0; p < 4; p++) {
                uint32_t ao = aoff_t + (uint32_t)(32*p) * 80u;
                *(uint2*)(nb + ao)         = make_uint2(ra[p].x, ra[p].y);
                *(uint2*)(nb + 10240 + ao) = make_uint2(ra[p].z, ra[p].w);
                uint32_t bo = boff_t + (uint32_t)(8*p) * 272u;
                *(uint2*)(nb + BOFF + bo)       = make_uint2(rb[p].x, rb[p].y);
                *(uint2*)(nb + BOFF + BHI + bo) = make_uint2(rb[p].z, rb[p].w);
            }
            __syncthreads();
        }
    }

    const int mrow = m0 + wm*32;
    #pragma unroll
    for (int mt = 0; mt < 2; mt++) {
        #pragma unroll
        for (int nt = 0; nt < 8; nt++) {
            int col = n0 + wn*64 + nt*8 + tig*2;
            float b0v = bias[col], b1v = bias[col+1];
            #pragma unroll
            for (int hh = 0; hh < 2; hh++) {
                int row = mrow + mt*16 + grp + hh*8;
                float v0 = acc[mt][nt][2*hh+0] + b0v;
                float v1 = acc[mt][nt][2*hh+1] + b1v;
                float x2 = __shfl_down_sync(0xffffffffu, v0, 1);
                float x3 = __shfl_down_sync(0xffffffffu, v1, 1);
                if ((tig & 1) == 0) {
                    uint2 hi, lo;
                    split4(make_float4(v0, v1, x2, x3), hi, lo);
                    size_t idx = (size_t)row * 576 + (size_t)(sel*192) + (col >> 2);
                    Chi[idx] = hi;
                    Clo[idx] = lo;
                }
            }
        }
    }
}

// ============ flash attention: cp.async 3-buffer ring ============
#define FKH 0
#define FKL 9216
#define FVH 18432
#define FVL 27648
#define FAM 36864
#define FBUF 37120

__global__ void __launch_bounds__(128, 1)
flash_kernel(const uint2* __restrict__ qhi, const uint2* __restrict__ qlo,
             const float* __restrict__ amask, uint4* __restrict__ outs)
{
    extern __shared__ __align__(16) unsigned char sm[];
    const uint32_t sbase = smem_u32(sm);
    const int tid = threadIdx.x, lane = tid & 31, w = tid >> 5;
    const int grp = lane >> 2, tig = lane & 3;
    const int qt = (int)gridDim.x - 1 - (int)blockIdx.x;
    const int bh = blockIdx.y, b = bh / HH, h = bh % HH;
    const int q0 = qt * 64;

    uint32_t qh[4][4], ql[4][4];
    #pragma unroll
    for (int ks = 0; ks < 4; ks++)
        #pragma unroll
        for (int j = 0; j < 4; j++) {
            int row = q0 + w*16 + grp + (j & 1) * 8;
            int col = h*64 + ks*16 + (j >> 1) * 8 + tig*2;
            size_t gi = (size_t)(b*SS + row) * 576 + (col >> 2);
            uint2 gh = qhi[gi], gl = qlo[gi];
            qh[ks][j] = ((col & 3) == 0) ? gh.x : gh.y;
            ql[ks][j] = ((col & 3) == 0) ? gl.x : gl.y;
        }

    float o[8][4];
    #pragma unroll
    for (int i = 0; i < 8; i++)
        #pragma unroll
        for (int j = 0; j < 4; j++) o[i][j] = 0.f;
    float mrow0 = -1e30f, mrow1 = -1e30f, lrow0 = 0.f, lrow1 = 0.f;
    const int qr0 = q0 + w*16 + grp, qr1 = qr0 + 8;

    auto issue_tile = [&](int kt, uint32_t bb) {
        const size_t rowbase = (size_t)(b*SS + kt*64) * 576 + 192 + h*16;
        #pragma unroll
        for (int it = 0; it < 4; it++) {
            int idx = tid + it*128;
            int r = idx >> 3, c = idx & 7;
            size_t go = rowbase + (size_t)r*576 + c*2;
            uint32_t so = (uint32_t)r*144u + (uint32_t)c*16u;
            cp16(bb + FKH + so, qhi + go);
            cp16(bb + FKL + so, qlo + go);
            cp16(bb + FVH + so, qhi + go + 192);
            cp16(bb + FVL + so, qlo + go + 192);
        }
        if (tid < 16) cp16(bb + FAM + tid*16, amask + b*SS + kt*64 + tid*4);
    };

    issue_tile(0, sbase);
    CP_COMMIT();

    for (int kt = 0; kt <= qt; kt++) {
        if (kt < qt) {
            issue_tile(kt + 1, sbase + (uint32_t)((kt + 1) % 3) * FBUF);
            CP_COMMIT();
            CP_WAIT1();
        } else {
            CP_WAIT0();
        }
        __syncthreads();
        const uint32_t cbuf = sbase + (uint32_t)(kt % 3) * FBUF;

        float s[8][4];
        #pragma unroll
        for (int i = 0; i < 8; i++)
            #pragma unroll
            for (int j = 0; j < 4; j++) s[i][j] = 0.f;
        #pragma unroll
        for (int ks = 0; ks < 4; ks++) {
            uint32_t kh_[8][2], kl_[8][2];
            #pragma unroll
            for (int ntp = 0; ntp < 4; ntp++) {
                uint32_t r0, r1, r2, r3;
                uint32_t addr = cbuf + FKH + (uint32_t)(ntp*16 + (lane & 15)) * 144u
                              + (uint32_t)(ks*32) + ((lane >> 4) << 4);
                ldsm_x4(r0, r1, r2, r3, addr);
                kh_[2*ntp][0] = r0; kh_[2*ntp][1] = r2;
                kh_[2*ntp+1][0] = r1; kh_[2*ntp+1][1] = r3;
                ldsm_x4(r0, r1, r2, r3, addr + (FKL - FKH));
                kl_[2*ntp][0] = r0; kl_[2*ntp][1] = r2;
                kl_[2*ntp+1][0] = r1; kl_[2*ntp+1][1] = r3;
            }
            #pragma unroll
            for (int nt = 0; nt < 8; nt++) {
                mma16816(s[nt], qh[ks], kh_[nt]);
                mma16816(s[nt], qh[ks], kl_[nt]);
                mma16816(s[nt], ql[ks], kh_[nt]);
            }
        }
        const float* am = (const float*)(sm + (size_t)(kt % 3) * FBUF + FAM);
        #pragma unroll
        for (int nt = 0; nt < 8; nt++) {
            int c0 = nt*8 + tig*2;
            int kc0 = kt*64 + c0, kc1 = kc0 + 1;
            float a0 = am[c0], a1 = am[c0+1];
            s[nt][0] = (kc0 <= qr0 && a0 != 0.f) ? s[nt][0]*0.125f : -1e30f;
            s[nt][1] = (kc1 <= qr0 && a1 != 0.f) ? s[nt][1]*0.125f : -1e30f;
            s[nt][2] = (kc0 <= qr1 && a0 != 0.f) ? s[nt][2]*0.125f : -1e30f;
            s[nt][3] = (kc1 <= qr1 && a1 != 0.f) ? s[nt][3]*0.125f : -1e30f;
        }
        float mx0 = -1e30f, mx1 = -1e30f;
        #pragma unroll
        for (int nt = 0; nt < 8; nt++) {
            mx0 = fmaxf(mx0, fmaxf(s[nt][0], s[nt][1]));
            mx1 = fmaxf(mx1, fmaxf(s[nt][2], s[nt][3]));
        }
        mx0 = fmaxf(mx0, __shfl_xor_sync(0xffffffffu, mx0, 1));
        mx0 = fmaxf(mx0, __shfl_xor_sync(0xffffffffu, mx0, 2));
        mx1 = fmaxf(mx1, __shfl_xor_sync(0xffffffffu, mx1, 1));
        mx1 = fmaxf(mx1, __shfl_xor_sync(0xffffffffu, mx1, 2));
        float mn0 = fmaxf(mrow0, mx0), mn1 = fmaxf(mrow1, mx1);
        float sc0 = __expf(mrow0 - mn0), sc1 = __expf(mrow1 - mn1);
        mrow0 = mn0; mrow1 = mn1;
        float rs0 = 0.f, rs1 = 0.f;
        #pragma unroll
        for (int nt = 0; nt < 8; nt++) {
            s[nt][0] = __expf(s[nt][0] - mn0); rs0 += s[nt][0];
            s[nt][1] = __expf(s[nt][1] - mn0); rs0 += s[nt][1];
            s[nt][2] = __expf(s[nt][2] - mn1); rs1 += s[nt][2];
            s[nt][3] = __expf(s[nt][3] - mn1); rs1 += s[nt][3];
        }
        rs0 += __shfl_xor_sync(0xffffffffu, rs0, 1);
        rs0 += __shfl_xor_sync(0xffffffffu, rs0, 2);
        rs1 += __shfl_xor_sync(0xffffffffu, rs1, 1);
        rs1 += __shfl_xor_sync(0xffffffffu, rs1, 2);
        lrow0 = lrow0*sc0 + rs0; lrow1 = lrow1*sc1 + rs1;
        #pragma unroll
        for (int nt = 0; nt < 8; nt++) {
            o[nt][0] *= sc0; o[nt][1] *= sc0;
            o[nt][2] *= sc1; o[nt][3] *= sc1;
        }
        #pragma unroll
        for (int ks = 0; ks < 4; ks++) {
            uint32_t pah[4], pal[4];
            split2(s[2*ks][0],   s[2*ks][1],   pah[0], pal[0]);
            split2(s[2*ks][2],   s[2*ks][3],   pah[1], pal[1]);
            split2(s[2*ks+1][0], s[2*ks+1][1], pah[2], pal[2]);
            split2(s[2*ks+1][2], s[2*ks+1][3], pah[3], pal[3]);
            uint32_t vh_[8][2], vl_[8][2];
            #pragma unroll
            for (int ntp = 0; ntp < 4; ntp++) {
                uint32_t r0, r1, r2, r3;
                uint32_t addr = cbuf + FVH + (uint32_t)(ks*16 + (lane & 15)) * 144u
                              + (uint32_t)(ntp*32) + ((lane >> 4) << 4);
                ldsm_x4_t(r0, r1, r2, r3, addr);
                vh_[2*ntp][0] = r0; vh_[2*ntp][1] = r1;
                vh_[2*ntp+1][0] = r2; vh_[2*ntp+1][1] = r3;
                ldsm_x4_t(r0, r1, r2, r3, addr + (FVL - FVH));
                vl_[2*ntp][0] = r0; vl_[2*ntp][1] = r1;
                vl_[2*ntp+1][0] = r2; vl_[2*ntp+1][1] = r3;
            }
            #pragma unroll
            for (int nt = 0; nt < 8; nt++) {
                mma16816(o[nt], pah, vh_[nt]);
                mma16816(o[nt], pah, vl_[nt]);
                mma16816(o[nt], pal, vh_[nt]);
            }
        }
        // no trailing sync: 3-buffer ring tolerates one-iteration warp drift
    }
    float inv0 = 1.f / lrow0, inv1 = 1.f / lrow1;
    #pragma unroll
    for (int nt = 0; nt < 8; nt++) {
        int col = h*64 + nt*8 + tig*2;
        float v0 = o[nt][0]*inv0, v1 = o[nt][1]*inv0;
        float u0 = o[nt][2]*inv1, u1 = o[nt][3]*inv1;
        float x2 = __shfl_down_sync(0xffffffffu, v0, 1);
        float x3 = __shfl_down_sync(0xffffffffu, v1, 1);
        float y2 = __shfl_down_sync(0xffffffffu, u0, 1);
        float y3 = __shfl_down_sync(0xffffffffu, u1, 1);
        if ((tig & 1) == 0) {
            uint2 hi, lo;
            split4(make_float4(v0, v1, x2, x3), hi, lo);
            outs[(size_t)(b*SS + qr0) * 192 + (col >> 2)] = make_uint4(hi.x, hi.y, lo.x, lo.y);
            split4(make_float4(u0, u1, y2, y3), hi, lo);
            outs[(size_t)(b*SS + qr1) * 192 + (col >> 2)] = make_uint4(hi.x, hi.y, lo.x, lo.y);
        }
    }
}

// ---------------- position ids (parallel block scan) ----------------
__global__ void posids_kernel(const float* __restrict__ amask, int* __restrict__ pos) {
    __shared__ float ws[32];
    int b = blockIdx.x, t = threadIdx.x;
    float m = amask[b*SS + t];
    float v = m;
    #pragma unroll
    for (int o = 1; o < 32; o <<= 1) {
        float u = __shfl_up_sync(0xffffffffu, v, o);
        if ((t & 31) >= o) v += u;
    }
    if ((t & 31) == 31) ws[t >> 5] = v;
    __syncthreads();
    if (t < 32) {
        float w2 = ws[t];
        #pragma unroll
        for (int o = 1; o < 32; o <<= 1) {
            float u = __shfl_up_sync(0xffffffffu, w2, o);
            if (t >= o) w2 += u;
        }
        ws[t] = w2;
    }
    __syncthreads();
    float total = v + ((t >> 5) ? ws[(t >> 5) - 1] : 0.f);
    pos[b*SS + t] = (m == 0.f) ? 0 : (int)(total - 1.f);
}

// ---------------- launch ----------------
extern "C" void kernel_launch(void* const* d_in, const int* in_sizes, int n_in,
                              void* d_out, int out_size) {
    const int*   ids   = (const int*)  d_in[0];
    const float* amask = (const float*)d_in[1];
    const float* tok   = (const float*)d_in[2];
    const float* pemb  = (const float*)d_in[3];
    const float* ln1g  = (const float*)d_in[4];
    const float* ln1b  = (const float*)d_in[5];
    const float* Wq    = (const float*)d_in[6];
    const float* bq    = (const float*)d_in[7];
    const float* Wk    = (const float*)d_in[8];
    const float* bk    = (const float*)d_in[9];
    const float* Wv    = (const float*)d_in[10];
    const float* bv    = (const float*)d_in[11];
    const float* Wp    = (const float*)d_in[12];
    const float* bp    = (const float*)d_in[13];
    const float* ln2g  = (const float*)d_in[14];
    const float* ln2b  = (const float*)d_in[15];
    const float* W1    = (const float*)d_in[16];
    const float* b1    = (const float*)d_in[17];
    const float* W2    = (const float*)d_in[18];
    const float* b2    = (const float*)d_in[19];
    const float* lnfg  = (const float*)d_in[20];
    const float* lnfb  = (const float*)d_in[21];
    float* out = (float*)d_out;

    float *xp, *partp; int* pidp;
    uint2 *qhi, *qlo;
    uint4 *hs, *as, *fs, *wqs, *wks, *wvs, *wps, *w1s, *w2s, *toks;
    cudaGetSymbolAddress((void**)&xp,   g_x);
    cudaGetSymbolAddress((void**)&partp, g_mlp2p);
    cudaGetSymbolAddress((void**)&pidp, g_pos);
    cudaGetSymbolAddress((void**)&hs,   g_h_s);
    cudaGetSymbolAddress((void**)&qhi,  g_qkv_hi);
    cudaGetSymbolAddress((void**)&qlo,  g_qkv_lo);
    cudaGetSymbolAddress((void**)&as,   g_attn_s);
    cudaGetSymbolAddress((void**)&fs,   g_ff_s);
    cudaGetSymbolAddress((void**)&wqs,  g_wq_s);
    cudaGetSymbolAddress((void**)&wks,  g_wk_s);
    cudaGetSymbolAddress((void**)&wvs,  g_wv_s);
    cudaGetSymbolAddress((void**)&wps,  g_wp_s);
    cudaGetSymbolAddress((void**)&w1s,  g_w1_s);
    cudaGetSymbolAddress((void**)&w2s,  g_w2_s);
    cudaGetSymbolAddress((void**)&toks, g_tok_s);

    const int SM_T0 = 2*(20480 + 2*8704);   // 75776
    const int SM_T1 = 2*(20480 + 2*10240);  // 81920
    const int SM_FA = 3*FBUF;               // 111360
    cudaFuncSetAttribute(mma_gemm<0,0>, cudaFuncAttributeMaxDynamicSharedMemorySize, SM_T0);
    cudaFuncSetAttribute(mma_gemm<0,1>, cudaFuncAttributeMaxDynamicSharedMemorySize, SM_T0);
    cudaFuncSetAttribute(mma_gemm<1,0>, cudaFuncAttributeMaxDynamicSharedMemorySize, SM_T1);
    cudaFuncSetAttribute(qkv_gemm, cudaFuncAttributeMaxDynamicSharedMemorySize, SM_T0);
    cudaFuncSetAttribute(flash_kernel, cudaFuncAttributeMaxDynamicSharedMemorySize, SM_FA);

    const int nW  = LL*DD*DD/4;
    const int nW1 = LL*DD*FF/4;
    const int nT  = VV*DD/4;
    split_kernel<<<(nW +255)/256, 256>>>((const float4*)Wq, wqs, nW);
    split_kernel<<<(nW +255)/256, 256>>>((const float4*)Wk, wks, nW);
    split_kernel<<<(nW +255)/256, 256>>>((const float4*)Wv, wvs, nW);
    split_kernel<<<(nW +255)/256, 256>>>((const float4*)Wp, wps, nW);
    split_kernel<<<(nW1+255)/256, 256>>>((const float4*)W1, w1s, nW1);
    split_kernel<<<(nW1+255)/256, 256>>>((const float4*)W2, w2s, nW1);
    split_kernel<<<(nT +255)/256, 256>>>((const float4*)tok, toks, nT);

    posids_kernel<<<BB, 1024>>>(amask, pidp);
    // fused embed + layer0 ln1
    embed_ln_kernel<<<MM, 192>>>(ids, pidp, tok, pemb, xp, ln1g, ln1b, hs);

    dim3 gQKV(18, MM/128);
    dim3 gF(FF/128, MM/128);
    dim3 gP(DD/128, MM/128, 3);
    dim3 gM2(DD/128, MM/128, 3);
    dim3 gV(MM/128, (VV+127)/128);
    dim3 gFA(SS/64, BB*HH);

    for (int l = 0; l < LL; l++) {
        const uint4* wql = wqs + (size_t)l*(DD*DD/4);
        const uint4* wkl = wks + (size_t)l*(DD*DD/4);
        const uint4* wvl = wvs + (size_t)l*(DD*DD/4);
        const uint4* wpl = wps + (size_t)l*(DD*DD/4);
        const uint4* w1l = w1s + (size_t)l*(DD*FF/4);
        const uint4* w2l = w2s + (size_t)l*(DD*FF/4);

        qkv_gemm<<<gQKV, 256, SM_T0>>>(hs, wql, wkl, wvl, bq + l*DD, bk + l*DD, bv + l*DD,
                                       qhi, qlo);
        flash_kernel<<<gFA, 128, SM_FA>>>(qhi, qlo, amask, as);
        mma_gemm<0,0><<<gP, 256, SM_T0>>>(as, wpl, nullptr, nullptr, partp, nullptr,
                                          MM, DD, DD/3, 0, DD/4);
        reduce_ln_kernel<<<MM, 192>>>((const float4*)partp, bp + l*DD, (float4*)xp,
                                      ln2g + l*DD, ln2b + l*DD, hs);
        mma_gemm<0,1><<<gF, 256, SM_T0>>>(hs, w1l, b1 + l*FF, nullptr, nullptr, fs,
                                          MM, FF, DD, 1, DD/4);
        mma_gemm<0,0><<<gM2, 256, SM_T0>>>(fs, w2l, nullptr, nullptr, partp, nullptr,
                                           MM, DD, FF/3, 0, FF/4);
        const float* ng = (l + 1 < LL) ? (ln1g + (l+1)*DD) : lnfg;
        const float* nb = (l + 1 < LL) ? (ln1b + (l+1)*DD) : lnfb;
        reduce_ln_kernel<<<MM, 192>>>((const float4*)partp, b2 + l*DD, (float4*)xp,
                                      ng, nb, hs);
    }

    mma_gemm<1,0><<<gV, 256, SM_T1>>>(hs, toks, nullptr, nullptr, out, nullptr,
                                      MM, VV, DD, 0, DD/4);
}

// round 17
// speedup vs baseline: 1.6579x; 1.0243x over previous
#include <cuda_runtime.h>
#include <cuda_bf16.h>
#include <math.h>
#include <stdint.h>

#define BB 2
#define SS 1024
#define DD 768
#define HH 12
#define HDD 64
#define LL 12
#define VV 50257
#define FF 3072
#define MM (BB*SS)   // 2048

// ---------------- scratch (allocation-free) ----------------
__device__ float g_x[MM*DD];
__device__ int   g_pos[BB*SS];
__device__ uint4 g_h_s[MM*DD/4];
__device__ uint2 g_qkv_hi[MM*576];
__device__ uint2 g_qkv_lo[MM*576];
__device__ uint4 g_attn_s[MM*DD/4];
__device__ uint4 g_ff_s[MM*FF/4];
__device__ float g_mlp2p[3*MM*DD];
__device__ uint4 g_wq_s[LL*DD*DD/4];
__device__ uint4 g_wk_s[LL*DD*DD/4];
__device__ uint4 g_wv_s[LL*DD*DD/4];
__device__ uint4 g_wp_s[LL*DD*DD/4];
__device__ uint4 g_w1_s[LL*DD*FF/4];
__device__ uint4 g_w2_s[LL*DD*FF/4];
__device__ uint4 g_tok_s[(size_t)VV*DD/4];

// ================= helpers =================
__device__ __forceinline__ uint32_t smem_u32(const void* p) {
    uint32_t a;
    asm("{ .reg .u64 t; cvta.to.shared.u64 t, %1; cvt.u32.u64 %0, t; }" : "=r"(a) : "l"(p));
    return a;
}
__device__ __forceinline__ void ldsm_x4(uint32_t& r0, uint32_t& r1, uint32_t& r2, uint32_t& r3,
                                        uint32_t addr) {
    asm volatile("ldmatrix.sync.aligned.m8n8.x4.shared.b16 {%0,%1,%2,%3}, [%4];"
                 : "=r"(r0), "=r"(r1), "=r"(r2), "=r"(r3) : "r"(addr));
}
__device__ __forceinline__ void ldsm_x4_t(uint32_t& r0, uint32_t& r1, uint32_t& r2, uint32_t& r3,
                                          uint32_t addr) {
    asm volatile("ldmatrix.sync.aligned.m8n8.x4.trans.shared.b16 {%0,%1,%2,%3}, [%4];"
                 : "=r"(r0), "=r"(r1), "=r"(r2), "=r"(r3) : "r"(addr));
}
__device__ __forceinline__ void mma16816(float* c, const uint32_t* a, const uint32_t* b) {
    asm volatile("mma.sync.aligned.m16n8k16.row.col.f32.bf16.bf16.f32 "
                 "{%0,%1,%2,%3}, {%4,%5,%6,%7}, {%8,%9}, {%0,%1,%2,%3};"
                 : "+f"(c[0]), "+f"(c[1]), "+f"(c[2]), "+f"(c[3])
                 : "r"(a[0]), "r"(a[1]), "r"(a[2]), "r"(a[3]), "r"(b[0]), "r"(b[1]));
}
__device__ __forceinline__ void cp16(uint32_t saddr, const void* gptr) {
    asm volatile("cp.async.cg.shared.global [%0], [%1], 16;" :: "r"(saddr), "l"(gptr));
}
#define CP_COMMIT() asm volatile("cp.async.commit_group;" ::: "memory")
#define CP_WAIT1()  asm volatile("cp.async.wait_group 1;" ::: "memory")
#define CP_WAIT0()  asm volatile("cp.async.wait_group 0;" ::: "memory")

__device__ __forceinline__ void split4(float4 v, uint2& hi, uint2& lo) {
    __nv_bfloat16 h0 = __float2bfloat16(v.x), h1 = __float2bfloat16(v.y);
    __nv_bfloat16 h2 = __float2bfloat16(v.z), h3 = __float2bfloat16(v.w);
    __nv_bfloat16 l0 = __float2bfloat16(v.x - __bfloat162float(h0));
    __nv_bfloat16 l1 = __float2bfloat16(v.y - __bfloat162float(h1));
    __nv_bfloat16 l2 = __float2bfloat16(v.z - __bfloat162float(h2));
    __nv_bfloat16 l3 = __float2bfloat16(v.w - __bfloat162float(h3));
    __nv_bfloat162 a = __nv_bfloat162(h0, h1), b = __nv_bfloat162(h2, h3);
    __nv_bfloat162 c = __nv_bfloat162(l0, l1), d = __nv_bfloat162(l2, l3);
    hi.x = *(uint32_t*)&a; hi.y = *(uint32_t*)&b;
    lo.x = *(uint32_t*)&c; lo.y = *(uint32_t*)&d;
}
__device__ __forceinline__ void split2(float a, float b, uint32_t& hi, uint32_t& lo) {
    __nv_bfloat16 h0 = __float2bfloat16(a), h1 = __float2bfloat16(b);
    __nv_bfloat16 l0 = __float2bfloat16(a - __bfloat162float(h0));
    __nv_bfloat16 l1 = __float2bfloat16(b - __bfloat162float(h1));
    __nv_bfloat162 H(h0, h1), L(l0, l1);
    hi = *(uint32_t*)&H; lo = *(uint32_t*)&L;
}
__device__ __forceinline__ float gelu_exact(float v) {
    return 0.5f * v * (1.0f + erff(v * 0.70710678118654752f));
}

// ---------------- fp32 -> split converter ----------------
__global__ void split_kernel(const float4* __restrict__ src, uint4* __restrict__ dst, int n) {
    int i = blockIdx.x*blockDim.x + threadIdx.x;
    if (i < n) {
        uint2 hi, lo;
        split4(src[i], hi, lo);
        dst[i] = make_uint4(hi.x, hi.y, lo.x, lo.y);
    }
}

// ---------------- common LN tail ----------------
__device__ __forceinline__ void ln_tail(float4 v, int i, int tid,
                                        const float* __restrict__ g,
                                        const float* __restrict__ b,
                                        uint4* __restrict__ ys, float* pr) {
    float s = v.x + v.y + v.z + v.w;
    #pragma unroll
    for (int o = 16; o; o >>= 1) s += __shfl_xor_sync(0xffffffffu, s, o);
    if ((tid & 31) == 0) pr[tid >> 5] = s;
    __syncthreads();
    float mu = (pr[0]+pr[1]+pr[2]+pr[3]+pr[4]+pr[5]) * (1.f/DD);
    float dx = v.x-mu, dy = v.y-mu, dz = v.z-mu, dw = v.w-mu;
    float s2 = dx*dx + dy*dy + dz*dz + dw*dw;
    #pragma unroll
    for (int o = 16; o; o >>= 1) s2 += __shfl_xor_sync(0xffffffffu, s2, o);
    __syncthreads();
    if ((tid & 31) == 0) pr[tid >> 5] = s2;
    __syncthreads();
    float rstd = rsqrtf((pr[0]+pr[1]+pr[2]+pr[3]+pr[4]+pr[5]) * (1.f/DD) + 1e-5f);
    float4 gg = ((const float4*)g)[tid], bb = ((const float4*)b)[tid];
    float4 y = make_float4(dx*rstd*gg.x + bb.x, dy*rstd*gg.y + bb.y,
                           dz*rstd*gg.z + bb.z, dw*rstd*gg.w + bb.w);
    uint2 hi, lo; split4(y, hi, lo);
    ys[i] = make_uint4(hi.x, hi.y, lo.x, lo.y);
}

// ---------------- fused embed + layer0 ln1 ----------------
__global__ void embed_ln_kernel(const int* __restrict__ ids, const int* __restrict__ pos,
                                const float* __restrict__ tok, const float* __restrict__ pemb,
                                float* __restrict__ x, const float* __restrict__ g,
                                const float* __restrict__ b, uint4* __restrict__ ys) {
    __shared__ float pr[6];
    int row = blockIdx.x, tid = threadIdx.x;
    int id = ids[row], p = pos[row];
    float4 t4 = ((const float4*)(tok + (size_t)id*DD))[tid];
    float4 p4 = ((const float4*)(pemb + (size_t)p*DD))[tid];
    float4 v = make_float4(t4.x+p4.x, t4.y+p4.y, t4.z+p4.z, t4.w+p4.w);
    int i = row*192 + tid;
    ((float4*)x)[i] = v;
    ln_tail(v, i, tid, g, b, ys, pr);
}

// ---------------- fused split-K reduce + layernorm + split ----------------
__global__ void reduce_ln_kernel(const float4* __restrict__ part, const float* __restrict__ bias,
                                 float4* __restrict__ x, const float* __restrict__ g,
                                 const float* __restrict__ b, uint4* __restrict__ ys) {
    __shared__ float pr[6];
    const int S = MM*DD/4;
    int row = blockIdx.x, tid = threadIdx.x;
    int i = row*192 + tid;
    float4 p0 = part[i], p1 = part[i + S], p2 = part[i + 2*S];
    float4 bb4 = ((const float4*)bias)[tid];
    float4 v = x[i];
    v.x += p0.x + p1.x + p2.x + bb4.x;
    v.y += p0.y + p1.y + p2.y + bb4.y;
    v.z += p0.z + p1.z + p2.z + bb4.z;
    v.w += p0.w + p1.w + p2.w + bb4.w;
    x[i] = v;
    ln_tail(v, i, tid, g, b, ys, pr);
}

// ============ split-bf16 GEMM: BK=64, double-buffered smem ============
// A smem: 128 rows x 144B pitch (hi plane 18432B, lo at +18432). BOFF=36864.
// B non-trans: 64 k-rows x 272B (plane 17408). B trans: 128 n-rows x 144B (18432).
template<int TRANSB, int OUTSPLIT>
__global__ void __launch_bounds__(256, 1)
mma_gemm(const uint4* __restrict__ As, const uint4* __restrict__ Bs,
         const float* __restrict__ bias, const float* __restrict__ res,
         float* __restrict__ C, uint4* __restrict__ Cs,
         int M, int N, int K, int act, int lda4)
{
    extern __shared__ __align__(16) unsigned char sm[];
    constexpr int A_LO  = 18432;
    constexpr int BOFF  = 36864;
    constexpr int BHI   = TRANSB ? 18432 : 17408;
    constexpr int BUFSZ = BOFF + 2*BHI;
    const uint32_t sbase = smem_u32(sm);
    const int tid = threadIdx.x, lane = tid & 31, wid = tid >> 5;
    const int wm = wid & 3, wn = wid >> 2;
    const int m0 = (TRANSB ? blockIdx.x : blockIdx.y) << 7;
    const int n0 = (TRANSB ? blockIdx.y : blockIdx.x) << 7;
    const int grp = lane >> 2, tig = lane & 3;
    const int N4 = N >> 2;

    const int z = blockIdx.z;
    As += (size_t)z * (K >> 2);
    if (TRANSB) Bs += (size_t)z * (K >> 2);
    else        Bs += (size_t)z * K * N4;
    C  += (size_t)z * M * N;

    float acc[2][8][4];
    #pragma unroll
    for (int i = 0; i < 2; i++)
        #pragma unroll
        for (int j = 0; j < 8; j++)
            #pragma unroll
            for (int q = 0; q < 4; q++) acc[i][j][q] = 0.f;

    // A: thread covers rows arow+16p (p=0..7), uint4 group ag (0..15)
    const int arow = tid >> 4, ag = tid & 15;
    const uint4* pa = As + (size_t)(m0 + arow) * lda4 + ag;

    const uint4* pb;
    bool bpred[8];
    if (TRANSB) {
        #pragma unroll
        for (int p = 0; p < 8; p++) bpred[p] = (n0 + arow + 16*p) < N;
        pb = Bs + (size_t)(n0 + arow) * lda4 + ag;
    } else {
        #pragma unroll
        for (int p = 0; p < 8; p++) bpred[p] = true;
        pb = Bs + (size_t)(tid >> 5) * N4 + (n0 >> 2) + (tid & 31);
    }

    const int NC = K >> 6;
    uint4 ra[8], rb[8];
    const uint4 z4 = make_uint4(0u, 0u, 0u, 0u);

    const uint32_t aoff_t = (uint32_t)arow * 144u + (uint32_t)ag * 8u;
    uint32_t boff_t;
    if (TRANSB) boff_t = aoff_t;
    else        boff_t = (uint32_t)(tid >> 5) * 272u + (uint32_t)(tid & 31) * 8u;

    // ---- load chunk 0 ----
    #pragma unroll
    for (int p = 0; p < 8; p++) {
        ra[p] = pa[(size_t)(16*p) * lda4];
        if (TRANSB) rb[p] = bpred[p] ? pb[(size_t)(16*p) * lda4] : z4;
        else        rb[p] = pb[(size_t)(8*p) * N4];
    }
    #pragma unroll
    for (int p = 0; p < 8; p++) {
        uint32_t ao = aoff_t + (uint32_t)(16*p) * 144u;
        *(uint2*)(sm + ao)        = make_uint2(ra[p].x, ra[p].y);
        *(uint2*)(sm + A_LO + ao) = make_uint2(ra[p].z, ra[p].w);
        uint32_t bo = TRANSB ? (boff_t + (uint32_t)(16*p) * 144u)
                             : (boff_t + (uint32_t)(8*p) * 272u);
        *(uint2*)(sm + BOFF + bo)       = make_uint2(rb[p].x, rb[p].y);
        *(uint2*)(sm + BOFF + BHI + bo) = make_uint2(rb[p].z, rb[p].w);
    }
    __syncthreads();

    for (int kc = 0; kc < NC; kc++) {
        if (kc + 1 < NC) {
            const int kg = (kc + 1) * 16;
            #pragma unroll
            for (int p = 0; p < 8; p++) {
                ra[p] = pa[(size_t)(16*p) * lda4 + kg];
                if (TRANSB) rb[p] = bpred[p] ? pb[(size_t)(16*p) * lda4 + kg] : z4;
                else        rb[p] = pb[((size_t)(8*p) + (size_t)(kc+1)*64) * N4];
            }
        }

        const uint32_t cb = sbase + (uint32_t)(kc & 1) * BUFSZ;
        #pragma unroll
        for (int ks = 0; ks < 4; ks++) {
            uint32_t ah[2][4], al[2][4], bh[8][2], bl[8][2];
            #pragma unroll
            for (int mt = 0; mt < 2; mt++) {
                uint32_t addr = cb + (uint32_t)(wm*32 + mt*16 + (lane & 15)) * 144u
                              + (uint32_t)(ks*32) + ((lane >> 4) << 4);
                ldsm_x4(ah[mt][0], ah[mt][1], ah[mt][2], ah[mt][3], addr);
                ldsm_x4(al[mt][0], al[mt][1], al[mt][2], al[mt][3], addr + A_LO);
            }
            #pragma unroll
            for (int ntp = 0; ntp < 4; ntp++) {
                uint32_t r0, r1, r2, r3;
                if (TRANSB) {
                    uint32_t addr = cb + BOFF
                                  + (uint32_t)(wn*64 + ntp*16 + (lane & 15)) * 144u
                                  + (uint32_t)(ks*32) + ((lane >> 4) << 4);
                    ldsm_x4(r0, r1, r2, r3, addr);
                    bh[2*ntp][0] = r0; bh[2*ntp+1][0] = r1;
                    bh[2*ntp][1] = r2; bh[2*ntp+1][1] = r3;
                    ldsm_x4(r0, r1, r2, r3, addr + BHI);
                    bl[2*ntp][0] = r0; bl[2*ntp+1][0] = r1;
                    bl[2*ntp][1] = r2; bl[2*ntp+1][1] = r3;
                } else {
                    uint32_t addr = cb + BOFF
                                  + (uint32_t)(ks*16 + (lane & 15)) * 272u
                                  + (uint32_t)(wn*64 + ntp*16) * 2u + ((lane >> 4) << 4);
                    ldsm_x4_t(r0, r1, r2, r3, addr);
                    bh[2*ntp][0] = r0; bh[2*ntp][1] = r1;
                    bh[2*ntp+1][0] = r2; bh[2*ntp+1][1] = r3;
                    ldsm_x4_t(r0, r1, r2, r3, addr + BHI);
                    bl[2*ntp][0] = r0; bl[2*ntp][1] = r1;
                    bl[2*ntp+1][0] = r2; bl[2*ntp+1][1] = r3;
                }
            }
            #pragma unroll
            for (int mt = 0; mt < 2; mt++)
                #pragma unroll
                for (int nt = 0; nt < 8; nt++) {
                    mma16816(acc[mt][nt], ah[mt], bh[nt]);
                    mma16816(acc[mt][nt], ah[mt], bl[nt]);
                    mma16816(acc[mt][nt], al[mt], bh[nt]);
                }
        }

        if (kc + 1 < NC) {
            unsigned char* nb = sm + (uint32_t)((kc + 1) & 1) * BUFSZ;
            #pragma unroll
            for (int p = 0; p < 8; p++) {
                uint32_t ao = aoff_t + (uint32_t)(16*p) * 144u;
                *(uint2*)(nb + ao)        = make_uint2(ra[p].x, ra[p].y);
                *(uint2*)(nb + A_LO + ao) = make_uint2(ra[p].z, ra[p].w);
                uint32_t bo = TRANSB ? (boff_t + (uint32_t)(16*p) * 144u)
                                     : (boff_t + (uint32_t)(8*p) * 272u);
                *(uint2*)(nb + BOFF + bo)       = make_uint2(rb[p].x, rb[p].y);
                *(uint2*)(nb + BOFF + BHI + bo) = make_uint2(rb[p].z, rb[p].w);
            }
            __syncthreads();
        }
    }

    const int mrow = m0 + wm*32;
    #pragma unroll
    for (int mt = 0; mt < 2; mt++) {
        #pragma unroll
        for (int nt = 0; nt < 8; nt++) {
            int col = n0 + wn*64 + nt*8 + tig*2;
            bool ok0 = (!TRANSB) || (col < N);
            bool ok1 = (!TRANSB) || (col + 1 < N);
            float b0v = 0.f, b1v = 0.f;
            if (bias) { if (ok0) b0v = bias[col]; if (ok1) b1v = bias[col+1]; }
            #pragma unroll
            for (int hh = 0; hh < 2; hh++) {
                int row = mrow + mt*16 + grp + hh*8;
                float v0 = acc[mt][nt][2*hh+0] + b0v;
                float v1 = acc[mt][nt][2*hh+1] + b1v;
                if (act) { v0 = gelu_exact(v0); v1 = gelu_exact(v1); }
                if (OUTSPLIT) {
                    float x2 = __shfl_down_sync(0xffffffffu, v0, 1);
                    float x3 = __shfl_down_sync(0xffffffffu, v1, 1);
                    if ((tig & 1) == 0) {
                        uint2 hi, lo;
                        split4(make_float4(v0, v1, x2, x3), hi, lo);
                        Cs[(size_t)row * (N >> 2) + (col >> 2)] = make_uint4(hi.x, hi.y, lo.x, lo.y);
                    }
                } else {
                    size_t base = (size_t)row * N + col;
                    if (res) { if (ok0) v0 += res[base]; if (ok1) v1 += res[base+1]; }
                    if (!TRANSB) {
                        float2 o; o.x = v0; o.y = v1;
                        *(float2*)(C + base) = o;
                    } else {
                        if (ok0) C[base] = v0;
                        if (ok1) C[base+1] = v1;
                    }
                }
            }
        }
    }
}

// ============ fused QKV GEMM: BK=64, split in, hi/lo planes out ============
__global__ void __launch_bounds__(256, 1)
qkv_gemm(const uint4* __restrict__ As,
         const uint4* __restrict__ Wqs, const uint4* __restrict__ Wks, const uint4* __restrict__ Wvs,
         const float* __restrict__ bq_, const float* __restrict__ bk_, const float* __restrict__ bv_,
         uint2* __restrict__ Chi, uint2* __restrict__ Clo)
{
    extern __shared__ __align__(16) unsigned char sm[];
    constexpr int A_LO  = 18432;
    constexpr int BOFF  = 36864;
    constexpr int BHI   = 17408;
    constexpr int BUFSZ = BOFF + 2*BHI;
    const int K4 = DD >> 2, N4 = DD >> 2;
    const uint32_t sbase = smem_u32(sm);
    const int tid = threadIdx.x, lane = tid & 31, wid = tid >> 5;
    const int wm = wid & 3, wn = wid >> 2;
    const int m0 = blockIdx.y << 7;
    const int sel = blockIdx.x / 6;
    const int n0 = (blockIdx.x % 6) << 7;
    const uint4* Bs   = (sel == 0) ? Wqs : (sel == 1) ? Wks : Wvs;
    const float* bias = (sel == 0) ? bq_ : (sel == 1) ? bk_ : bv_;
    const int grp = lane >> 2, tig = lane & 3;

    float acc[2][8][4];
    #pragma unroll
    for (int i = 0; i < 2; i++)
        #pragma unroll
        for (int j = 0; j < 8; j++)
            #pragma unroll
            for (int q = 0; q < 4; q++) acc[i][j][q] = 0.f;

    const int arow = tid >> 4, ag = tid & 15;
    const uint4* pa = As + (size_t)(m0 + arow) * K4 + ag;
    const uint4* pb = Bs + (size_t)(tid >> 5) * N4 + (n0 >> 2) + (tid & 31);

    const int NC = DD >> 6;
    uint4 ra[8], rb[8];
    const uint32_t aoff_t = (uint32_t)arow * 144u + (uint32_t)ag * 8u;
    const uint32_t boff_t = (uint32_t)(tid >> 5) * 272u + (uint32_t)(tid & 31) * 8u;

    #pragma unroll
    for (int p = 0; p < 8; p++) {
        ra[p] = pa[(size_t)(16*p) * K4];
        rb[p] = pb[(size_t)(8*p) * N4];
    }
    #pragma unroll
    for (int p = 0; p < 8; p++) {
        uint32_t ao = aoff_t + (uint32_t)(16*p) * 144u;
        *(uint2*)(sm + ao)        = make_uint2(ra[p].x, ra[p].y);
        *(uint2*)(sm + A_LO + ao) = make_uint2(ra[p].z, ra[p].w);
        uint32_t bo = boff_t + (uint32_t)(8*p) * 272u;
        *(uint2*)(sm + BOFF + bo)       = make_uint2(rb[p].x, rb[p].y);
        *(uint2*)(sm + BOFF + BHI + bo) = make_uint2(rb[p].z, rb[p].w);
    }
    __syncthreads();

    for (int kc = 0; kc < NC; kc++) {
        if (kc + 1 < NC) {
            const int kg = (kc + 1) * 16;
            #pragma unroll
            for (int p = 0; p < 8; p++) {
                ra[p] = pa[(size_t)(16*p) * K4 + kg];
                rb[p] = pb[((size_t)(8*p) + (size_t)(kc+1)*64) * N4];
            }
        }

        const uint32_t cb = sbase + (uint32_t)(kc & 1) * BUFSZ;
        #pragma unroll
        for (int ks = 0; ks < 4; ks++) {
            uint32_t ah[2][4], al[2][4], bh[8][2], bl[8][2];
            #pragma unroll
            for (int mt = 0; mt < 2; mt++) {
                uint32_t addr = cb + (uint32_t)(wm*32 + mt*16 + (lane & 15)) * 144u
                              + (uint32_t)(ks*32) + ((lane >> 4) << 4);
                ldsm_x4(ah[mt][0], ah[mt][1], ah[mt][2], ah[mt][3], addr);
                ldsm_x4(al[mt][0], al[mt][1], al[mt][2], al[mt][3], addr + A_LO);
            }
            #pragma unroll
            for (int ntp = 0; ntp < 4; ntp++) {
                uint32_t r0, r1, r2, r3;
                uint32_t addr = cb + BOFF
                              + (uint32_t)(ks*16 + (lane & 15)) * 272u
                              + (uint32_t)(wn*64 + ntp*16) * 2u + ((lane >> 4) << 4);
                ldsm_x4_t(r0, r1, r2, r3, addr);
                bh[2*ntp][0] = r0; bh[2*ntp][1] = r1;
                bh[2*ntp+1][0] = r2; bh[2*ntp+1][1] = r3;
                ldsm_x4_t(r0, r1, r2, r3, addr + BHI);
                bl[2*ntp][0] = r0; bl[2*ntp][1] = r1;
                bl[2*ntp+1][0] = r2; bl[2*ntp+1][1] = r3;
            }
            #pragma unroll
            for (int mt = 0; mt < 2; mt++)
                #pragma unroll
                for (int nt = 0; nt < 8; nt++) {
                    mma16816(acc[mt][nt], ah[mt], bh[nt]);
                    mma16816(acc[mt][nt], ah[mt], bl[nt]);
                    mma16816(acc[mt][nt], al[mt], bh[nt]);
                }
        }

        if (kc + 1 < NC) {
            unsigned char* nb = sm + (uint32_t)((kc + 1) & 1) * BUFSZ;
            #pragma unroll
            for (int p = 0; p < 8; p++) {
                uint32_t ao = aoff_t + (uint32_t)(16*p) * 144u;
                *(uint2*)(nb + ao)        = make_uint2(ra[p].x, ra[p].y);
                *(uint2*)(nb + A_LO + ao) = make_uint2(ra[p].z, ra[p].w);
                uint32_t bo = boff_t + (uint32_t)(8*p) * 272u;
                *(uint2*)(nb + BOFF + bo)       = make_uint2(rb[p].x, rb[p].y);
                *(uint2*)(nb + BOFF + BHI + bo) = make_uint2(rb[p].z, rb[p].w);
            }
            __syncthreads();
        }
    }

    const int mrow = m0 + wm*32;
    #pragma unroll
    for (int mt = 0; mt < 2; mt++) {
        #pragma unroll
        for (int nt = 0; nt < 8; nt++) {
            int col = n0 + wn*64 + nt*8 + tig*2;
            float b0v = bias[col], b1v = bias[col+1];
            #pragma unroll
            for (int hh = 0; hh < 2; hh++) {
                int row = mrow + mt*16 + grp + hh*8;
                float v0 = acc[mt][nt][2*hh+0] + b0v;
                float v1 = acc[mt][nt][2*hh+1] + b1v;
                float x2 = __shfl_down_sync(0xffffffffu, v0, 1);
                float x3 = __shfl_down_sync(0xffffffffu, v1, 1);
                if ((tig & 1) == 0) {
                    uint2 hi, lo;
                    split4(make_float4(v0, v1, x2, x3), hi, lo);
                    size_t idx = (size_t)row * 576 + (size_t)(sel*192) + (col >> 2);
                    Chi[idx] = hi;
                    Clo[idx] = lo;
                }
            }
        }
    }
}

// ============ flash attention: cp.async 3-buffer ring ============
#define FKH 0
#define FKL 9216
#define FVH 18432
#define FVL 27648
#define FAM 36864
#define FBUF 37120

__global__ void __launch_bounds__(128, 1)
flash_kernel(const uint2* __restrict__ qhi, const uint2* __restrict__ qlo,
             const float* __restrict__ amask, uint4* __restrict__ outs)
{
    extern __shared__ __align__(16) unsigned char sm[];
    const uint32_t sbase = smem_u32(sm);
    const int tid = threadIdx.x, lane = tid & 31, w = tid >> 5;
    const int grp = lane >> 2, tig = lane & 3;
    const int qt = (int)gridDim.x - 1 - (int)blockIdx.x;
    const int bh = blockIdx.y, b = bh / HH, h = bh % HH;
    const int q0 = qt * 64;

    uint32_t qh[4][4], ql[4][4];
    #pragma unroll
    for (int ks = 0; ks < 4; ks++)
        #pragma unroll
        for (int j = 0; j < 4; j++) {
            int row = q0 + w*16 + grp + (j & 1) * 8;
            int col = h*64 + ks*16 + (j >> 1) * 8 + tig*2;
            size_t gi = (size_t)(b*SS + row) * 576 + (col >> 2);
            uint2 gh = qhi[gi], gl = qlo[gi];
            qh[ks][j] = ((col & 3) == 0) ? gh.x : gh.y;
            ql[ks][j] = ((col & 3) == 0) ? gl.x : gl.y;
        }

    float o[8][4];
    #pragma unroll
    for (int i = 0; i < 8; i++)
        #pragma unroll
        for (int j = 0; j < 4; j++) o[i][j] = 0.f;
    float mrow0 = -1e30f, mrow1 = -1e30f, lrow0 = 0.f, lrow1 = 0.f;
    const int qr0 = q0 + w*16 + grp, qr1 = qr0 + 8;

    auto issue_tile = [&](int kt, uint32_t bb) {
        const size_t rowbase = (size_t)(b*SS + kt*64) * 576 + 192 + h*16;
        #pragma unroll
        for (int it = 0; it < 4; it++) {
            int idx = tid + it*128;
            int r = idx >> 3, c = idx & 7;
            size_t go = rowbase + (size_t)r*576 + c*2;
            uint32_t so = (uint32_t)r*144u + (uint32_t)c*16u;
            cp16(bb + FKH + so, qhi + go);
            cp16(bb + FKL + so, qlo + go);
            cp16(bb + FVH + so, qhi + go + 192);
            cp16(bb + FVL + so, qlo + go + 192);
        }
        if (tid < 16) cp16(bb + FAM + tid*16, amask + b*SS + kt*64 + tid*4);
    };

    issue_tile(0, sbase);
    CP_COMMIT();

    for (int kt = 0; kt <= qt; kt++) {
        if (kt < qt) {
            issue_tile(kt + 1, sbase + (uint32_t)((kt + 1) % 3) * FBUF);
            CP_COMMIT();
            CP_WAIT1();
        } else {
            CP_WAIT0();
        }
        __syncthreads();
        const uint32_t cbuf = sbase + (uint32_t)(kt % 3) * FBUF;

        float s[8][4];
        #pragma unroll
        for (int i = 0; i < 8; i++)
            #pragma unroll
            for (int j = 0; j < 4; j++) s[i][j] = 0.f;
        #pragma unroll
        for (int ks = 0; ks < 4; ks++) {
            uint32_t kh_[8][2], kl_[8][2];
            #pragma unroll
            for (int ntp = 0; ntp < 4; ntp++) {
                uint32_t r0, r1, r2, r3;
                uint32_t addr = cbuf + FKH + (uint32_t)(ntp*16 + (lane & 15)) * 144u
                              + (uint32_t)(ks*32) + ((lane >> 4) << 4);
                ldsm_x4(r0, r1, r2, r3, addr);
                kh_[2*ntp][0] = r0; kh_[2*ntp][1] = r2;
                kh_[2*ntp+1][0] = r1; kh_[2*ntp+1][1] = r3;
                ldsm_x4(r0, r1, r2, r3, addr + (FKL - FKH));
                kl_[2*ntp][0] = r0; kl_[2*ntp][1] = r2;
                kl_[2*ntp+1][0] = r1; kl_[2*ntp+1][1] = r3;
            }
            #pragma unroll
            for (int nt = 0; nt < 8; nt++) {
                mma16816(s[nt], qh[ks], kh_[nt]);
                mma16816(s[nt], qh[ks], kl_[nt]);
                mma16816(s[nt], ql[ks], kh_[nt]);
            }
        }
        const float* am = (const float*)(sm + (size_t)(kt % 3) * FBUF + FAM);
        #pragma unroll
        for (int nt = 0; nt < 8; nt++) {
            int c0 = nt*8 + tig*2;
            int kc0 = kt*64 + c0, kc1 = kc0 + 1;
            float a0 = am[c0], a1 = am[c0+1];
            s[nt][0] = (kc0 <= qr0 && a0 != 0.f) ? s[nt][0]*0.125f : -1e30f;
            s[nt][1] = (kc1 <= qr0 && a1 != 0.f) ? s[nt][1]*0.125f : -1e30f;
            s[nt][2] = (kc0 <= qr1 && a0 != 0.f) ? s[nt][2]*0.125f : -1e30f;
            s[nt][3] = (kc1 <= qr1 && a1 != 0.f) ? s[nt][3]*0.125f : -1e30f;
        }
        float mx0 = -1e30f, mx1 = -1e30f;
        #pragma unroll
        for (int nt = 0; nt < 8; nt++) {
            mx0 = fmaxf(mx0, fmaxf(s[nt][0], s[nt][1]));
            mx1 = fmaxf(mx1, fmaxf(s[nt][2], s[nt][3]));
        }
        mx0 = fmaxf(mx0, __shfl_xor_sync(0xffffffffu, mx0, 1));
        mx0 = fmaxf(mx0, __shfl_xor_sync(0xffffffffu, mx0, 2));
        mx1 = fmaxf(mx1, __shfl_xor_sync(0xffffffffu, mx1, 1));
        mx1 = fmaxf(mx1, __shfl_xor_sync(0xffffffffu, mx1, 2));
        float mn0 = fmaxf(mrow0, mx0), mn1 = fmaxf(mrow1, mx1);
        float sc0 = __expf(mrow0 - mn0), sc1 = __expf(mrow1 - mn1);
        mrow0 = mn0; mrow1 = mn1;
        float rs0 = 0.f, rs1 = 0.f;
        #pragma unroll
        for (int nt = 0; nt < 8; nt++) {
            s[nt][0] = __expf(s[nt][0] - mn0); rs0 += s[nt][0];
            s[nt][1] = __expf(s[nt][1] - mn0); rs0 += s[nt][1];
            s[nt][2] = __expf(s[nt][2] - mn1); rs1 += s[nt][2];
            s[nt][3] = __expf(s[nt][3] - mn1); rs1 += s[nt][3];
        }
        rs0 += __shfl_xor_sync(0xffffffffu, rs0, 1);
        rs0 += __shfl_xor_sync(0xffffffffu, rs0, 2);
        rs1 += __shfl_xor_sync(0xffffffffu, rs1, 1);
        rs1 += __shfl_xor_sync(0xffffffffu, rs1, 2);
        lrow0 = lrow0*sc0 + rs0; lrow1 = lrow1*sc1 + rs1;
        #pragma unroll
        for (int nt = 0; nt < 8; nt++) {
            o[nt][0] *= sc0; o[nt][1] *= sc0;
            o[nt][2] *= sc1; o[nt][3] *= sc1;
        }
        #pragma unroll
        for (int ks = 0; ks < 4; ks++) {
            uint32_t pah[4], pal[4];
            split2(s[2*ks][0],   s[2*ks][1],   pah[0], pal[0]);
            split2(s[2*ks][2],   s[2*ks][3],   pah[1], pal[1]);
            split2(s[2*ks+1][0], s[2*ks+1][1], pah[2], pal[2]);
            split2(s[2*ks+1][2], s[2*ks+1][3], pah[3], pal[3]);
            uint32_t vh_[8][2], vl_[8][2];
            #pragma unroll
            for (int ntp = 0; ntp < 4; ntp++) {
                uint32_t r0, r1, r2, r3;
                uint32_t addr = cbuf + FVH + (uint32_t)(ks*16 + (lane & 15)) * 144u
                              + (uint32_t)(ntp*32) + ((lane >> 4) << 4);
                ldsm_x4_t(r0, r1, r2, r3, addr);
                vh_[2*ntp][0] = r0; vh_[2*ntp][1] = r1;
                vh_[2*ntp+1][0] = r2; vh_[2*ntp+1][1] = r3;
                ldsm_x4_t(r0, r1, r2, r3, addr + (FVL - FVH));
                vl_[2*ntp][0] = r0; vl_[2*ntp][1] = r1;
                vl_[2*ntp+1][0] = r2; vl_[2*ntp+1][1] = r3;
            }
            #pragma unroll
            for (int nt = 0; nt < 8; nt++) {
                mma16816(o[nt], pah, vh_[nt]);
                mma16816(o[nt], pah, vl_[nt]);
                mma16816(o[nt], pal, vh_[nt]);
            }
        }
    }
    float inv0 = 1.f / lrow0, inv1 = 1.f / lrow1;
    #pragma unroll
    for (int nt = 0; nt < 8; nt++) {
        int col = h*64 + nt*8 + tig*2;
        float v0 = o[nt][0]*inv0, v1 = o[nt][1]*inv0;
        float u0 = o[nt][2]*inv1, u1 = o[nt][3]*inv1;
        float x2 = __shfl_down_sync(0xffffffffu, v0, 1);
        float x3 = __shfl_down_sync(0xffffffffu, v1, 1);
        float y2 = __shfl_down_sync(0xffffffffu, u0, 1);
        float y3 = __shfl_down_sync(0xffffffffu, u1, 1);
        if ((tig & 1) == 0) {
            uint2 hi, lo;
            split4(make_float4(v0, v1, x2, x3), hi, lo);
            outs[(size_t)(b*SS + qr0) * 192 + (col >> 2)] = make_uint4(hi.x, hi.y, lo.x, lo.y);
            split4(make_float4(u0, u1, y2, y3), hi, lo);
            outs[(size_t)(b*SS + qr1) * 192 + (col >> 2)] = make_uint4(hi.x, hi.y, lo.x, lo.y);
        }
    }
}

// ---------------- position ids ----------------
__global__ void posids_kernel(const float* __restrict__ amask, int* __restrict__ pos) {
    __shared__ float ws[32];
    int b = blockIdx.x, t = threadIdx.x;
    float m = amask[b*SS + t];
    float v = m;
    #pragma unroll
    for (int o = 1; o < 32; o <<= 1) {
        float u = __shfl_up_sync(0xffffffffu, v, o);
        if ((t & 31) >= o) v += u;
    }
    if ((t & 31) == 31) ws[t >> 5] = v;
    __syncthreads();
    if (t < 32) {
        float w2 = ws[t];
        #pragma unroll
        for (int o = 1; o < 32; o <<= 1) {
            float u = __shfl_up_sync(0xffffffffu, w2, o);
            if (t >= o) w2 += u;
        }
        ws[t] = w2;
    }
    __syncthreads();
    float total = v + ((t >> 5) ? ws[(t >> 5) - 1] : 0.f);
    pos[b*SS + t] = (m == 0.f) ? 0 : (int)(total - 1.f);
}

// ---------------- launch ----------------
extern "C" void kernel_launch(void* const* d_in, const int* in_sizes, int n_in,
                              void* d_out, int out_size) {
    const int*   ids   = (const int*)  d_in[0];
    const float* amask = (const float*)d_in[1];
    const float* tok   = (const float*)d_in[2];
    const float* pemb  = (const float*)d_in[3];
    const float* ln1g  = (const float*)d_in[4];
    const float* ln1b  = (const float*)d_in[5];
    const float* Wq    = (const float*)d_in[6];
    const float* bq    = (const float*)d_in[7];
    const float* Wk    = (const float*)d_in[8];
    const float* bk    = (const float*)d_in[9];
    const float* Wv    = (const float*)d_in[10];
    const float* bv    = (const float*)d_in[11];
    const float* Wp    = (const float*)d_in[12];
    const float* bp    = (const float*)d_in[13];
    const float* ln2g  = (const float*)d_in[14];
    const float* ln2b  = (const float*)d_in[15];
    const float* W1    = (const float*)d_in[16];
    const float* b1    = (const float*)d_in[17];
    const float* W2    = (const float*)d_in[18];
    const float* b2    = (const float*)d_in[19];
    const float* lnfg  = (const float*)d_in[20];
    const float* lnfb  = (const float*)d_in[21];
    float* out = (float*)d_out;

    float *xp, *partp; int* pidp;
    uint2 *qhi, *qlo;
    uint4 *hs, *as, *fs, *wqs, *wks, *wvs, *wps, *w1s, *w2s, *toks;
    cudaGetSymbolAddress((void**)&xp,   g_x);
    cudaGetSymbolAddress((void**)&partp, g_mlp2p);
    cudaGetSymbolAddress((void**)&pidp, g_pos);
    cudaGetSymbolAddress((void**)&hs,   g_h_s);
    cudaGetSymbolAddress((void**)&qhi,  g_qkv_hi);
    cudaGetSymbolAddress((void**)&qlo,  g_qkv_lo);
    cudaGetSymbolAddress((void**)&as,   g_attn_s);
    cudaGetSymbolAddress((void**)&fs,   g_ff_s);
    cudaGetSymbolAddress((void**)&wqs,  g_wq_s);
    cudaGetSymbolAddress((void**)&wks,  g_wk_s);
    cudaGetSymbolAddress((void**)&wvs,  g_wv_s);
    cudaGetSymbolAddress((void**)&wps,  g_wp_s);
    cudaGetSymbolAddress((void**)&w1s,  g_w1_s);
    cudaGetSymbolAddress((void**)&w2s,  g_w2_s);
    cudaGetSymbolAddress((void**)&toks, g_tok_s);

    const int SM_T0 = 2*(36864 + 2*17408);  // 143360
    const int SM_T1 = 2*(36864 + 2*18432);  // 147456
    const int SM_FA = 3*FBUF;               // 111360
    cudaFuncSetAttribute(mma_gemm<0,0>, cudaFuncAttributeMaxDynamicSharedMemorySize, SM_T0);
    cudaFuncSetAttribute(mma_gemm<0,1>, cudaFuncAttributeMaxDynamicSharedMemorySize, SM_T0);
    cudaFuncSetAttribute(mma_gemm<1,0>, cudaFuncAttributeMaxDynamicSharedMemorySize, SM_T1);
    cudaFuncSetAttribute(qkv_gemm, cudaFuncAttributeMaxDynamicSharedMemorySize, SM_T0);
    cudaFuncSetAttribute(flash_kernel, cudaFuncAttributeMaxDynamicSharedMemorySize, SM_FA);

    const int nW  = LL*DD*DD/4;
    const int nW1 = LL*DD*FF/4;
    const int nT  = VV*DD/4;
    split_kernel<<<(nW +255)/256, 256>>>((const float4*)Wq, wqs, nW);
    split_kernel<<<(nW +255)/256, 256>>>((const float4*)Wk, wks, nW);
    split_kernel<<<(nW +255)/256, 256>>>((const float4*)Wv, wvs, nW);
    split_kernel<<<(nW +255)/256, 256>>>((const float4*)Wp, wps, nW);
    split_kernel<<<(nW1+255)/256, 256>>>((const float4*)W1, w1s, nW1);
    split_kernel<<<(nW1+255)/256, 256>>>((const float4*)W2, w2s, nW1);
    split_kernel<<<(nT +255)/256, 256>>>((const float4*)tok, toks, nT);

    posids_kernel<<<BB, 1024>>>(amask, pidp);
    embed_ln_kernel<<<MM, 192>>>(ids, pidp, tok, pemb, xp, ln1g, ln1b, hs);

    dim3 gQKV(18, MM/128);
    dim3 gF(FF/128, MM/128);
    dim3 gP(DD/128, MM/128, 3);
    dim3 gM2(DD/128, MM/128, 3);
    dim3 gV(MM/128, (VV+127)/128);
    dim3 gFA(SS/64, BB*HH);

    for (int l = 0; l < LL; l++) {
        const uint4* wql = wqs + (size_t)l*(DD*DD/4);
        const uint4* wkl = wks + (size_t)l*(DD*DD/4);
        const uint4* wvl = wvs + (size_t)l*(DD*DD/4);
        const uint4* wpl = wps + (size_t)l*(DD*DD/4);
        const uint4* w1l = w1s + (size_t)l*(DD*FF/4);
        const uint4* w2l = w2s + (size_t)l*(DD*FF/4);

        qkv_gemm<<<gQKV, 256, SM_T0>>>(hs, wql, wkl, wvl, bq + l*DD, bk + l*DD, bv + l*DD,
                                       qhi, qlo);
        flash_kernel<<<gFA, 128, SM_FA>>>(qhi, qlo, amask, as);
        mma_gemm<0,0><<<gP, 256, SM_T0>>>(as, wpl, nullptr, nullptr, partp, nullptr,
                                          MM, DD, DD/3, 0, DD/4);
        reduce_ln_kernel<<<MM, 192>>>((const float4*)partp, bp + l*DD, (float4*)xp,
                                      ln2g + l*DD, ln2b + l*DD, hs);
        mma_gemm<0,1><<<gF, 256, SM_T0>>>(hs, w1l, b1 + l*FF, nullptr, nullptr, fs,
                                          MM, FF, DD, 1, DD/4);
        mma_gemm<0,0><<<gM2, 256, SM_T0>>>(fs, w2l, nullptr, nullptr, partp, nullptr,
                                           MM, DD, FF/3, 0, FF/4);
        const float* ng = (l + 1 < LL) ? (ln1g + (l+1)*DD) : lnfg;
        const float* nb = (l + 1 < LL) ? (ln1b + (l+1)*DD) : lnfb;
        reduce_ln_kernel<<<MM, 192>>>((const float4*)partp, b2 + l*DD, (float4*)xp,
                                      ng, nb, hs);
    }

    mma_gemm<1,0><<<gV, 256, SM_T1>>>(hs, toks, nullptr, nullptr, out, nullptr,
                                      MM, VV, DD, 0, DD/4);
}